// round 1
// baseline (speedup 1.0000x reference)
#include <cuda_runtime.h>
#include <cstddef>

// Problem constants
#define DIMC   1024
#define NHEADS 16
#define HDIM   64
#define NTOK   4096
#define NPAD   4120      // 4096 + 24 pad -> 103 blocks of 40
#define BATCH  8
#define RR     206       // 103 blocks * 2 parities
#define SP     20        // tokens per patch
#define K3     3072      // 3*DIM

// Scratch (device globals: allocation-free per harness rules)
__device__ float g_qkv[(size_t)BATCH * NPAD * K3];    // [b, n, 3*1024]
__device__ float g_att[(size_t)BATCH * NPAD * DIMC];  // [b, n, 1024]

// ---------------------------------------------------------------------------
// Tiled fp32 GEMM: C[M,N] = A[M,K=1024] * W[N,K]^T (+bias)
// MODE 0: A = x (padded-token addressing, zero rows for t>=4096), C = g_qkv
// MODE 1: A = g_att (padded-token addressing, only t<4096 used), C = out + bias
// Block tile 128x128, K-tile 16, 256 threads, 8x8 per-thread micro-tile.
// ---------------------------------------------------------------------------
template<int MODE>
__global__ void __launch_bounds__(256)
gemm128(const float* __restrict__ Ain, const float* __restrict__ W,
        const float* __restrict__ bias, float* __restrict__ Cout,
        int M, int N)
{
    const int K = DIMC;
    __shared__ float As[16][132];
    __shared__ float Bs[16][132];

    const int tid = threadIdx.x;
    const int bm = blockIdx.y, bn = blockIdx.x;

    const float* Asrc = (MODE == 0) ? Ain : g_att;
    float*       C    = (MODE == 0) ? g_qkv : Cout;

    // Per-thread load assignment: id = tid + i*256, row = id>>2, k4 = (tid&3)*4
    const float* aPtr[2];
    const float* wPtr[2];
    int rowA[2];
    #pragma unroll
    for (int i = 0; i < 2; i++) {
        int id = tid + i * 256;
        int r  = id >> 2;
        rowA[i] = r;
        int m = bm * 128 + r;
        if (m >= M) {
            aPtr[i] = nullptr;
        } else if (MODE == 0) {
            int b = m / NPAD, t = m - b * NPAD;
            aPtr[i] = (t < NTOK) ? (Asrc + ((size_t)(b * NTOK + t)) * K) : nullptr;
        } else {
            int b = m / NTOK, t = m - b * NTOK;
            aPtr[i] = Asrc + ((size_t)(b * NPAD + t)) * K;
        }
        wPtr[i] = W + ((size_t)(bn * 128 + r)) * K;   // N is a multiple of 128
    }
    const int k4 = (tid & 3) * 4;

    float acc[8][8];
    #pragma unroll
    for (int i = 0; i < 8; i++)
        #pragma unroll
        for (int j = 0; j < 8; j++) acc[i][j] = 0.f;

    const int ty = tid >> 4, tx = tid & 15;

    for (int kt = 0; kt < K; kt += 16) {
        #pragma unroll
        for (int i = 0; i < 2; i++) {
            int r = rowA[i];
            float4 av = aPtr[i] ? *(const float4*)(aPtr[i] + kt + k4)
                                : make_float4(0.f, 0.f, 0.f, 0.f);
            As[k4 + 0][r] = av.x; As[k4 + 1][r] = av.y;
            As[k4 + 2][r] = av.z; As[k4 + 3][r] = av.w;
            float4 bv = *(const float4*)(wPtr[i] + kt + k4);
            Bs[k4 + 0][r] = bv.x; Bs[k4 + 1][r] = bv.y;
            Bs[k4 + 2][r] = bv.z; Bs[k4 + 3][r] = bv.w;
        }
        __syncthreads();

        #pragma unroll
        for (int k = 0; k < 16; k++) {
            float a[8], b[8];
            *(float4*)&a[0] = *(const float4*)&As[k][ty * 8];
            *(float4*)&a[4] = *(const float4*)&As[k][ty * 8 + 4];
            *(float4*)&b[0] = *(const float4*)&Bs[k][tx * 8];
            *(float4*)&b[4] = *(const float4*)&Bs[k][tx * 8 + 4];
            #pragma unroll
            for (int i = 0; i < 8; i++)
                #pragma unroll
                for (int j = 0; j < 8; j++)
                    acc[i][j] += a[i] * b[j];
        }
        __syncthreads();
    }

    const int mBase = bm * 128 + ty * 8;
    const int nBase = bn * 128 + tx * 8;

    float bv[8];
    #pragma unroll
    for (int j = 0; j < 8; j++)
        bv[j] = (MODE == 1) ? bias[nBase + j] : 0.f;

    #pragma unroll
    for (int i = 0; i < 8; i++) {
        int m = mBase + i;
        if (m >= M) break;
        float4 o0, o1;
        o0.x = acc[i][0] + bv[0]; o0.y = acc[i][1] + bv[1];
        o0.z = acc[i][2] + bv[2]; o0.w = acc[i][3] + bv[3];
        o1.x = acc[i][4] + bv[4]; o1.y = acc[i][5] + bv[5];
        o1.z = acc[i][6] + bv[6]; o1.w = acc[i][7] + bv[7];
        float* cp = C + (size_t)m * N + nBase;
        *(float4*)(cp)     = o0;
        *(float4*)(cp + 4) = o1;
    }
}

// ---------------------------------------------------------------------------
// Per-patch attention. Grid: (RR=206, NHEADS=16, BATCH=8), 256 threads.
// Patch r = 2*blk + par contains tokens n = blk*40 + par + 2*s, s=0..19.
// ---------------------------------------------------------------------------
__global__ void __launch_bounds__(256)
attn_kernel()
{
    const int r   = blockIdx.x;
    const int h   = blockIdx.y;
    const int b   = blockIdx.z;
    const int blk = r >> 1, par = r & 1;

    __shared__ float q[SP][HDIM];
    __shared__ float k[SP][HDIM];
    __shared__ float v[SP][HDIM];
    __shared__ float dots[SP][SP];

    const int tid = threadIdx.x;
    const size_t base = (size_t)b * NPAD * K3;

    // Load q/k/v tiles (20 rows x 16 float4 each)
    for (int i = tid; i < SP * 16; i += 256) {
        int s = i >> 4, j = i & 15;
        int n = blk * 40 + par + 2 * s;
        const float* rp = g_qkv + base + (size_t)n * K3 + h * HDIM;
        ((float4*)q[s])[j] = ((const float4*)(rp))[j];
        ((float4*)k[s])[j] = ((const float4*)(rp + DIMC))[j];
        ((float4*)v[s])[j] = ((const float4*)(rp + 2 * DIMC))[j];
    }
    __syncthreads();

    // dots[s][t] = scale * <q_s, k_t>
    const float scale = 0.125f;  // 64^-0.5
    for (int i = tid; i < SP * SP; i += 256) {
        int s = i / SP, t = i - s * SP;
        float sum = 0.f;
        #pragma unroll
        for (int e = 0; e < HDIM; e++) sum += q[s][e] * k[t][e];
        dots[s][t] = sum * scale;
    }
    __syncthreads();

    // Row softmax (threads 0..19)
    if (tid < SP) {
        float mx = -1e30f;
        #pragma unroll
        for (int t = 0; t < SP; t++) mx = fmaxf(mx, dots[tid][t]);
        float ex[SP];
        float sum = 0.f;
        #pragma unroll
        for (int t = 0; t < SP; t++) { float e = expf(dots[tid][t] - mx); ex[t] = e; sum += e; }
        float inv = 1.f / sum;
        #pragma unroll
        for (int t = 0; t < SP; t++) dots[tid][t] = ex[t] * inv;
    }
    __syncthreads();

    // out[s][e] = sum_t attn[s][t] * v[t][e]; scatter to g_att
    for (int i = tid; i < SP * HDIM; i += 256) {
        int s = i >> 6, e = i & 63;
        float sum = 0.f;
        #pragma unroll
        for (int t = 0; t < SP; t++) sum += dots[s][t] * v[t][e];
        int n = blk * 40 + par + 2 * s;
        g_att[((size_t)b * NPAD + n) * DIMC + h * HDIM + e] = sum;
    }
}

// ---------------------------------------------------------------------------
extern "C" void kernel_launch(void* const* d_in, const int* in_sizes, int n_in,
                              void* d_out, int out_size)
{
    const float* x    = (const float*)d_in[0];  // (8, 4096, 1024)
    const float* Wqkv = (const float*)d_in[1];  // (3072, 1024)
    const float* Wout = (const float*)d_in[2];  // (1024, 1024)
    const float* bout = (const float*)d_in[3];  // (1024,)
    float* out = (float*)d_out;                 // (8, 4096, 1024)

    // 1) QKV projection: M = 8*4120 = 32960, N = 3072
    {
        dim3 grid(K3 / 128, (BATCH * NPAD + 127) / 128);
        gemm128<0><<<grid, 256>>>(x, Wqkv, nullptr, nullptr, BATCH * NPAD, K3);
    }
    // 2) Patch attention
    {
        dim3 grid(RR, NHEADS, BATCH);
        attn_kernel<<<grid, 256>>>();
    }
    // 3) Output projection + bias: M = 8*4096 = 32768, N = 1024
    {
        dim3 grid(DIMC / 128, (BATCH * NTOK) / 128);
        gemm128<1><<<grid, 256>>>(nullptr, Wout, bout, out, BATCH * NTOK, DIMC);
    }
}

// round 3
// speedup vs baseline: 1.8253x; 1.8253x over previous
#include <cuda_runtime.h>
#include <cuda_bf16.h>
#include <cstdint>
#include <cstddef>

// ---------------------------------------------------------------------------
// Problem constants
// ---------------------------------------------------------------------------
#define DIMC   1024
#define NHEADS 16
#define HDIM   64
#define NTOK   4096
#define NPADR  4224      // per-batch rows padded to multiple of 128
#define BATCH  8
#define RR     206       // 103 blocks * 2 parities
#define SP     20        // tokens per patch
#define K3     3072      // 3*DIM

#define MROWS0 (BATCH*NPADR)   // 33792  (GEMM1 M)
#define MROWS1 (BATCH*NTOK)    // 32768  (GEMM2 M)

// ---------------------------------------------------------------------------
// Device scratch
// ---------------------------------------------------------------------------
__device__ float g_qkv[(size_t)MROWS0 * K3];   // qkv, fp32, padded-row layout
__device__ float g_att[(size_t)MROWS1 * DIMC]; // attention output, fp32

// ---------------------------------------------------------------------------
// Helpers
// ---------------------------------------------------------------------------
__device__ __forceinline__ uint32_t smem_to_u32(const void* p) {
    uint32_t a;
    asm("{ .reg .u64 t; cvta.to.shared.u64 t, %1; cvt.u32.u64 %0, t; }"
        : "=r"(a) : "l"(p));
    return a;
}

__device__ __forceinline__ uint32_t pack_bf(__nv_bfloat16 a, __nv_bfloat16 b) {
    return (uint32_t)__bfloat16_as_ushort(a) | ((uint32_t)__bfloat16_as_ushort(b) << 16);
}

// split fp32x4 -> bf16 hi (4) + bf16 lo (4)
__device__ __forceinline__ void split4(const float4 v, uint2& hi, uint2& lo) {
    __nv_bfloat16 h0 = __float2bfloat16_rn(v.x), h1 = __float2bfloat16_rn(v.y);
    __nv_bfloat16 h2 = __float2bfloat16_rn(v.z), h3 = __float2bfloat16_rn(v.w);
    __nv_bfloat16 l0 = __float2bfloat16_rn(v.x - __bfloat162float(h0));
    __nv_bfloat16 l1 = __float2bfloat16_rn(v.y - __bfloat162float(h1));
    __nv_bfloat16 l2 = __float2bfloat16_rn(v.z - __bfloat162float(h2));
    __nv_bfloat16 l3 = __float2bfloat16_rn(v.w - __bfloat162float(h3));
    hi.x = pack_bf(h0, h1); hi.y = pack_bf(h2, h3);
    lo.x = pack_bf(l0, l1); lo.y = pack_bf(l2, l3);
}

#define LDSM4(r, addr) \
    asm volatile("ldmatrix.sync.aligned.m8n8.x4.shared.b16 {%0,%1,%2,%3}, [%4];" \
        : "=r"((r)[0]), "=r"((r)[1]), "=r"((r)[2]), "=r"((r)[3]) : "r"(addr))

#define MMA16816(d, a, b0, b1) \
    asm volatile("mma.sync.aligned.m16n8k16.row.col.f32.bf16.bf16.f32 " \
        "{%0,%1,%2,%3}, {%4,%5,%6,%7}, {%8,%9}, {%0,%1,%2,%3};" \
        : "+f"((d)[0]), "+f"((d)[1]), "+f"((d)[2]), "+f"((d)[3]) \
        : "r"((a)[0]), "r"((a)[1]), "r"((a)[2]), "r"((a)[3]), "r"(b0), "r"(b1))

// ---------------------------------------------------------------------------
// Split-bf16 mma.sync GEMM:  C[M,N] = A[M,1024] * W[N,1024]^T (+bias MODE 1)
// CTA 128x128, BK=32, 256 threads, warp grid 2(m) x 4(n), warp tile 64x32.
// smem per stage: A_hi 8K | A_lo 8K | B_hi 8K | B_lo 8K = 32K, double buffered.
// Swizzle: halves, row stride 64B; 16B chunk c at (row, c): c ^= (row>>1)&3.
// ---------------------------------------------------------------------------
#define BK 32
#define STAGE   32768
#define OFF_AHI 0
#define OFF_ALO 8192
#define OFF_BHI 16384
#define OFF_BLO 24576
#define SMEM_TOTAL (2*STAGE)

template<int MODE>
__global__ void __launch_bounds__(256, 1)
gemm_mma(const float* __restrict__ Ain, const float* __restrict__ W,
         const float* __restrict__ bias, float* __restrict__ Cout, int Ncols)
{
    extern __shared__ char smem[];
    const uint32_t sbase = smem_to_u32(smem);
    const int tid  = threadIdx.x;
    const int lane = tid & 31;
    const int wid  = tid >> 5;
    const int wm   = wid >> 2;   // 0..1
    const int wn   = wid & 3;    // 0..3
    const int m0   = blockIdx.y * 128;
    const int n0   = blockIdx.x * 128;

    float* C = (MODE == 0) ? g_qkv : Cout;

    // ---- global load assignment: 4 A rows + 4 B rows per thread -----------
    const float* aPtr[4];
    const float* bPtr[4];
    uint32_t st[4];
    #pragma unroll
    for (int j = 0; j < 4; j++) {
        int id  = tid + j * 256;
        int row = id >> 3;          // 0..127
        int f4  = id & 7;           // float4 index within 32 floats
        int m = m0 + row;
        if (MODE == 0) {
            int b = m / NPADR, t = m - b * NPADR;
            aPtr[j] = (t < NTOK) ? (Ain + ((size_t)(b * NTOK + t)) * DIMC + f4 * 4)
                                 : nullptr;
        } else {
            aPtr[j] = g_att + (size_t)m * DIMC + f4 * 4;
        }
        bPtr[j] = W + (size_t)(n0 + row) * DIMC + f4 * 4;
        st[j] = (uint32_t)(row * 64 + ((((uint32_t)f4 >> 1) ^ (((uint32_t)row >> 1) & 3)) << 4)
                           + (f4 & 1) * 8);
    }

    // ---- ldmatrix address components ---------------------------------------
    // A: row = wm*64 + mf*16 + (lane&15); chunk = ks*2 + (lane>>4)
    uint32_t aOff[4], aXor[4];
    #pragma unroll
    for (int mf = 0; mf < 4; mf++) {
        int row = wm * 64 + mf * 16 + (lane & 15);
        aOff[mf] = (uint32_t)row * 64;
        aXor[mf] = ((uint32_t)row >> 1) & 3;
    }
    const uint32_t aHi = (uint32_t)(lane >> 4);
    // B: n_row = wn*32 + (lane&7) + 8*(lane>>4) + g*16; chunk = ks*2 + ((lane>>3)&1)
    uint32_t bOff[2], bXor[2];
    #pragma unroll
    for (int g = 0; g < 2; g++) {
        int row = wn * 32 + (lane & 7) + ((lane >> 4) << 3) + g * 16;
        bOff[g] = (uint32_t)row * 64;
        bXor[g] = ((uint32_t)row >> 1) & 3;
    }
    const uint32_t bk = (uint32_t)((lane >> 3) & 1);

    float acc[4][4][4];
    #pragma unroll
    for (int i = 0; i < 4; i++)
        #pragma unroll
        for (int j = 0; j < 4; j++)
            #pragma unroll
            for (int q = 0; q < 4; q++) acc[i][j][q] = 0.f;

    // ---- prologue: tile 0 ---------------------------------------------------
    {
        #pragma unroll
        for (int j = 0; j < 4; j++) {
            float4 va = aPtr[j] ? *(const float4*)(aPtr[j]) : make_float4(0.f,0.f,0.f,0.f);
            float4 vb = *(const float4*)(bPtr[j]);
            uint2 hi, lo;
            split4(va, hi, lo);
            *(uint2*)(smem + OFF_AHI + st[j]) = hi;
            *(uint2*)(smem + OFF_ALO + st[j]) = lo;
            split4(vb, hi, lo);
            *(uint2*)(smem + OFF_BHI + st[j]) = hi;
            *(uint2*)(smem + OFF_BLO + st[j]) = lo;
        }
    }
    __syncthreads();

    // ---- main loop ----------------------------------------------------------
    const int NIT = DIMC / BK;   // 32
    #pragma unroll 1
    for (int it = 0; it < NIT; ++it) {
        float4 fA[4], fB[4];
        const bool more = (it + 1) < NIT;
        if (more) {
            const int k = (it + 1) * BK;
            #pragma unroll
            for (int j = 0; j < 4; j++) {
                fA[j] = aPtr[j] ? *(const float4*)(aPtr[j] + k) : make_float4(0.f,0.f,0.f,0.f);
                fB[j] = *(const float4*)(bPtr[j] + k);
            }
        }

        const uint32_t s = sbase + (uint32_t)(it & 1) * STAGE;
        #pragma unroll
        for (int ks = 0; ks < 2; ++ks) {
            uint32_t ahi[4][4], alo[4][4];
            uint32_t bhi[2][4], blo[2][4];
            #pragma unroll
            for (int mf = 0; mf < 4; mf++) {
                uint32_t c = (((uint32_t)(ks * 2) + aHi) ^ aXor[mf]) << 4;
                LDSM4(ahi[mf], s + OFF_AHI + aOff[mf] + c);
                LDSM4(alo[mf], s + OFF_ALO + aOff[mf] + c);
            }
            #pragma unroll
            for (int g = 0; g < 2; g++) {
                uint32_t c = (((uint32_t)(ks * 2) + bk) ^ bXor[g]) << 4;
                LDSM4(bhi[g], s + OFF_BHI + bOff[g] + c);
                LDSM4(blo[g], s + OFF_BLO + bOff[g] + c);
            }
            #pragma unroll
            for (int mf = 0; mf < 4; mf++) {
                #pragma unroll
                for (int nf = 0; nf < 4; nf++) {
                    const int g = nf >> 1, p = (nf & 1) * 2;
                    MMA16816(acc[mf][nf], ahi[mf], bhi[g][p], bhi[g][p + 1]); // hi*hi
                    MMA16816(acc[mf][nf], ahi[mf], blo[g][p], blo[g][p + 1]); // hi*lo
                    MMA16816(acc[mf][nf], alo[mf], bhi[g][p], bhi[g][p + 1]); // lo*hi
                }
            }
        }

        if (more) {
            char* d = smem + ((it + 1) & 1) * STAGE;
            #pragma unroll
            for (int j = 0; j < 4; j++) {
                uint2 hi, lo;
                split4(fA[j], hi, lo);
                *(uint2*)(d + OFF_AHI + st[j]) = hi;
                *(uint2*)(d + OFF_ALO + st[j]) = lo;
                split4(fB[j], hi, lo);
                *(uint2*)(d + OFF_BHI + st[j]) = hi;
                *(uint2*)(d + OFF_BLO + st[j]) = lo;
            }
        }
        __syncthreads();
    }

    // ---- epilogue -----------------------------------------------------------
    const int grp = lane >> 2;   // 0..7
    const int thr = lane & 3;    // 0..3
    #pragma unroll
    for (int mf = 0; mf < 4; mf++) {
        const int mrow = m0 + wm * 64 + mf * 16 + grp;
        #pragma unroll
        for (int nf = 0; nf < 4; nf++) {
            const int col = n0 + wn * 32 + nf * 8 + thr * 2;
            float2 v0 = make_float2(acc[mf][nf][0], acc[mf][nf][1]);
            float2 v1 = make_float2(acc[mf][nf][2], acc[mf][nf][3]);
            if (MODE == 1) {
                const float2 bv = *(const float2*)(bias + col);
                v0.x += bv.x; v0.y += bv.y;
                v1.x += bv.x; v1.y += bv.y;
            }
            *(float2*)(C + (size_t)mrow * Ncols + col)       = v0;
            *(float2*)(C + (size_t)(mrow + 8) * Ncols + col) = v1;
        }
    }
}

// ---------------------------------------------------------------------------
// Per-patch attention. Grid: (RR, NHEADS, BATCH), 256 threads.
// Patch r = 2*blk + par contains tokens n = blk*40 + par + 2*s, s=0..19.
// Reads g_qkv (padded-row layout, stride NPADR), writes g_att (compact).
// ---------------------------------------------------------------------------
__global__ void __launch_bounds__(256) attn_kernel()
{
    const int r   = blockIdx.x;
    const int h   = blockIdx.y;
    const int b   = blockIdx.z;
    const int blk = r >> 1, par = r & 1;

    __shared__ float q[SP][HDIM];
    __shared__ float k[SP][HDIM];
    __shared__ float v[SP][HDIM];
    __shared__ float dots[SP][SP];

    const int tid = threadIdx.x;
    const size_t base = (size_t)b * NPADR * K3;

    for (int i = tid; i < SP * 16; i += 256) {
        int s = i >> 4, j = i & 15;
        int n = blk * 40 + par + 2 * s;
        const float* rp = g_qkv + base + (size_t)n * K3 + h * HDIM;
        ((float4*)q[s])[j] = ((const float4*)(rp))[j];
        ((float4*)k[s])[j] = ((const float4*)(rp + DIMC))[j];
        ((float4*)v[s])[j] = ((const float4*)(rp + 2 * DIMC))[j];
    }
    __syncthreads();

    const float scale = 0.125f;  // 64^-0.5
    for (int i = tid; i < SP * SP; i += 256) {
        int s = i / SP, t = i - s * SP;
        float sum = 0.f;
        #pragma unroll
        for (int e = 0; e < HDIM; e++) sum += q[s][e] * k[t][e];
        dots[s][t] = sum * scale;
    }
    __syncthreads();

    if (tid < SP) {
        float mx = -1e30f;
        #pragma unroll
        for (int t = 0; t < SP; t++) mx = fmaxf(mx, dots[tid][t]);
        float ex[SP]; float sum = 0.f;
        #pragma unroll
        for (int t = 0; t < SP; t++) { float e = expf(dots[tid][t] - mx); ex[t] = e; sum += e; }
        float inv = 1.f / sum;
        #pragma unroll
        for (int t = 0; t < SP; t++) dots[tid][t] = ex[t] * inv;
    }
    __syncthreads();

    for (int i = tid; i < SP * HDIM; i += 256) {
        int s = i >> 6, e = i & 63;
        int n = blk * 40 + par + 2 * s;
        if (n >= NTOK) continue;   // padded-token outputs are discarded
        float sum = 0.f;
        #pragma unroll
        for (int t = 0; t < SP; t++) sum += dots[s][t] * v[t][e];
        g_att[((size_t)b * NTOK + n) * DIMC + h * HDIM + e] = sum;
    }
}

// ---------------------------------------------------------------------------
extern "C" void kernel_launch(void* const* d_in, const int* in_sizes, int n_in,
                              void* d_out, int out_size)
{
    const float* x    = (const float*)d_in[0];  // (8, 4096, 1024)
    const float* Wqkv = (const float*)d_in[1];  // (3072, 1024)
    const float* Wout = (const float*)d_in[2];  // (1024, 1024)
    const float* bout = (const float*)d_in[3];  // (1024,)
    float* out = (float*)d_out;                 // (8, 4096, 1024)

    static bool attr_done = false;
    if (!attr_done) {
        cudaFuncSetAttribute(gemm_mma<0>, cudaFuncAttributeMaxDynamicSharedMemorySize, SMEM_TOTAL);
        cudaFuncSetAttribute(gemm_mma<1>, cudaFuncAttributeMaxDynamicSharedMemorySize, SMEM_TOTAL);
        attr_done = true;
    }

    // 1) QKV projection: M=33792, N=3072
    gemm_mma<0><<<dim3(K3 / 128, MROWS0 / 128), 256, SMEM_TOTAL>>>(x, Wqkv, nullptr, nullptr, K3);

    // 2) Patch attention
    attn_kernel<<<dim3(RR, NHEADS, BATCH), 256>>>();

    // 3) Output projection + bias: M=32768, N=1024
    gemm_mma<1><<<dim3(DIMC / 128, MROWS1 / 128), 256, SMEM_TOTAL>>>(nullptr, Wout, bout, out, DIMC);
}

// round 4
// speedup vs baseline: 2.4194x; 1.3255x over previous
#include <cuda_runtime.h>
#include <cuda_bf16.h>
#include <cstdint>
#include <cstddef>

// ---------------------------------------------------------------------------
// Problem constants
// ---------------------------------------------------------------------------
#define DIMC   1024
#define NHEADS 16
#define HDIM   64
#define NTOK   4096
#define NPADR  4224      // per-batch rows padded to multiple of 128
#define BATCH  8
#define RR     206       // 103 blocks * 2 parities
#define SP     20        // tokens per patch
#define K3     3072      // 3*DIM

#define MROWS0 (BATCH*NPADR)   // 33792  (GEMM1 M)
#define MROWS1 (BATCH*NTOK)    // 32768  (GEMM2 M)

// ---------------------------------------------------------------------------
// Device scratch
// ---------------------------------------------------------------------------
__device__ __align__(16) float          g_qkv[(size_t)MROWS0 * K3];     // fp32 qkv (padded rows)
__device__ __align__(16) __nv_bfloat16  g_x_hi[(size_t)MROWS0 * DIMC];
__device__ __align__(16) __nv_bfloat16  g_x_lo[(size_t)MROWS0 * DIMC];
__device__ __align__(16) __nv_bfloat16  g_att_hi[(size_t)MROWS1 * DIMC];
__device__ __align__(16) __nv_bfloat16  g_att_lo[(size_t)MROWS1 * DIMC];
__device__ __align__(16) __nv_bfloat16  g_wq_hi[(size_t)K3 * DIMC];
__device__ __align__(16) __nv_bfloat16  g_wq_lo[(size_t)K3 * DIMC];
__device__ __align__(16) __nv_bfloat16  g_wo_hi[(size_t)DIMC * DIMC];
__device__ __align__(16) __nv_bfloat16  g_wo_lo[(size_t)DIMC * DIMC];

// ---------------------------------------------------------------------------
// Helpers
// ---------------------------------------------------------------------------
__device__ __forceinline__ uint32_t smem_to_u32(const void* p) {
    uint32_t a;
    asm("{ .reg .u64 t; cvta.to.shared.u64 t, %1; cvt.u32.u64 %0, t; }"
        : "=r"(a) : "l"(p));
    return a;
}

__device__ __forceinline__ uint32_t pack_bf(__nv_bfloat16 a, __nv_bfloat16 b) {
    return (uint32_t)__bfloat16_as_ushort(a) | ((uint32_t)__bfloat16_as_ushort(b) << 16);
}

__device__ __forceinline__ void split1(float v, unsigned short& h, unsigned short& l) {
    __nv_bfloat16 hb = __float2bfloat16_rn(v);
    float r = v - __bfloat162float(hb);
    __nv_bfloat16 lb = __float2bfloat16_rn(r);
    h = __bfloat16_as_ushort(hb);
    l = __bfloat16_as_ushort(lb);
}

__device__ __forceinline__ void split4(const float4 v, uint2& hi, uint2& lo) {
    __nv_bfloat16 h0 = __float2bfloat16_rn(v.x), h1 = __float2bfloat16_rn(v.y);
    __nv_bfloat16 h2 = __float2bfloat16_rn(v.z), h3 = __float2bfloat16_rn(v.w);
    __nv_bfloat16 l0 = __float2bfloat16_rn(v.x - __bfloat162float(h0));
    __nv_bfloat16 l1 = __float2bfloat16_rn(v.y - __bfloat162float(h1));
    __nv_bfloat16 l2 = __float2bfloat16_rn(v.z - __bfloat162float(h2));
    __nv_bfloat16 l3 = __float2bfloat16_rn(v.w - __bfloat162float(h3));
    hi.x = pack_bf(h0, h1); hi.y = pack_bf(h2, h3);
    lo.x = pack_bf(l0, l1); lo.y = pack_bf(l2, l3);
}

#define LDSM4(r, addr) \
    asm volatile("ldmatrix.sync.aligned.m8n8.x4.shared.b16 {%0,%1,%2,%3}, [%4];" \
        : "=r"((r)[0]), "=r"((r)[1]), "=r"((r)[2]), "=r"((r)[3]) : "r"(addr))

#define MMA16816(d, a, b0, b1) \
    asm volatile("mma.sync.aligned.m16n8k16.row.col.f32.bf16.bf16.f32 " \
        "{%0,%1,%2,%3}, {%4,%5,%6,%7}, {%8,%9}, {%0,%1,%2,%3};" \
        : "+f"((d)[0]), "+f"((d)[1]), "+f"((d)[2]), "+f"((d)[3]) \
        : "r"((a)[0]), "r"((a)[1]), "r"((a)[2]), "r"((a)[3]), "r"(b0), "r"(b1))

#define CP_ASYNC16(dst, src) \
    asm volatile("cp.async.cg.shared.global [%0], [%1], 16;" :: "r"(dst), "l"(src))
#define CP_COMMIT() asm volatile("cp.async.commit_group;" ::: "memory")
#define CP_WAIT(n)  asm volatile("cp.async.wait_group %0;" :: "n"(n) : "memory")

// ---------------------------------------------------------------------------
// Conversion prepasses: fp32 -> split bf16 (hi/lo)
// ---------------------------------------------------------------------------
__global__ void __launch_bounds__(256) conv_x(const float* __restrict__ x) {
    size_t i = (size_t)blockIdx.x * 256 + threadIdx.x;  // one float4
    size_t e = i * 4;
    size_t rowp = e >> 10;
    int c = (int)(e & 1023);
    int b = (int)(rowp / NPADR);
    int t = (int)(rowp - (size_t)b * NPADR);
    float4 v = make_float4(0.f, 0.f, 0.f, 0.f);
    if (t < NTOK)
        v = *(const float4*)(x + (((size_t)b * NTOK + t) << 10) + c);
    uint2 h, l; split4(v, h, l);
    *(uint2*)(g_x_hi + e) = h;
    *(uint2*)(g_x_lo + e) = l;
}

__global__ void __launch_bounds__(256) conv_w(const float* __restrict__ wq,
                                              const float* __restrict__ wo) {
    size_t i = (size_t)blockIdx.x * 256 + threadIdx.x;
    size_t e = i * 4;
    const size_t NQ = (size_t)K3 * DIMC;
    uint2 h, l;
    if (e < NQ) {
        float4 v = *(const float4*)(wq + e);
        split4(v, h, l);
        *(uint2*)(g_wq_hi + e) = h;
        *(uint2*)(g_wq_lo + e) = l;
    } else {
        size_t o = e - NQ;
        float4 v = *(const float4*)(wo + o);
        split4(v, h, l);
        *(uint2*)(g_wo_hi + o) = h;
        *(uint2*)(g_wo_lo + o) = l;
    }
}

// ---------------------------------------------------------------------------
// Split-bf16 mma.sync GEMM with 3-stage cp.async pipeline.
// C[M,N] = A[M,1024] * W[N,1024]^T (+bias for MODE 1)
// CTA 128x128, BK=32, 256 threads, warp grid 2(m) x 4(n), warp tile 64x32.
// Stage (32 KB): A_hi 8K | A_lo 8K | B_hi 8K | B_lo 8K, 3 stages.
// Swizzle: row stride 64B; 16B chunk c at (row): c ^= (row>>1)&3.
// ---------------------------------------------------------------------------
#define BK      32
#define NSTAGE  3
#define STAGE   32768
#define OFF_AHI 0
#define OFF_ALO 8192
#define OFF_BHI 16384
#define OFF_BLO 24576
#define SMEM_TOTAL (NSTAGE*STAGE)   // 98304

template<int MODE>
__global__ void __launch_bounds__(256, 2)
gemm_mma(const float* __restrict__ bias, float* __restrict__ Cout, int Ncols)
{
    extern __shared__ char smem[];
    const uint32_t sbase = smem_to_u32(smem);
    const int tid  = threadIdx.x;
    const int lane = tid & 31;
    const int wid  = tid >> 5;
    const int wm   = wid >> 2;   // 0..1
    const int wn   = wid & 3;    // 0..3
    const int m0   = blockIdx.y * 128;
    const int n0   = blockIdx.x * 128;

    const __nv_bfloat16* gAhi = (MODE == 0) ? g_x_hi : g_att_hi;
    const __nv_bfloat16* gAlo = (MODE == 0) ? g_x_lo : g_att_lo;
    const __nv_bfloat16* gBhi = (MODE == 0) ? g_wq_hi : g_wo_hi;
    const __nv_bfloat16* gBlo = (MODE == 0) ? g_wq_lo : g_wo_lo;
    float* C = (MODE == 0) ? g_qkv : Cout;

    // ---- cp.async assignment: 2 chunks of 16B per thread per region --------
    // chunk c (0..511): row = c>>2 (0..127), col = c&3 (16B chunk in 64B row)
    uint32_t dsto[2];
    const __nv_bfloat16 *srcAh[2], *srcAl[2], *srcBh[2], *srcBl[2];
    #pragma unroll
    for (int j = 0; j < 2; j++) {
        int c = tid + j * 256;
        int row = c >> 2, col = c & 3;
        dsto[j] = (uint32_t)(row * 64 + (((uint32_t)col ^ (((uint32_t)row >> 1) & 3)) << 4));
        size_t aoff = (size_t)(m0 + row) * DIMC + col * 8;
        size_t boff = (size_t)(n0 + row) * DIMC + col * 8;
        srcAh[j] = gAhi + aoff; srcAl[j] = gAlo + aoff;
        srcBh[j] = gBhi + boff; srcBl[j] = gBlo + boff;
    }

    // ---- ldmatrix address components ---------------------------------------
    uint32_t aOff[4], aXor[4];
    #pragma unroll
    for (int mf = 0; mf < 4; mf++) {
        int row = wm * 64 + mf * 16 + (lane & 15);
        aOff[mf] = (uint32_t)row * 64;
        aXor[mf] = ((uint32_t)row >> 1) & 3;
    }
    const uint32_t aHi = (uint32_t)(lane >> 4);
    uint32_t bOff[2], bXor[2];
    #pragma unroll
    for (int g = 0; g < 2; g++) {
        int row = wn * 32 + (lane & 7) + ((lane >> 4) << 3) + g * 16;
        bOff[g] = (uint32_t)row * 64;
        bXor[g] = ((uint32_t)row >> 1) & 3;
    }
    const uint32_t bk = (uint32_t)((lane >> 3) & 1);

    float acc[4][4][4];
    #pragma unroll
    for (int i = 0; i < 4; i++)
        #pragma unroll
        for (int j = 0; j < 4; j++)
            #pragma unroll
            for (int q = 0; q < 4; q++) acc[i][j][q] = 0.f;

    const int NIT = DIMC / BK;   // 32

    // ---- issue helper (macro to keep everything in registers) --------------
    #define ISSUE_TILE(tile) do {                                             \
        const uint32_t sd = sbase + (uint32_t)((tile) % NSTAGE) * STAGE;      \
        const int kt = (tile) * BK;                                           \
        _Pragma("unroll")                                                     \
        for (int j = 0; j < 2; j++) {                                         \
            CP_ASYNC16(sd + OFF_AHI + dsto[j], srcAh[j] + kt);                \
            CP_ASYNC16(sd + OFF_ALO + dsto[j], srcAl[j] + kt);                \
            CP_ASYNC16(sd + OFF_BHI + dsto[j], srcBh[j] + kt);                \
            CP_ASYNC16(sd + OFF_BLO + dsto[j], srcBl[j] + kt);                \
        }                                                                     \
        CP_COMMIT();                                                          \
    } while (0)

    // ---- prologue: tiles 0,1 -----------------------------------------------
    ISSUE_TILE(0);
    ISSUE_TILE(1);

    // ---- main loop ----------------------------------------------------------
    #pragma unroll 1
    for (int it = 0; it < NIT; ++it) {
        if (it < NIT - 1) { CP_WAIT(1); } else { CP_WAIT(0); }
        __syncthreads();
        if (it + 2 < NIT) ISSUE_TILE(it + 2);

        const uint32_t s = sbase + (uint32_t)(it % NSTAGE) * STAGE;
        #pragma unroll
        for (int ks = 0; ks < 2; ++ks) {
            uint32_t ahi[4][4], alo[4][4];
            uint32_t bhi[2][4], blo[2][4];
            // hi * hi
            #pragma unroll
            for (int mf = 0; mf < 4; mf++) {
                uint32_t c = (((uint32_t)(ks * 2) + aHi) ^ aXor[mf]) << 4;
                LDSM4(ahi[mf], s + OFF_AHI + aOff[mf] + c);
            }
            #pragma unroll
            for (int g = 0; g < 2; g++) {
                uint32_t c = (((uint32_t)(ks * 2) + bk) ^ bXor[g]) << 4;
                LDSM4(bhi[g], s + OFF_BHI + bOff[g] + c);
            }
            #pragma unroll
            for (int mf = 0; mf < 4; mf++)
                #pragma unroll
                for (int nf = 0; nf < 4; nf++) {
                    const int g = nf >> 1, p = (nf & 1) * 2;
                    MMA16816(acc[mf][nf], ahi[mf], bhi[g][p], bhi[g][p + 1]);
                }
            // hi * lo
            #pragma unroll
            for (int g = 0; g < 2; g++) {
                uint32_t c = (((uint32_t)(ks * 2) + bk) ^ bXor[g]) << 4;
                LDSM4(blo[g], s + OFF_BLO + bOff[g] + c);
            }
            #pragma unroll
            for (int mf = 0; mf < 4; mf++)
                #pragma unroll
                for (int nf = 0; nf < 4; nf++) {
                    const int g = nf >> 1, p = (nf & 1) * 2;
                    MMA16816(acc[mf][nf], ahi[mf], blo[g][p], blo[g][p + 1]);
                }
            // lo * hi
            #pragma unroll
            for (int mf = 0; mf < 4; mf++) {
                uint32_t c = (((uint32_t)(ks * 2) + aHi) ^ aXor[mf]) << 4;
                LDSM4(alo[mf], s + OFF_ALO + aOff[mf] + c);
            }
            #pragma unroll
            for (int mf = 0; mf < 4; mf++)
                #pragma unroll
                for (int nf = 0; nf < 4; nf++) {
                    const int g = nf >> 1, p = (nf & 1) * 2;
                    MMA16816(acc[mf][nf], alo[mf], bhi[g][p], bhi[g][p + 1]);
                }
        }
        __syncthreads();
    }
    #undef ISSUE_TILE

    // ---- epilogue -----------------------------------------------------------
    const int grp = lane >> 2;   // 0..7
    const int thr = lane & 3;    // 0..3
    #pragma unroll
    for (int mf = 0; mf < 4; mf++) {
        const int mrow = m0 + wm * 64 + mf * 16 + grp;
        #pragma unroll
        for (int nf = 0; nf < 4; nf++) {
            const int col = n0 + wn * 32 + nf * 8 + thr * 2;
            float2 v0 = make_float2(acc[mf][nf][0], acc[mf][nf][1]);
            float2 v1 = make_float2(acc[mf][nf][2], acc[mf][nf][3]);
            if (MODE == 1) {
                const float2 bv = *(const float2*)(bias + col);
                v0.x += bv.x; v0.y += bv.y;
                v1.x += bv.x; v1.y += bv.y;
            }
            *(float2*)(C + (size_t)mrow * Ncols + col)       = v0;
            *(float2*)(C + (size_t)(mrow + 8) * Ncols + col) = v1;
        }
    }
}

// ---------------------------------------------------------------------------
// Per-patch attention. Grid: (RR, NHEADS, BATCH), 256 threads.
// Reads g_qkv (padded-row layout), writes split-bf16 g_att_hi/lo (compact).
// ---------------------------------------------------------------------------
__global__ void __launch_bounds__(256) attn_kernel()
{
    const int r   = blockIdx.x;
    const int h   = blockIdx.y;
    const int b   = blockIdx.z;
    const int blk = r >> 1, par = r & 1;

    __shared__ float q[SP][HDIM];
    __shared__ float k[SP][HDIM];
    __shared__ float v[SP][HDIM];
    __shared__ float dots[SP][SP];

    const int tid = threadIdx.x;
    const size_t base = (size_t)b * NPADR * K3;

    for (int i = tid; i < SP * 16; i += 256) {
        int s = i >> 4, j = i & 15;
        int n = blk * 40 + par + 2 * s;
        const float* rp = g_qkv + base + (size_t)n * K3 + h * HDIM;
        ((float4*)q[s])[j] = ((const float4*)(rp))[j];
        ((float4*)k[s])[j] = ((const float4*)(rp + DIMC))[j];
        ((float4*)v[s])[j] = ((const float4*)(rp + 2 * DIMC))[j];
    }
    __syncthreads();

    const float scale = 0.125f;  // 64^-0.5
    for (int i = tid; i < SP * SP; i += 256) {
        int s = i / SP, t = i - s * SP;
        float sum = 0.f;
        #pragma unroll
        for (int e = 0; e < HDIM; e++) sum += q[s][e] * k[t][e];
        dots[s][t] = sum * scale;
    }
    __syncthreads();

    if (tid < SP) {
        float mx = -1e30f;
        #pragma unroll
        for (int t = 0; t < SP; t++) mx = fmaxf(mx, dots[tid][t]);
        float ex[SP]; float sum = 0.f;
        #pragma unroll
        for (int t = 0; t < SP; t++) { float e = expf(dots[tid][t] - mx); ex[t] = e; sum += e; }
        float inv = 1.f / sum;
        #pragma unroll
        for (int t = 0; t < SP; t++) dots[tid][t] = ex[t] * inv;
    }
    __syncthreads();

    for (int i = tid; i < SP * HDIM; i += 256) {
        int s = i >> 6, e = i & 63;
        int n = blk * 40 + par + 2 * s;
        if (n >= NTOK) continue;
        float sum = 0.f;
        #pragma unroll
        for (int t = 0; t < SP; t++) sum += dots[s][t] * v[t][e];
        unsigned short hh, ll;
        split1(sum, hh, ll);
        size_t idx = ((size_t)b * NTOK + n) * DIMC + h * HDIM + e;
        g_att_hi[idx] = __ushort_as_bfloat16(hh);
        g_att_lo[idx] = __ushort_as_bfloat16(ll);
    }
}

// ---------------------------------------------------------------------------
extern "C" void kernel_launch(void* const* d_in, const int* in_sizes, int n_in,
                              void* d_out, int out_size)
{
    const float* x    = (const float*)d_in[0];  // (8, 4096, 1024)
    const float* Wqkv = (const float*)d_in[1];  // (3072, 1024)
    const float* Wout = (const float*)d_in[2];  // (1024, 1024)
    const float* bout = (const float*)d_in[3];  // (1024,)
    float* out = (float*)d_out;                 // (8, 4096, 1024)

    static bool attr_done = false;
    if (!attr_done) {
        cudaFuncSetAttribute(gemm_mma<0>, cudaFuncAttributeMaxDynamicSharedMemorySize, SMEM_TOTAL);
        cudaFuncSetAttribute(gemm_mma<1>, cudaFuncAttributeMaxDynamicSharedMemorySize, SMEM_TOTAL);
        attr_done = true;
    }

    // 0) Split inputs/weights into bf16 hi/lo
    conv_x<<<MROWS0 * DIMC / 1024, 256>>>(x);
    conv_w<<<(K3 * DIMC + DIMC * DIMC) / 1024, 256>>>(Wqkv, Wout);

    // 1) QKV projection: M=33792, N=3072
    gemm_mma<0><<<dim3(K3 / 128, MROWS0 / 128), 256, SMEM_TOTAL>>>(nullptr, nullptr, K3);

    // 2) Patch attention
    attn_kernel<<<dim3(RR, NHEADS, BATCH), 256>>>();

    // 3) Output projection + bias: M=32768, N=1024
    gemm_mma<1><<<dim3(DIMC / 128, MROWS1 / 128), 256, SMEM_TOTAL>>>(bout, out, DIMC);
}

// round 5
// speedup vs baseline: 2.9316x; 1.2117x over previous
#include <cuda_runtime.h>
#include <cuda_bf16.h>
#include <cstdint>
#include <cstddef>

// ---------------------------------------------------------------------------
// Problem constants
// ---------------------------------------------------------------------------
#define DIMC   1024
#define NHEADS 16
#define HDIM   64
#define NTOK   4096
#define NPADR  4224      // per-batch rows padded to multiple of 128
#define BATCH  8
#define RR     206       // 103 blocks * 2 parities
#define SP     20        // tokens per patch
#define K3     3072      // 3*DIM

#define MROWS0 (BATCH*NPADR)   // 33792  (GEMM1 M)
#define MROWS1 (BATCH*NTOK)    // 32768  (GEMM2 M)

// ---------------------------------------------------------------------------
// Device scratch
// ---------------------------------------------------------------------------
__device__ __align__(16) float          g_qkv[(size_t)MROWS0 * K3];     // fp32 qkv (padded rows)
__device__ __align__(16) __nv_bfloat16  g_x_hi[(size_t)MROWS0 * DIMC];
__device__ __align__(16) __nv_bfloat16  g_x_lo[(size_t)MROWS0 * DIMC];
__device__ __align__(16) __nv_bfloat16  g_att_hi[(size_t)MROWS1 * DIMC];
__device__ __align__(16) __nv_bfloat16  g_att_lo[(size_t)MROWS1 * DIMC];
__device__ __align__(16) __nv_bfloat16  g_wq_hi[(size_t)K3 * DIMC];
__device__ __align__(16) __nv_bfloat16  g_wq_lo[(size_t)K3 * DIMC];
__device__ __align__(16) __nv_bfloat16  g_wo_hi[(size_t)DIMC * DIMC];
__device__ __align__(16) __nv_bfloat16  g_wo_lo[(size_t)DIMC * DIMC];

// ---------------------------------------------------------------------------
// Helpers
// ---------------------------------------------------------------------------
__device__ __forceinline__ uint32_t smem_to_u32(const void* p) {
    uint32_t a;
    asm("{ .reg .u64 t; cvta.to.shared.u64 t, %1; cvt.u32.u64 %0, t; }"
        : "=r"(a) : "l"(p));
    return a;
}

__device__ __forceinline__ uint32_t pack_bf(__nv_bfloat16 a, __nv_bfloat16 b) {
    return (uint32_t)__bfloat16_as_ushort(a) | ((uint32_t)__bfloat16_as_ushort(b) << 16);
}

__device__ __forceinline__ void split1(float v, unsigned short& h, unsigned short& l) {
    __nv_bfloat16 hb = __float2bfloat16_rn(v);
    float r = v - __bfloat162float(hb);
    __nv_bfloat16 lb = __float2bfloat16_rn(r);
    h = __bfloat16_as_ushort(hb);
    l = __bfloat16_as_ushort(lb);
}

__device__ __forceinline__ void split4(const float4 v, uint2& hi, uint2& lo) {
    __nv_bfloat16 h0 = __float2bfloat16_rn(v.x), h1 = __float2bfloat16_rn(v.y);
    __nv_bfloat16 h2 = __float2bfloat16_rn(v.z), h3 = __float2bfloat16_rn(v.w);
    __nv_bfloat16 l0 = __float2bfloat16_rn(v.x - __bfloat162float(h0));
    __nv_bfloat16 l1 = __float2bfloat16_rn(v.y - __bfloat162float(h1));
    __nv_bfloat16 l2 = __float2bfloat16_rn(v.z - __bfloat162float(h2));
    __nv_bfloat16 l3 = __float2bfloat16_rn(v.w - __bfloat162float(h3));
    hi.x = pack_bf(h0, h1); hi.y = pack_bf(h2, h3);
    lo.x = pack_bf(l0, l1); lo.y = pack_bf(l2, l3);
}

#define LDSM4(r, addr) \
    asm volatile("ldmatrix.sync.aligned.m8n8.x4.shared.b16 {%0,%1,%2,%3}, [%4];" \
        : "=r"((r)[0]), "=r"((r)[1]), "=r"((r)[2]), "=r"((r)[3]) : "r"(addr))

#define MMA16816(d, a, b0, b1) \
    asm volatile("mma.sync.aligned.m16n8k16.row.col.f32.bf16.bf16.f32 " \
        "{%0,%1,%2,%3}, {%4,%5,%6,%7}, {%8,%9}, {%0,%1,%2,%3};" \
        : "+f"((d)[0]), "+f"((d)[1]), "+f"((d)[2]), "+f"((d)[3]) \
        : "r"((a)[0]), "r"((a)[1]), "r"((a)[2]), "r"((a)[3]), "r"(b0), "r"(b1))

#define CP_ASYNC16(dst, src) \
    asm volatile("cp.async.cg.shared.global [%0], [%1], 16;" :: "r"(dst), "l"(src))
#define CP_COMMIT() asm volatile("cp.async.commit_group;" ::: "memory")
#define CP_WAIT(n)  asm volatile("cp.async.wait_group %0;" :: "n"(n) : "memory")

// ---------------------------------------------------------------------------
// Conversion prepasses: fp32 -> split bf16 (hi/lo)
// ---------------------------------------------------------------------------
__global__ void __launch_bounds__(256) conv_x(const float* __restrict__ x) {
    size_t i = (size_t)blockIdx.x * 256 + threadIdx.x;  // one float4
    size_t e = i * 4;
    size_t rowp = e >> 10;
    int c = (int)(e & 1023);
    int b = (int)(rowp / NPADR);
    int t = (int)(rowp - (size_t)b * NPADR);
    float4 v = make_float4(0.f, 0.f, 0.f, 0.f);
    if (t < NTOK)
        v = *(const float4*)(x + (((size_t)b * NTOK + t) << 10) + c);
    uint2 h, l; split4(v, h, l);
    *(uint2*)(g_x_hi + e) = h;
    *(uint2*)(g_x_lo + e) = l;
}

__global__ void __launch_bounds__(256) conv_w(const float* __restrict__ wq,
                                              const float* __restrict__ wo) {
    size_t i = (size_t)blockIdx.x * 256 + threadIdx.x;
    size_t e = i * 4;
    const size_t NQ = (size_t)K3 * DIMC;
    uint2 h, l;
    if (e < NQ) {
        float4 v = *(const float4*)(wq + e);
        split4(v, h, l);
        *(uint2*)(g_wq_hi + e) = h;
        *(uint2*)(g_wq_lo + e) = l;
    } else {
        size_t o = e - NQ;
        float4 v = *(const float4*)(wo + o);
        split4(v, h, l);
        *(uint2*)(g_wo_hi + o) = h;
        *(uint2*)(g_wo_lo + o) = l;
    }
}

// ---------------------------------------------------------------------------
// Split-bf16 mma.sync GEMM with 3-stage cp.async pipeline.
// ---------------------------------------------------------------------------
#define BK      32
#define NSTAGE  3
#define STAGE   32768
#define OFF_AHI 0
#define OFF_ALO 8192
#define OFF_BHI 16384
#define OFF_BLO 24576
#define SMEM_TOTAL (NSTAGE*STAGE)   // 98304

template<int MODE>
__global__ void __launch_bounds__(256, 2)
gemm_mma(const float* __restrict__ bias, float* __restrict__ Cout, int Ncols)
{
    extern __shared__ char smem[];
    const uint32_t sbase = smem_to_u32(smem);
    const int tid  = threadIdx.x;
    const int lane = tid & 31;
    const int wid  = tid >> 5;
    const int wm   = wid >> 2;   // 0..1
    const int wn   = wid & 3;    // 0..3
    const int m0   = blockIdx.y * 128;
    const int n0   = blockIdx.x * 128;

    const __nv_bfloat16* gAhi = (MODE == 0) ? g_x_hi : g_att_hi;
    const __nv_bfloat16* gAlo = (MODE == 0) ? g_x_lo : g_att_lo;
    const __nv_bfloat16* gBhi = (MODE == 0) ? g_wq_hi : g_wo_hi;
    const __nv_bfloat16* gBlo = (MODE == 0) ? g_wq_lo : g_wo_lo;
    float* C = (MODE == 0) ? g_qkv : Cout;

    uint32_t dsto[2];
    const __nv_bfloat16 *srcAh[2], *srcAl[2], *srcBh[2], *srcBl[2];
    #pragma unroll
    for (int j = 0; j < 2; j++) {
        int c = tid + j * 256;
        int row = c >> 2, col = c & 3;
        dsto[j] = (uint32_t)(row * 64 + (((uint32_t)col ^ (((uint32_t)row >> 1) & 3)) << 4));
        size_t aoff = (size_t)(m0 + row) * DIMC + col * 8;
        size_t boff = (size_t)(n0 + row) * DIMC + col * 8;
        srcAh[j] = gAhi + aoff; srcAl[j] = gAlo + aoff;
        srcBh[j] = gBhi + boff; srcBl[j] = gBlo + boff;
    }

    uint32_t aOff[4], aXor[4];
    #pragma unroll
    for (int mf = 0; mf < 4; mf++) {
        int row = wm * 64 + mf * 16 + (lane & 15);
        aOff[mf] = (uint32_t)row * 64;
        aXor[mf] = ((uint32_t)row >> 1) & 3;
    }
    const uint32_t aHi = (uint32_t)(lane >> 4);
    uint32_t bOff[2], bXor[2];
    #pragma unroll
    for (int g = 0; g < 2; g++) {
        int row = wn * 32 + (lane & 7) + ((lane >> 4) << 3) + g * 16;
        bOff[g] = (uint32_t)row * 64;
        bXor[g] = ((uint32_t)row >> 1) & 3;
    }
    const uint32_t bk = (uint32_t)((lane >> 3) & 1);

    float acc[4][4][4];
    #pragma unroll
    for (int i = 0; i < 4; i++)
        #pragma unroll
        for (int j = 0; j < 4; j++)
            #pragma unroll
            for (int q = 0; q < 4; q++) acc[i][j][q] = 0.f;

    const int NIT = DIMC / BK;   // 32

    #define ISSUE_TILE(tile) do {                                             \
        const uint32_t sd = sbase + (uint32_t)((tile) % NSTAGE) * STAGE;      \
        const int kt = (tile) * BK;                                           \
        _Pragma("unroll")                                                     \
        for (int j = 0; j < 2; j++) {                                         \
            CP_ASYNC16(sd + OFF_AHI + dsto[j], srcAh[j] + kt);                \
            CP_ASYNC16(sd + OFF_ALO + dsto[j], srcAl[j] + kt);                \
            CP_ASYNC16(sd + OFF_BHI + dsto[j], srcBh[j] + kt);                \
            CP_ASYNC16(sd + OFF_BLO + dsto[j], srcBl[j] + kt);                \
        }                                                                     \
        CP_COMMIT();                                                          \
    } while (0)

    ISSUE_TILE(0);
    ISSUE_TILE(1);

    #pragma unroll 1
    for (int it = 0; it < NIT; ++it) {
        if (it < NIT - 1) { CP_WAIT(1); } else { CP_WAIT(0); }
        __syncthreads();
        if (it + 2 < NIT) ISSUE_TILE(it + 2);

        const uint32_t s = sbase + (uint32_t)(it % NSTAGE) * STAGE;
        #pragma unroll
        for (int ks = 0; ks < 2; ++ks) {
            uint32_t ahi[4][4], alo[4][4];
            uint32_t bhi[2][4], blo[2][4];
            #pragma unroll
            for (int mf = 0; mf < 4; mf++) {
                uint32_t c = (((uint32_t)(ks * 2) + aHi) ^ aXor[mf]) << 4;
                LDSM4(ahi[mf], s + OFF_AHI + aOff[mf] + c);
            }
            #pragma unroll
            for (int g = 0; g < 2; g++) {
                uint32_t c = (((uint32_t)(ks * 2) + bk) ^ bXor[g]) << 4;
                LDSM4(bhi[g], s + OFF_BHI + bOff[g] + c);
            }
            #pragma unroll
            for (int mf = 0; mf < 4; mf++)
                #pragma unroll
                for (int nf = 0; nf < 4; nf++) {
                    const int g = nf >> 1, p = (nf & 1) * 2;
                    MMA16816(acc[mf][nf], ahi[mf], bhi[g][p], bhi[g][p + 1]);
                }
            #pragma unroll
            for (int g = 0; g < 2; g++) {
                uint32_t c = (((uint32_t)(ks * 2) + bk) ^ bXor[g]) << 4;
                LDSM4(blo[g], s + OFF_BLO + bOff[g] + c);
            }
            #pragma unroll
            for (int mf = 0; mf < 4; mf++)
                #pragma unroll
                for (int nf = 0; nf < 4; nf++) {
                    const int g = nf >> 1, p = (nf & 1) * 2;
                    MMA16816(acc[mf][nf], ahi[mf], blo[g][p], blo[g][p + 1]);
                }
            #pragma unroll
            for (int mf = 0; mf < 4; mf++) {
                uint32_t c = (((uint32_t)(ks * 2) + aHi) ^ aXor[mf]) << 4;
                LDSM4(alo[mf], s + OFF_ALO + aOff[mf] + c);
            }
            #pragma unroll
            for (int mf = 0; mf < 4; mf++)
                #pragma unroll
                for (int nf = 0; nf < 4; nf++) {
                    const int g = nf >> 1, p = (nf & 1) * 2;
                    MMA16816(acc[mf][nf], alo[mf], bhi[g][p], bhi[g][p + 1]);
                }
        }
        __syncthreads();
    }
    #undef ISSUE_TILE

    const int grp = lane >> 2;
    const int thr = lane & 3;
    #pragma unroll
    for (int mf = 0; mf < 4; mf++) {
        const int mrow = m0 + wm * 64 + mf * 16 + grp;
        #pragma unroll
        for (int nf = 0; nf < 4; nf++) {
            const int col = n0 + wn * 32 + nf * 8 + thr * 2;
            float2 v0 = make_float2(acc[mf][nf][0], acc[mf][nf][1]);
            float2 v1 = make_float2(acc[mf][nf][2], acc[mf][nf][3]);
            if (MODE == 1) {
                const float2 bv = *(const float2*)(bias + col);
                v0.x += bv.x; v0.y += bv.y;
                v1.x += bv.x; v1.y += bv.y;
            }
            *(float2*)(C + (size_t)mrow * Ncols + col)       = v0;
            *(float2*)(C + (size_t)(mrow + 8) * Ncols + col) = v1;
        }
    }
}

// ---------------------------------------------------------------------------
// Per-patch attention, bank-conflict-free SMEM layout.
//   q[s][e]  stride 68  (s-groups in a warp land on different banks)
//   kT[e][t] stride SP  (dots phase: lanes differ in t -> distinct banks / bcast)
//   v[t][e]  stride 64  (AV phase: lanes differ in e -> distinct banks)
// ---------------------------------------------------------------------------
#define QSTR 68
__global__ void __launch_bounds__(256) attn_kernel()
{
    const int r   = blockIdx.x;
    const int h   = blockIdx.y;
    const int b   = blockIdx.z;
    const int blk = r >> 1, par = r & 1;

    __shared__ float q[SP][QSTR];
    __shared__ float kT[HDIM][SP];
    __shared__ float v[SP][HDIM];
    __shared__ float dots[SP][SP];

    const int tid = threadIdx.x;
    const size_t base = (size_t)b * NPADR * K3;

    // Load q/k/v tiles (20 tokens x 16 float4 each)
    for (int i = tid; i < SP * 16; i += 256) {
        int s = i >> 4, j = i & 15;
        int n = blk * 40 + par + 2 * s;
        const float* rp = g_qkv + base + (size_t)n * K3 + h * HDIM;
        float4 qv = ((const float4*)(rp))[j];
        float4 kv = ((const float4*)(rp + DIMC))[j];
        float4 vv = ((const float4*)(rp + 2 * DIMC))[j];
        q[s][4 * j + 0] = qv.x; q[s][4 * j + 1] = qv.y;
        q[s][4 * j + 2] = qv.z; q[s][4 * j + 3] = qv.w;
        kT[4 * j + 0][s] = kv.x; kT[4 * j + 1][s] = kv.y;
        kT[4 * j + 2][s] = kv.z; kT[4 * j + 3][s] = kv.w;
        ((float4*)v[s])[j] = vv;
    }
    __syncthreads();

    // dots[s][t] = scale * <q_s, k_t>
    const float scale = 0.125f;  // 64^-0.5
    for (int i = tid; i < SP * SP; i += 256) {
        int s = i / SP, t = i - s * SP;
        float sum = 0.f;
        #pragma unroll
        for (int e = 0; e < HDIM; e++) sum += q[s][e] * kT[e][t];
        dots[s][t] = sum * scale;
    }
    __syncthreads();

    // Row softmax (threads 0..19)
    if (tid < SP) {
        float mx = -1e30f;
        #pragma unroll
        for (int t = 0; t < SP; t++) mx = fmaxf(mx, dots[tid][t]);
        float ex[SP]; float sum = 0.f;
        #pragma unroll
        for (int t = 0; t < SP; t++) { float e = expf(dots[tid][t] - mx); ex[t] = e; sum += e; }
        float inv = 1.f / sum;
        #pragma unroll
        for (int t = 0; t < SP; t++) dots[tid][t] = ex[t] * inv;
    }
    __syncthreads();

    // out[s][e] = sum_t attn[s][t] * v[t][e]; write split bf16
    for (int i = tid; i < SP * HDIM; i += 256) {
        int s = i >> 6, e = i & 63;
        int n = blk * 40 + par + 2 * s;
        if (n >= NTOK) continue;
        float sum = 0.f;
        #pragma unroll
        for (int t = 0; t < SP; t++) sum += dots[s][t] * v[t][e];
        unsigned short hh, ll;
        split1(sum, hh, ll);
        size_t idx = ((size_t)b * NTOK + n) * DIMC + h * HDIM + e;
        g_att_hi[idx] = __ushort_as_bfloat16(hh);
        g_att_lo[idx] = __ushort_as_bfloat16(ll);
    }
}

// ---------------------------------------------------------------------------
extern "C" void kernel_launch(void* const* d_in, const int* in_sizes, int n_in,
                              void* d_out, int out_size)
{
    const float* x    = (const float*)d_in[0];  // (8, 4096, 1024)
    const float* Wqkv = (const float*)d_in[1];  // (3072, 1024)
    const float* Wout = (const float*)d_in[2];  // (1024, 1024)
    const float* bout = (const float*)d_in[3];  // (1024,)
    float* out = (float*)d_out;                 // (8, 4096, 1024)

    static bool attr_done = false;
    if (!attr_done) {
        cudaFuncSetAttribute(gemm_mma<0>, cudaFuncAttributeMaxDynamicSharedMemorySize, SMEM_TOTAL);
        cudaFuncSetAttribute(gemm_mma<1>, cudaFuncAttributeMaxDynamicSharedMemorySize, SMEM_TOTAL);
        attr_done = true;
    }

    // 0) Split inputs/weights into bf16 hi/lo
    conv_x<<<MROWS0 * DIMC / 1024, 256>>>(x);
    conv_w<<<(K3 * DIMC + DIMC * DIMC) / 1024, 256>>>(Wqkv, Wout);

    // 1) QKV projection: M=33792, N=3072
    gemm_mma<0><<<dim3(K3 / 128, MROWS0 / 128), 256, SMEM_TOTAL>>>(nullptr, nullptr, K3);

    // 2) Patch attention
    attn_kernel<<<dim3(RR, NHEADS, BATCH), 256>>>();

    // 3) Output projection + bias: M=32768, N=1024
    gemm_mma<1><<<dim3(DIMC / 128, MROWS1 / 128), 256, SMEM_TOTAL>>>(bout, out, DIMC);
}

// round 6
// speedup vs baseline: 3.1017x; 1.0580x over previous
#include <cuda_runtime.h>
#include <cuda_bf16.h>
#include <cstdint>
#include <cstddef>

// ---------------------------------------------------------------------------
// Problem constants
// ---------------------------------------------------------------------------
#define DIMC   1024
#define NHEADS 16
#define HDIM   64
#define NTOK   4096
#define NPADR  4224      // per-batch rows padded to multiple of 128
#define BATCH  8
#define RR     206       // 103 blocks * 2 parities
#define SP     20        // tokens per patch
#define K3     3072      // 3*DIM

#define MROWS0 (BATCH*NPADR)   // 33792  (GEMM1 M)
#define MROWS1 (BATCH*NTOK)    // 32768  (GEMM2 M)

// ---------------------------------------------------------------------------
// Device scratch
// ---------------------------------------------------------------------------
__device__ __align__(16) float          g_qkv[(size_t)MROWS0 * K3];
__device__ __align__(16) __nv_bfloat16  g_x_hi[(size_t)MROWS0 * DIMC];
__device__ __align__(16) __nv_bfloat16  g_x_lo[(size_t)MROWS0 * DIMC];
__device__ __align__(16) __nv_bfloat16  g_att_hi[(size_t)MROWS1 * DIMC];
__device__ __align__(16) __nv_bfloat16  g_att_lo[(size_t)MROWS1 * DIMC];
__device__ __align__(16) __nv_bfloat16  g_wq_hi[(size_t)K3 * DIMC];
__device__ __align__(16) __nv_bfloat16  g_wq_lo[(size_t)K3 * DIMC];
__device__ __align__(16) __nv_bfloat16  g_wo_hi[(size_t)DIMC * DIMC];
__device__ __align__(16) __nv_bfloat16  g_wo_lo[(size_t)DIMC * DIMC];

// ---------------------------------------------------------------------------
// Helpers
// ---------------------------------------------------------------------------
__device__ __forceinline__ uint32_t smem_to_u32(const void* p) {
    uint32_t a;
    asm("{ .reg .u64 t; cvta.to.shared.u64 t, %1; cvt.u32.u64 %0, t; }"
        : "=r"(a) : "l"(p));
    return a;
}

__device__ __forceinline__ uint32_t pack_bf(__nv_bfloat16 a, __nv_bfloat16 b) {
    return (uint32_t)__bfloat16_as_ushort(a) | ((uint32_t)__bfloat16_as_ushort(b) << 16);
}

__device__ __forceinline__ void split1(float v, unsigned short& h, unsigned short& l) {
    __nv_bfloat16 hb = __float2bfloat16_rn(v);
    float r = v - __bfloat162float(hb);
    __nv_bfloat16 lb = __float2bfloat16_rn(r);
    h = __bfloat16_as_ushort(hb);
    l = __bfloat16_as_ushort(lb);
}

__device__ __forceinline__ void split4(const float4 v, uint2& hi, uint2& lo) {
    __nv_bfloat16 h0 = __float2bfloat16_rn(v.x), h1 = __float2bfloat16_rn(v.y);
    __nv_bfloat16 h2 = __float2bfloat16_rn(v.z), h3 = __float2bfloat16_rn(v.w);
    __nv_bfloat16 l0 = __float2bfloat16_rn(v.x - __bfloat162float(h0));
    __nv_bfloat16 l1 = __float2bfloat16_rn(v.y - __bfloat162float(h1));
    __nv_bfloat16 l2 = __float2bfloat16_rn(v.z - __bfloat162float(h2));
    __nv_bfloat16 l3 = __float2bfloat16_rn(v.w - __bfloat162float(h3));
    hi.x = pack_bf(h0, h1); hi.y = pack_bf(h2, h3);
    lo.x = pack_bf(l0, l1); lo.y = pack_bf(l2, l3);
}

#define LDSM4(r, addr) \
    asm volatile("ldmatrix.sync.aligned.m8n8.x4.shared.b16 {%0,%1,%2,%3}, [%4];" \
        : "=r"((r)[0]), "=r"((r)[1]), "=r"((r)[2]), "=r"((r)[3]) : "r"(addr))

#define MMA16816(d, a, b0, b1) \
    asm volatile("mma.sync.aligned.m16n8k16.row.col.f32.bf16.bf16.f32 " \
        "{%0,%1,%2,%3}, {%4,%5,%6,%7}, {%8,%9}, {%0,%1,%2,%3};" \
        : "+f"((d)[0]), "+f"((d)[1]), "+f"((d)[2]), "+f"((d)[3]) \
        : "r"((a)[0]), "r"((a)[1]), "r"((a)[2]), "r"((a)[3]), "r"(b0), "r"(b1))

#define CP_ASYNC16(dst, src) \
    asm volatile("cp.async.cg.shared.global [%0], [%1], 16;" :: "r"(dst), "l"(src))
#define CP_COMMIT() asm volatile("cp.async.commit_group;" ::: "memory")
#define CP_WAIT(n)  asm volatile("cp.async.wait_group %0;" :: "n"(n) : "memory")

// ---------------------------------------------------------------------------
// Conversion prepasses: fp32 -> split bf16 (hi/lo)
// ---------------------------------------------------------------------------
__global__ void __launch_bounds__(256) conv_x(const float* __restrict__ x) {
    size_t i = (size_t)blockIdx.x * 256 + threadIdx.x;  // one float4
    size_t e = i * 4;
    size_t rowp = e >> 10;
    int c = (int)(e & 1023);
    int b = (int)(rowp / NPADR);
    int t = (int)(rowp - (size_t)b * NPADR);
    float4 v = make_float4(0.f, 0.f, 0.f, 0.f);
    if (t < NTOK)
        v = *(const float4*)(x + (((size_t)b * NTOK + t) << 10) + c);
    uint2 h, l; split4(v, h, l);
    *(uint2*)(g_x_hi + e) = h;
    *(uint2*)(g_x_lo + e) = l;
}

__global__ void __launch_bounds__(256) conv_w(const float* __restrict__ wq,
                                              const float* __restrict__ wo) {
    size_t i = (size_t)blockIdx.x * 256 + threadIdx.x;
    size_t e = i * 4;
    const size_t NQ = (size_t)K3 * DIMC;
    uint2 h, l;
    if (e < NQ) {
        float4 v = *(const float4*)(wq + e);
        split4(v, h, l);
        *(uint2*)(g_wq_hi + e) = h;
        *(uint2*)(g_wq_lo + e) = l;
    } else {
        size_t o = e - NQ;
        float4 v = *(const float4*)(wo + o);
        split4(v, h, l);
        *(uint2*)(g_wo_hi + o) = h;
        *(uint2*)(g_wo_lo + o) = l;
    }
}

// ---------------------------------------------------------------------------
// Split-bf16 mma.sync GEMM, CTA 128x128, 4 warps (warp tile 64x64), BK=32,
// 3-stage cp.async pipeline. 2 CTAs/SM.
// Stage (32 KB): A_hi 8K | A_lo 8K | B_hi 8K | B_lo 8K.
// ---------------------------------------------------------------------------
#define BK      32
#define NSTAGE  3
#define STAGE   32768
#define OFF_AHI 0
#define OFF_ALO 8192
#define OFF_BHI 16384
#define OFF_BLO 24576
#define SMEM_TOTAL (NSTAGE*STAGE)   // 98304

template<int MODE>
__global__ void __launch_bounds__(128, 2)
gemm_mma(const float* __restrict__ bias, float* __restrict__ Cout, int Ncols)
{
    extern __shared__ char smem[];
    const uint32_t sbase = smem_to_u32(smem);
    const int tid  = threadIdx.x;
    const int lane = tid & 31;
    const int wid  = tid >> 5;   // 0..3
    const int wm   = wid >> 1;   // 0..1
    const int wn   = wid & 1;    // 0..1
    const int m0   = blockIdx.y * 128;
    const int n0   = blockIdx.x * 128;

    const __nv_bfloat16* gAhi = (MODE == 0) ? g_x_hi : g_att_hi;
    const __nv_bfloat16* gAlo = (MODE == 0) ? g_x_lo : g_att_lo;
    const __nv_bfloat16* gBhi = (MODE == 0) ? g_wq_hi : g_wo_hi;
    const __nv_bfloat16* gBlo = (MODE == 0) ? g_wq_lo : g_wo_lo;
    float* C = (MODE == 0) ? g_qkv : Cout;

    // cp.async: 4 chunks of 16B per thread per region (512 chunks per region)
    uint32_t dsto[4];
    const __nv_bfloat16 *srcAh[4], *srcAl[4], *srcBh[4], *srcBl[4];
    #pragma unroll
    for (int j = 0; j < 4; j++) {
        int c = tid + j * 128;
        int row = c >> 2, col = c & 3;
        dsto[j] = (uint32_t)(row * 64 + (((uint32_t)col ^ (((uint32_t)row >> 1) & 3)) << 4));
        size_t aoff = (size_t)(m0 + row) * DIMC + col * 8;
        size_t boff = (size_t)(n0 + row) * DIMC + col * 8;
        srcAh[j] = gAhi + aoff; srcAl[j] = gAlo + aoff;
        srcBh[j] = gBhi + boff; srcBl[j] = gBlo + boff;
    }

    // ldmatrix address components. A: 4 m-frags of 16 rows; B: 4 n-groups of 16.
    uint32_t aOff[4], aXor[4];
    #pragma unroll
    for (int mf = 0; mf < 4; mf++) {
        int row = wm * 64 + mf * 16 + (lane & 15);
        aOff[mf] = (uint32_t)row * 64;
        aXor[mf] = ((uint32_t)row >> 1) & 3;
    }
    const uint32_t aHi = (uint32_t)(lane >> 4);
    uint32_t bOff[4], bXor[4];
    #pragma unroll
    for (int g = 0; g < 4; g++) {
        int row = wn * 64 + (lane & 7) + ((lane >> 4) << 3) + g * 16;
        bOff[g] = (uint32_t)row * 64;
        bXor[g] = ((uint32_t)row >> 1) & 3;
    }
    const uint32_t bk = (uint32_t)((lane >> 3) & 1);

    float acc[4][8][4];
    #pragma unroll
    for (int i = 0; i < 4; i++)
        #pragma unroll
        for (int j = 0; j < 8; j++)
            #pragma unroll
            for (int q = 0; q < 4; q++) acc[i][j][q] = 0.f;

    const int NIT = DIMC / BK;   // 32

    #define ISSUE_TILE(tile) do {                                             \
        const uint32_t sd = sbase + (uint32_t)((tile) % NSTAGE) * STAGE;      \
        const int kt = (tile) * BK;                                           \
        _Pragma("unroll")                                                     \
        for (int j = 0; j < 4; j++) {                                         \
            CP_ASYNC16(sd + OFF_AHI + dsto[j], srcAh[j] + kt);                \
            CP_ASYNC16(sd + OFF_ALO + dsto[j], srcAl[j] + kt);                \
            CP_ASYNC16(sd + OFF_BHI + dsto[j], srcBh[j] + kt);                \
            CP_ASYNC16(sd + OFF_BLO + dsto[j], srcBl[j] + kt);                \
        }                                                                     \
        CP_COMMIT();                                                          \
    } while (0)

    ISSUE_TILE(0);
    ISSUE_TILE(1);

    #pragma unroll 1
    for (int it = 0; it < NIT; ++it) {
        if (it < NIT - 1) { CP_WAIT(1); } else { CP_WAIT(0); }
        __syncthreads();
        if (it + 2 < NIT) ISSUE_TILE(it + 2);

        const uint32_t s = sbase + (uint32_t)(it % NSTAGE) * STAGE;
        #pragma unroll
        for (int ks = 0; ks < 2; ++ks) {
            uint32_t ahi[4][4], alo[4][4];
            uint32_t bhi[4][4], blo[4][4];
            // hi*hi
            #pragma unroll
            for (int mf = 0; mf < 4; mf++) {
                uint32_t c = (((uint32_t)(ks * 2) + aHi) ^ aXor[mf]) << 4;
                LDSM4(ahi[mf], s + OFF_AHI + aOff[mf] + c);
            }
            #pragma unroll
            for (int g = 0; g < 4; g++) {
                uint32_t c = (((uint32_t)(ks * 2) + bk) ^ bXor[g]) << 4;
                LDSM4(bhi[g], s + OFF_BHI + bOff[g] + c);
            }
            #pragma unroll
            for (int mf = 0; mf < 4; mf++)
                #pragma unroll
                for (int nf = 0; nf < 8; nf++) {
                    const int g = nf >> 1, p = (nf & 1) * 2;
                    MMA16816(acc[mf][nf], ahi[mf], bhi[g][p], bhi[g][p + 1]);
                }
            // hi*lo
            #pragma unroll
            for (int g = 0; g < 4; g++) {
                uint32_t c = (((uint32_t)(ks * 2) + bk) ^ bXor[g]) << 4;
                LDSM4(blo[g], s + OFF_BLO + bOff[g] + c);
            }
            #pragma unroll
            for (int mf = 0; mf < 4; mf++)
                #pragma unroll
                for (int nf = 0; nf < 8; nf++) {
                    const int g = nf >> 1, p = (nf & 1) * 2;
                    MMA16816(acc[mf][nf], ahi[mf], blo[g][p], blo[g][p + 1]);
                }
            // lo*hi
            #pragma unroll
            for (int mf = 0; mf < 4; mf++) {
                uint32_t c = (((uint32_t)(ks * 2) + aHi) ^ aXor[mf]) << 4;
                LDSM4(alo[mf], s + OFF_ALO + aOff[mf] + c);
            }
            #pragma unroll
            for (int mf = 0; mf < 4; mf++)
                #pragma unroll
                for (int nf = 0; nf < 8; nf++) {
                    const int g = nf >> 1, p = (nf & 1) * 2;
                    MMA16816(acc[mf][nf], alo[mf], bhi[g][p], bhi[g][p + 1]);
                }
        }
        __syncthreads();
    }
    #undef ISSUE_TILE

    // Epilogue
    const int grp = lane >> 2;
    const int thr = lane & 3;
    #pragma unroll
    for (int mf = 0; mf < 4; mf++) {
        const int mrow = m0 + wm * 64 + mf * 16 + grp;
        #pragma unroll
        for (int nf = 0; nf < 8; nf++) {
            const int col = n0 + wn * 64 + nf * 8 + thr * 2;
            float2 v0 = make_float2(acc[mf][nf][0], acc[mf][nf][1]);
            float2 v1 = make_float2(acc[mf][nf][2], acc[mf][nf][3]);
            if (MODE == 1) {
                const float2 bv = *(const float2*)(bias + col);
                v0.x += bv.x; v0.y += bv.y;
                v1.x += bv.x; v1.y += bv.y;
            }
            *(float2*)(C + (size_t)mrow * Ncols + col)       = v0;
            *(float2*)(C + (size_t)(mrow + 8) * Ncols + col) = v1;
        }
    }
}

// ---------------------------------------------------------------------------
// Per-patch attention, float4-vectorized, conflict-free SMEM.
// q/k/v rows padded to 68 floats (bank = 4*row + 4*e4 mod 32, conflict-free).
// ---------------------------------------------------------------------------
#define RSTR 68
__global__ void __launch_bounds__(256) attn_kernel()
{
    const int r   = blockIdx.x;
    const int h   = blockIdx.y;
    const int b   = blockIdx.z;
    const int blk = r >> 1, par = r & 1;

    __shared__ float q[SP * RSTR];
    __shared__ float k[SP * RSTR];
    __shared__ float v[SP * RSTR];
    __shared__ float dots[SP][SP + 1];

    const int tid = threadIdx.x;
    const size_t base = (size_t)b * NPADR * K3;

    // Load q/k/v tiles (20 tokens x 16 float4 each)
    for (int i = tid; i < SP * 16; i += 256) {
        int s = i >> 4, j = i & 15;
        int n = blk * 40 + par + 2 * s;
        const float* rp = g_qkv + base + (size_t)n * K3 + h * HDIM;
        *(float4*)(q + s * RSTR + 4 * j) = ((const float4*)(rp))[j];
        *(float4*)(k + s * RSTR + 4 * j) = ((const float4*)(rp + DIMC))[j];
        *(float4*)(v + s * RSTR + 4 * j) = ((const float4*)(rp + 2 * DIMC))[j];
    }
    __syncthreads();

    // dots[s][t] = scale * <q_s, k_t>   (float4 inner loop)
    const float scale = 0.125f;  // 64^-0.5
    for (int i = tid; i < SP * SP; i += 256) {
        int s = i / SP, t = i - s * SP;
        const float4* qp = (const float4*)(q + s * RSTR);
        const float4* kp = (const float4*)(k + t * RSTR);
        float sum = 0.f;
        #pragma unroll
        for (int e4 = 0; e4 < 16; e4++) {
            float4 a = qp[e4], c = kp[e4];
            sum = fmaf(a.x, c.x, sum); sum = fmaf(a.y, c.y, sum);
            sum = fmaf(a.z, c.z, sum); sum = fmaf(a.w, c.w, sum);
        }
        dots[s][t] = sum * scale;
    }
    __syncthreads();

    // Row softmax (threads 0..19)
    if (tid < SP) {
        float mx = -1e30f;
        #pragma unroll
        for (int t = 0; t < SP; t++) mx = fmaxf(mx, dots[tid][t]);
        float ex[SP]; float sum = 0.f;
        #pragma unroll
        for (int t = 0; t < SP; t++) { float e = expf(dots[tid][t] - mx); ex[t] = e; sum += e; }
        float inv = 1.f / sum;
        #pragma unroll
        for (int t = 0; t < SP; t++) dots[tid][t] = ex[t] * inv;
    }
    __syncthreads();

    // out[s][e4*4..] = sum_t attn[s][t] * v[t][...]; write split bf16 (float4 lanes)
    for (int i = tid; i < SP * 16; i += 256) {
        int s = i >> 4, e4 = i & 15;
        int n = blk * 40 + par + 2 * s;
        if (n >= NTOK) continue;
        float4 sum = make_float4(0.f, 0.f, 0.f, 0.f);
        #pragma unroll
        for (int t = 0; t < SP; t++) {
            float w = dots[s][t];
            float4 vv = *(const float4*)(v + t * RSTR + 4 * e4);
            sum.x = fmaf(w, vv.x, sum.x); sum.y = fmaf(w, vv.y, sum.y);
            sum.z = fmaf(w, vv.z, sum.z); sum.w = fmaf(w, vv.w, sum.w);
        }
        uint2 hh, ll;
        split4(sum, hh, ll);
        size_t idx = ((size_t)b * NTOK + n) * DIMC + h * HDIM + e4 * 4;
        *(uint2*)(g_att_hi + idx) = hh;
        *(uint2*)(g_att_lo + idx) = ll;
    }
}

// ---------------------------------------------------------------------------
extern "C" void kernel_launch(void* const* d_in, const int* in_sizes, int n_in,
                              void* d_out, int out_size)
{
    const float* x    = (const float*)d_in[0];  // (8, 4096, 1024)
    const float* Wqkv = (const float*)d_in[1];  // (3072, 1024)
    const float* Wout = (const float*)d_in[2];  // (1024, 1024)
    const float* bout = (const float*)d_in[3];  // (1024,)
    float* out = (float*)d_out;                 // (8, 4096, 1024)

    static bool attr_done = false;
    if (!attr_done) {
        cudaFuncSetAttribute(gemm_mma<0>, cudaFuncAttributeMaxDynamicSharedMemorySize, SMEM_TOTAL);
        cudaFuncSetAttribute(gemm_mma<1>, cudaFuncAttributeMaxDynamicSharedMemorySize, SMEM_TOTAL);
        attr_done = true;
    }

    // 0) Split inputs/weights into bf16 hi/lo
    conv_x<<<MROWS0 * DIMC / 1024, 256>>>(x);
    conv_w<<<(K3 * DIMC + DIMC * DIMC) / 1024, 256>>>(Wqkv, Wout);

    // 1) QKV projection: M=33792, N=3072
    gemm_mma<0><<<dim3(K3 / 128, MROWS0 / 128), 128, SMEM_TOTAL>>>(nullptr, nullptr, K3);

    // 2) Patch attention
    attn_kernel<<<dim3(RR, NHEADS, BATCH), 256>>>();

    // 3) Output projection + bias: M=32768, N=1024
    gemm_mma<1><<<dim3(DIMC / 128, MROWS1 / 128), 128, SMEM_TOTAL>>>(bout, out, DIMC);
}

// round 7
// speedup vs baseline: 3.1959x; 1.0304x over previous
#include <cuda_runtime.h>
#include <cuda_bf16.h>
#include <cstdint>
#include <cstddef>

// ---------------------------------------------------------------------------
// Problem constants
// ---------------------------------------------------------------------------
#define DIMC   1024
#define NHEADS 16
#define HDIM   64
#define NTOK   4096
#define NPADR  4224      // per-batch rows padded to multiple of 128
#define BATCH  8
#define RR     206       // 103 blocks * 2 parities
#define SP     20        // tokens per patch
#define K3     3072      // 3*DIM

#define MROWS0 (BATCH*NPADR)   // 33792  (GEMM1 M)
#define MROWS1 (BATCH*NTOK)    // 32768  (GEMM2 M)

// ---------------------------------------------------------------------------
// Device scratch
// ---------------------------------------------------------------------------
__device__ __align__(16) float          g_qkv[(size_t)MROWS0 * K3];
__device__ __align__(16) __nv_bfloat16  g_x_hi[(size_t)MROWS0 * DIMC];
__device__ __align__(16) __nv_bfloat16  g_x_lo[(size_t)MROWS0 * DIMC];
__device__ __align__(16) __nv_bfloat16  g_att_hi[(size_t)MROWS1 * DIMC];
__device__ __align__(16) __nv_bfloat16  g_att_lo[(size_t)MROWS1 * DIMC];
__device__ __align__(16) __nv_bfloat16  g_wq_hi[(size_t)K3 * DIMC];
__device__ __align__(16) __nv_bfloat16  g_wq_lo[(size_t)K3 * DIMC];
__device__ __align__(16) __nv_bfloat16  g_wo_hi[(size_t)DIMC * DIMC];
__device__ __align__(16) __nv_bfloat16  g_wo_lo[(size_t)DIMC * DIMC];

// ---------------------------------------------------------------------------
// Helpers
// ---------------------------------------------------------------------------
__device__ __forceinline__ uint32_t smem_to_u32(const void* p) {
    uint32_t a;
    asm("{ .reg .u64 t; cvta.to.shared.u64 t, %1; cvt.u32.u64 %0, t; }"
        : "=r"(a) : "l"(p));
    return a;
}

__device__ __forceinline__ uint32_t pack_bf(__nv_bfloat16 a, __nv_bfloat16 b) {
    return (uint32_t)__bfloat16_as_ushort(a) | ((uint32_t)__bfloat16_as_ushort(b) << 16);
}

__device__ __forceinline__ void split4(const float4 v, uint2& hi, uint2& lo) {
    __nv_bfloat16 h0 = __float2bfloat16_rn(v.x), h1 = __float2bfloat16_rn(v.y);
    __nv_bfloat16 h2 = __float2bfloat16_rn(v.z), h3 = __float2bfloat16_rn(v.w);
    __nv_bfloat16 l0 = __float2bfloat16_rn(v.x - __bfloat162float(h0));
    __nv_bfloat16 l1 = __float2bfloat16_rn(v.y - __bfloat162float(h1));
    __nv_bfloat16 l2 = __float2bfloat16_rn(v.z - __bfloat162float(h2));
    __nv_bfloat16 l3 = __float2bfloat16_rn(v.w - __bfloat162float(h3));
    hi.x = pack_bf(h0, h1); hi.y = pack_bf(h2, h3);
    lo.x = pack_bf(l0, l1); lo.y = pack_bf(l2, l3);
}

#define LDSM4(r, addr) \
    asm volatile("ldmatrix.sync.aligned.m8n8.x4.shared.b16 {%0,%1,%2,%3}, [%4];" \
        : "=r"((r)[0]), "=r"((r)[1]), "=r"((r)[2]), "=r"((r)[3]) : "r"(addr))

#define MMA16816(d, a, b0, b1) \
    asm volatile("mma.sync.aligned.m16n8k16.row.col.f32.bf16.bf16.f32 " \
        "{%0,%1,%2,%3}, {%4,%5,%6,%7}, {%8,%9}, {%0,%1,%2,%3};" \
        : "+f"((d)[0]), "+f"((d)[1]), "+f"((d)[2]), "+f"((d)[3]) \
        : "r"((a)[0]), "r"((a)[1]), "r"((a)[2]), "r"((a)[3]), "r"(b0), "r"(b1))

#define CP_ASYNC16(dst, src) \
    asm volatile("cp.async.cg.shared.global [%0], [%1], 16;" :: "r"(dst), "l"(src))
#define CP_COMMIT() asm volatile("cp.async.commit_group;" ::: "memory")
#define CP_WAIT(n)  asm volatile("cp.async.wait_group %0;" :: "n"(n) : "memory")

// ---------------------------------------------------------------------------
// Conversion prepasses: fp32 -> split bf16 (hi/lo)
// ---------------------------------------------------------------------------
__global__ void __launch_bounds__(256) conv_x(const float* __restrict__ x) {
    size_t i = (size_t)blockIdx.x * 256 + threadIdx.x;  // one float4
    size_t e = i * 4;
    size_t rowp = e >> 10;
    int c = (int)(e & 1023);
    int b = (int)(rowp / NPADR);
    int t = (int)(rowp - (size_t)b * NPADR);
    float4 v = make_float4(0.f, 0.f, 0.f, 0.f);
    if (t < NTOK)
        v = *(const float4*)(x + (((size_t)b * NTOK + t) << 10) + c);
    uint2 h, l; split4(v, h, l);
    *(uint2*)(g_x_hi + e) = h;
    *(uint2*)(g_x_lo + e) = l;
}

__global__ void __launch_bounds__(256) conv_w(const float* __restrict__ wq,
                                              const float* __restrict__ wo) {
    size_t i = (size_t)blockIdx.x * 256 + threadIdx.x;
    size_t e = i * 4;
    const size_t NQ = (size_t)K3 * DIMC;
    uint2 h, l;
    if (e < NQ) {
        float4 v = *(const float4*)(wq + e);
        split4(v, h, l);
        *(uint2*)(g_wq_hi + e) = h;
        *(uint2*)(g_wq_lo + e) = l;
    } else {
        size_t o = e - NQ;
        float4 v = *(const float4*)(wo + o);
        split4(v, h, l);
        *(uint2*)(g_wo_hi + o) = h;
        *(uint2*)(g_wo_lo + o) = l;
    }
}

// ---------------------------------------------------------------------------
// Split-bf16 mma.sync GEMM, CTA 128x128, 4 warps (warp tile 64x64), BK=32,
// 3-stage cp.async pipeline, SINGLE barrier per k-iter. 2 CTAs/SM.
// ---------------------------------------------------------------------------
#define BK      32
#define NSTAGE  3
#define STAGE   32768
#define OFF_AHI 0
#define OFF_ALO 8192
#define OFF_BHI 16384
#define OFF_BLO 24576
#define SMEM_TOTAL (NSTAGE*STAGE)   // 98304

template<int MODE>
__global__ void __launch_bounds__(128, 2)
gemm_mma(const float* __restrict__ bias, float* __restrict__ Cout, int Ncols)
{
    extern __shared__ char smem[];
    const uint32_t sbase = smem_to_u32(smem);
    const int tid  = threadIdx.x;
    const int lane = tid & 31;
    const int wid  = tid >> 5;   // 0..3
    const int wm   = wid >> 1;   // 0..1
    const int wn   = wid & 1;    // 0..1
    const int m0   = blockIdx.y * 128;
    const int n0   = blockIdx.x * 128;

    const __nv_bfloat16* gAhi = (MODE == 0) ? g_x_hi : g_att_hi;
    const __nv_bfloat16* gAlo = (MODE == 0) ? g_x_lo : g_att_lo;
    const __nv_bfloat16* gBhi = (MODE == 0) ? g_wq_hi : g_wo_hi;
    const __nv_bfloat16* gBlo = (MODE == 0) ? g_wq_lo : g_wo_lo;
    float* C = (MODE == 0) ? g_qkv : Cout;

    uint32_t dsto[4];
    const __nv_bfloat16 *srcAh[4], *srcAl[4], *srcBh[4], *srcBl[4];
    #pragma unroll
    for (int j = 0; j < 4; j++) {
        int c = tid + j * 128;
        int row = c >> 2, col = c & 3;
        dsto[j] = (uint32_t)(row * 64 + (((uint32_t)col ^ (((uint32_t)row >> 1) & 3)) << 4));
        size_t aoff = (size_t)(m0 + row) * DIMC + col * 8;
        size_t boff = (size_t)(n0 + row) * DIMC + col * 8;
        srcAh[j] = gAhi + aoff; srcAl[j] = gAlo + aoff;
        srcBh[j] = gBhi + boff; srcBl[j] = gBlo + boff;
    }

    uint32_t aOff[4], aXor[4];
    #pragma unroll
    for (int mf = 0; mf < 4; mf++) {
        int row = wm * 64 + mf * 16 + (lane & 15);
        aOff[mf] = (uint32_t)row * 64;
        aXor[mf] = ((uint32_t)row >> 1) & 3;
    }
    const uint32_t aHi = (uint32_t)(lane >> 4);
    uint32_t bOff[4], bXor[4];
    #pragma unroll
    for (int g = 0; g < 4; g++) {
        int row = wn * 64 + (lane & 7) + ((lane >> 4) << 3) + g * 16;
        bOff[g] = (uint32_t)row * 64;
        bXor[g] = ((uint32_t)row >> 1) & 3;
    }
    const uint32_t bk = (uint32_t)((lane >> 3) & 1);

    float acc[4][8][4];
    #pragma unroll
    for (int i = 0; i < 4; i++)
        #pragma unroll
        for (int j = 0; j < 8; j++)
            #pragma unroll
            for (int q = 0; q < 4; q++) acc[i][j][q] = 0.f;

    const int NIT = DIMC / BK;   // 32

    #define ISSUE_TILE(tile) do {                                             \
        const uint32_t sd = sbase + (uint32_t)((tile) % NSTAGE) * STAGE;      \
        const int kt = (tile) * BK;                                           \
        _Pragma("unroll")                                                     \
        for (int j = 0; j < 4; j++) {                                         \
            CP_ASYNC16(sd + OFF_AHI + dsto[j], srcAh[j] + kt);                \
            CP_ASYNC16(sd + OFF_ALO + dsto[j], srcAl[j] + kt);                \
            CP_ASYNC16(sd + OFF_BHI + dsto[j], srcBh[j] + kt);                \
            CP_ASYNC16(sd + OFF_BLO + dsto[j], srcBl[j] + kt);                \
        }                                                                     \
        CP_COMMIT();                                                          \
    } while (0)

    ISSUE_TILE(0);
    ISSUE_TILE(1);

    // Single barrier per iteration: the sync at iter `it` (after CP_WAIT)
    // proves every warp finished computing iter it-1, so issuing into stage
    // (it+2)%3 == (it-1)%3 immediately after it is safe.
    #pragma unroll 1
    for (int it = 0; it < NIT; ++it) {
        if (it < NIT - 1) { CP_WAIT(1); } else { CP_WAIT(0); }
        __syncthreads();
        if (it + 2 < NIT) ISSUE_TILE(it + 2);

        const uint32_t s = sbase + (uint32_t)(it % NSTAGE) * STAGE;
        #pragma unroll
        for (int ks = 0; ks < 2; ++ks) {
            uint32_t ahi[4][4], alo[4][4];
            uint32_t bhi[4][4], blo[4][4];
            #pragma unroll
            for (int mf = 0; mf < 4; mf++) {
                uint32_t c = (((uint32_t)(ks * 2) + aHi) ^ aXor[mf]) << 4;
                LDSM4(ahi[mf], s + OFF_AHI + aOff[mf] + c);
            }
            #pragma unroll
            for (int g = 0; g < 4; g++) {
                uint32_t c = (((uint32_t)(ks * 2) + bk) ^ bXor[g]) << 4;
                LDSM4(bhi[g], s + OFF_BHI + bOff[g] + c);
            }
            #pragma unroll
            for (int mf = 0; mf < 4; mf++)
                #pragma unroll
                for (int nf = 0; nf < 8; nf++) {
                    const int g = nf >> 1, p = (nf & 1) * 2;
                    MMA16816(acc[mf][nf], ahi[mf], bhi[g][p], bhi[g][p + 1]);
                }
            #pragma unroll
            for (int g = 0; g < 4; g++) {
                uint32_t c = (((uint32_t)(ks * 2) + bk) ^ bXor[g]) << 4;
                LDSM4(blo[g], s + OFF_BLO + bOff[g] + c);
            }
            #pragma unroll
            for (int mf = 0; mf < 4; mf++)
                #pragma unroll
                for (int nf = 0; nf < 8; nf++) {
                    const int g = nf >> 1, p = (nf & 1) * 2;
                    MMA16816(acc[mf][nf], ahi[mf], blo[g][p], blo[g][p + 1]);
                }
            #pragma unroll
            for (int mf = 0; mf < 4; mf++) {
                uint32_t c = (((uint32_t)(ks * 2) + aHi) ^ aXor[mf]) << 4;
                LDSM4(alo[mf], s + OFF_ALO + aOff[mf] + c);
            }
            #pragma unroll
            for (int mf = 0; mf < 4; mf++)
                #pragma unroll
                for (int nf = 0; nf < 8; nf++) {
                    const int g = nf >> 1, p = (nf & 1) * 2;
                    MMA16816(acc[mf][nf], alo[mf], bhi[g][p], bhi[g][p + 1]);
                }
        }
    }
    #undef ISSUE_TILE

    // Epilogue
    const int grp = lane >> 2;
    const int thr = lane & 3;
    #pragma unroll
    for (int mf = 0; mf < 4; mf++) {
        const int mrow = m0 + wm * 64 + mf * 16 + grp;
        #pragma unroll
        for (int nf = 0; nf < 8; nf++) {
            const int col = n0 + wn * 64 + nf * 8 + thr * 2;
            float2 v0 = make_float2(acc[mf][nf][0], acc[mf][nf][1]);
            float2 v1 = make_float2(acc[mf][nf][2], acc[mf][nf][3]);
            if (MODE == 1) {
                const float2 bv = *(const float2*)(bias + col);
                v0.x += bv.x; v0.y += bv.y;
                v1.x += bv.x; v1.y += bv.y;
            }
            *(float2*)(C + (size_t)mrow * Ncols + col)       = v0;
            *(float2*)(C + (size_t)(mrow + 8) * Ncols + col) = v1;
        }
    }
}

// ---------------------------------------------------------------------------
// Per-patch attention, register-tiled phases to halve SMEM traffic.
//   dots: 2x2 tile per thread (100 threads) — q/k float4 loads reused 2x.
//   AV:   2 s-rows per thread (160 threads) — v float4 loads reused 2x.
// ---------------------------------------------------------------------------
#define RSTR 68
__global__ void __launch_bounds__(256) attn_kernel()
{
    const int r   = blockIdx.x;
    const int h   = blockIdx.y;
    const int b   = blockIdx.z;
    const int blk = r >> 1, par = r & 1;

    __shared__ float q[SP * RSTR];
    __shared__ float k[SP * RSTR];
    __shared__ float v[SP * RSTR];
    __shared__ float dots[SP][SP + 1];

    const int tid = threadIdx.x;
    const size_t base = (size_t)b * NPADR * K3;

    // Load q/k/v tiles (20 tokens x 16 float4 each)
    for (int i = tid; i < SP * 16; i += 256) {
        int s = i >> 4, j = i & 15;
        int n = blk * 40 + par + 2 * s;
        const float* rp = g_qkv + base + (size_t)n * K3 + h * HDIM;
        *(float4*)(q + s * RSTR + 4 * j) = ((const float4*)(rp))[j];
        *(float4*)(k + s * RSTR + 4 * j) = ((const float4*)(rp + DIMC))[j];
        *(float4*)(v + s * RSTR + 4 * j) = ((const float4*)(rp + 2 * DIMC))[j];
    }
    __syncthreads();

    // dots: 2x2 register tile per thread (100 threads)
    const float scale = 0.125f;  // 64^-0.5
    if (tid < 100) {
        const int s0 = (tid / 10) * 2;
        const int t0 = (tid % 10) * 2;
        const float4* q0 = (const float4*)(q + s0 * RSTR);
        const float4* q1 = (const float4*)(q + (s0 + 1) * RSTR);
        const float4* k0 = (const float4*)(k + t0 * RSTR);
        const float4* k1 = (const float4*)(k + (t0 + 1) * RSTR);
        float d00 = 0.f, d01 = 0.f, d10 = 0.f, d11 = 0.f;
        #pragma unroll
        for (int e4 = 0; e4 < 16; e4++) {
            float4 a0 = q0[e4], a1 = q1[e4];
            float4 c0 = k0[e4], c1 = k1[e4];
            d00 = fmaf(a0.x, c0.x, d00); d00 = fmaf(a0.y, c0.y, d00);
            d00 = fmaf(a0.z, c0.z, d00); d00 = fmaf(a0.w, c0.w, d00);
            d01 = fmaf(a0.x, c1.x, d01); d01 = fmaf(a0.y, c1.y, d01);
            d01 = fmaf(a0.z, c1.z, d01); d01 = fmaf(a0.w, c1.w, d01);
            d10 = fmaf(a1.x, c0.x, d10); d10 = fmaf(a1.y, c0.y, d10);
            d10 = fmaf(a1.z, c0.z, d10); d10 = fmaf(a1.w, c0.w, d10);
            d11 = fmaf(a1.x, c1.x, d11); d11 = fmaf(a1.y, c1.y, d11);
            d11 = fmaf(a1.z, c1.z, d11); d11 = fmaf(a1.w, c1.w, d11);
        }
        dots[s0][t0]         = d00 * scale;
        dots[s0][t0 + 1]     = d01 * scale;
        dots[s0 + 1][t0]     = d10 * scale;
        dots[s0 + 1][t0 + 1] = d11 * scale;
    }
    __syncthreads();

    // Row softmax (threads 0..19)
    if (tid < SP) {
        float mx = -1e30f;
        #pragma unroll
        for (int t = 0; t < SP; t++) mx = fmaxf(mx, dots[tid][t]);
        float ex[SP]; float sum = 0.f;
        #pragma unroll
        for (int t = 0; t < SP; t++) { float e = expf(dots[tid][t] - mx); ex[t] = e; sum += e; }
        float inv = 1.f / sum;
        #pragma unroll
        for (int t = 0; t < SP; t++) dots[tid][t] = ex[t] * inv;
    }
    __syncthreads();

    // AV: 2 s-rows per thread (160 threads), v loads reused
    if (tid < 160) {
        const int s0 = (tid >> 4) * 2;
        const int e4 = tid & 15;
        float4 sum0 = make_float4(0.f, 0.f, 0.f, 0.f);
        float4 sum1 = make_float4(0.f, 0.f, 0.f, 0.f);
        #pragma unroll
        for (int t = 0; t < SP; t++) {
            float w0 = dots[s0][t];
            float w1 = dots[s0 + 1][t];
            float4 vv = *(const float4*)(v + t * RSTR + 4 * e4);
            sum0.x = fmaf(w0, vv.x, sum0.x); sum0.y = fmaf(w0, vv.y, sum0.y);
            sum0.z = fmaf(w0, vv.z, sum0.z); sum0.w = fmaf(w0, vv.w, sum0.w);
            sum1.x = fmaf(w1, vv.x, sum1.x); sum1.y = fmaf(w1, vv.y, sum1.y);
            sum1.z = fmaf(w1, vv.z, sum1.z); sum1.w = fmaf(w1, vv.w, sum1.w);
        }
        const int n0 = blk * 40 + par + 2 * s0;
        const int n1 = n0 + 2;
        if (n0 < NTOK) {
            uint2 hh, ll;
            split4(sum0, hh, ll);
            size_t idx = ((size_t)b * NTOK + n0) * DIMC + h * HDIM + e4 * 4;
            *(uint2*)(g_att_hi + idx) = hh;
            *(uint2*)(g_att_lo + idx) = ll;
        }
        if (n1 < NTOK) {
            uint2 hh, ll;
            split4(sum1, hh, ll);
            size_t idx = ((size_t)b * NTOK + n1) * DIMC + h * HDIM + e4 * 4;
            *(uint2*)(g_att_hi + idx) = hh;
            *(uint2*)(g_att_lo + idx) = ll;
        }
    }
}

// ---------------------------------------------------------------------------
extern "C" void kernel_launch(void* const* d_in, const int* in_sizes, int n_in,
                              void* d_out, int out_size)
{
    const float* x    = (const float*)d_in[0];  // (8, 4096, 1024)
    const float* Wqkv = (const float*)d_in[1];  // (3072, 1024)
    const float* Wout = (const float*)d_in[2];  // (1024, 1024)
    const float* bout = (const float*)d_in[3];  // (1024,)
    float* out = (float*)d_out;                 // (8, 4096, 1024)

    static bool attr_done = false;
    if (!attr_done) {
        cudaFuncSetAttribute(gemm_mma<0>, cudaFuncAttributeMaxDynamicSharedMemorySize, SMEM_TOTAL);
        cudaFuncSetAttribute(gemm_mma<1>, cudaFuncAttributeMaxDynamicSharedMemorySize, SMEM_TOTAL);
        attr_done = true;
    }

    // 0) Split inputs/weights into bf16 hi/lo
    conv_x<<<MROWS0 * DIMC / 1024, 256>>>(x);
    conv_w<<<(K3 * DIMC + DIMC * DIMC) / 1024, 256>>>(Wqkv, Wout);

    // 1) QKV projection: M=33792, N=3072
    gemm_mma<0><<<dim3(K3 / 128, MROWS0 / 128), 128, SMEM_TOTAL>>>(nullptr, nullptr, K3);

    // 2) Patch attention
    attn_kernel<<<dim3(RR, NHEADS, BATCH), 256>>>();

    // 3) Output projection + bias: M=32768, N=1024
    gemm_mma<1><<<dim3(DIMC / 128, MROWS1 / 128), 128, SMEM_TOTAL>>>(bout, out, DIMC);
}

// round 8
// speedup vs baseline: 3.2673x; 1.0223x over previous
#include <cuda_runtime.h>
#include <cuda_bf16.h>
#include <cstdint>
#include <cstddef>

// ---------------------------------------------------------------------------
// Problem constants
// ---------------------------------------------------------------------------
#define DIMC   1024
#define NHEADS 16
#define HDIM   64
#define NTOK   4096
#define BATCH  8
#define RR     206       // 103 blocks * 2 parities
#define SP     20        // tokens per patch
#define K3     3072      // 3*DIM

#define MROWS  (BATCH*NTOK)    // 32768 (both GEMMs, compact)

// ---------------------------------------------------------------------------
// Device scratch
// ---------------------------------------------------------------------------
__device__ __align__(16) float          g_qkv[(size_t)MROWS * K3];
__device__ __align__(16) __nv_bfloat16  g_x_hi[(size_t)MROWS * DIMC];
__device__ __align__(16) __nv_bfloat16  g_x_lo[(size_t)MROWS * DIMC];
__device__ __align__(16) __nv_bfloat16  g_att_hi[(size_t)MROWS * DIMC];
__device__ __align__(16) __nv_bfloat16  g_att_lo[(size_t)MROWS * DIMC];
__device__ __align__(16) __nv_bfloat16  g_wq_hi[(size_t)K3 * DIMC];
__device__ __align__(16) __nv_bfloat16  g_wq_lo[(size_t)K3 * DIMC];
__device__ __align__(16) __nv_bfloat16  g_wo_hi[(size_t)DIMC * DIMC];
__device__ __align__(16) __nv_bfloat16  g_wo_lo[(size_t)DIMC * DIMC];

// ---------------------------------------------------------------------------
// Helpers
// ---------------------------------------------------------------------------
__device__ __forceinline__ uint32_t smem_to_u32(const void* p) {
    uint32_t a;
    asm("{ .reg .u64 t; cvta.to.shared.u64 t, %1; cvt.u32.u64 %0, t; }"
        : "=r"(a) : "l"(p));
    return a;
}

__device__ __forceinline__ uint32_t pack_bf(__nv_bfloat16 a, __nv_bfloat16 b) {
    return (uint32_t)__bfloat16_as_ushort(a) | ((uint32_t)__bfloat16_as_ushort(b) << 16);
}

__device__ __forceinline__ void split4(const float4 v, uint2& hi, uint2& lo) {
    __nv_bfloat16 h0 = __float2bfloat16_rn(v.x), h1 = __float2bfloat16_rn(v.y);
    __nv_bfloat16 h2 = __float2bfloat16_rn(v.z), h3 = __float2bfloat16_rn(v.w);
    __nv_bfloat16 l0 = __float2bfloat16_rn(v.x - __bfloat162float(h0));
    __nv_bfloat16 l1 = __float2bfloat16_rn(v.y - __bfloat162float(h1));
    __nv_bfloat16 l2 = __float2bfloat16_rn(v.z - __bfloat162float(h2));
    __nv_bfloat16 l3 = __float2bfloat16_rn(v.w - __bfloat162float(h3));
    hi.x = pack_bf(h0, h1); hi.y = pack_bf(h2, h3);
    lo.x = pack_bf(l0, l1); lo.y = pack_bf(l2, l3);
}

#define LDSM4(r, addr) \
    asm volatile("ldmatrix.sync.aligned.m8n8.x4.shared.b16 {%0,%1,%2,%3}, [%4];" \
        : "=r"((r)[0]), "=r"((r)[1]), "=r"((r)[2]), "=r"((r)[3]) : "r"(addr))

#define MMA16816(d, a, b0, b1) \
    asm volatile("mma.sync.aligned.m16n8k16.row.col.f32.bf16.bf16.f32 " \
        "{%0,%1,%2,%3}, {%4,%5,%6,%7}, {%8,%9}, {%0,%1,%2,%3};" \
        : "+f"((d)[0]), "+f"((d)[1]), "+f"((d)[2]), "+f"((d)[3]) \
        : "r"((a)[0]), "r"((a)[1]), "r"((a)[2]), "r"((a)[3]), "r"(b0), "r"(b1))

#define CP_ASYNC16(dst, src) \
    asm volatile("cp.async.cg.shared.global [%0], [%1], 16;" :: "r"(dst), "l"(src))
#define CP_COMMIT() asm volatile("cp.async.commit_group;" ::: "memory")
#define CP_WAIT(n)  asm volatile("cp.async.wait_group %0;" :: "n"(n) : "memory")

// ---------------------------------------------------------------------------
// Single merged conversion prepass: fp32 -> split bf16 for x, Wqkv, Wout.
// ---------------------------------------------------------------------------
#define NF4_X  ((size_t)MROWS * DIMC / 4)          // 8388608
#define NF4_WQ ((size_t)K3 * DIMC / 4)             // 786432
#define NF4_WO ((size_t)DIMC * DIMC / 4)           // 262144
#define CONV_BLOCKS ((NF4_X + NF4_WQ + NF4_WO) / 256)

__global__ void __launch_bounds__(256) conv_all(const float* __restrict__ x,
                                                const float* __restrict__ wq,
                                                const float* __restrict__ wo) {
    size_t i = (size_t)blockIdx.x * 256 + threadIdx.x;   // one float4
    uint2 h, l;
    if (i < NF4_X) {
        size_t e = i * 4;
        float4 v = *(const float4*)(x + e);
        split4(v, h, l);
        *(uint2*)(g_x_hi + e) = h;
        *(uint2*)(g_x_lo + e) = l;
    } else if (i < NF4_X + NF4_WQ) {
        size_t e = (i - NF4_X) * 4;
        float4 v = *(const float4*)(wq + e);
        split4(v, h, l);
        *(uint2*)(g_wq_hi + e) = h;
        *(uint2*)(g_wq_lo + e) = l;
    } else {
        size_t e = (i - NF4_X - NF4_WQ) * 4;
        float4 v = *(const float4*)(wo + e);
        split4(v, h, l);
        *(uint2*)(g_wo_hi + e) = h;
        *(uint2*)(g_wo_lo + e) = l;
    }
}

// ---------------------------------------------------------------------------
// Split-bf16 mma.sync GEMM, CTA 128x128, 4 warps (warp tile 64x64), BK=32,
// 3-stage cp.async pipeline, single barrier per k-iter. 2 CTAs/SM.
// ---------------------------------------------------------------------------
#define BK      32
#define NSTAGE  3
#define STAGE   32768
#define OFF_AHI 0
#define OFF_ALO 8192
#define OFF_BHI 16384
#define OFF_BLO 24576
#define SMEM_TOTAL (NSTAGE*STAGE)   // 98304

template<int MODE>
__global__ void __launch_bounds__(128, 2)
gemm_mma(const float* __restrict__ bias, float* __restrict__ Cout, int Ncols)
{
    extern __shared__ char smem[];
    const uint32_t sbase = smem_to_u32(smem);
    const int tid  = threadIdx.x;
    const int lane = tid & 31;
    const int wid  = tid >> 5;   // 0..3
    const int wm   = wid >> 1;   // 0..1
    const int wn   = wid & 1;    // 0..1
    const int m0   = blockIdx.y * 128;
    const int n0   = blockIdx.x * 128;

    const __nv_bfloat16* gAhi = (MODE == 0) ? g_x_hi : g_att_hi;
    const __nv_bfloat16* gAlo = (MODE == 0) ? g_x_lo : g_att_lo;
    const __nv_bfloat16* gBhi = (MODE == 0) ? g_wq_hi : g_wo_hi;
    const __nv_bfloat16* gBlo = (MODE == 0) ? g_wq_lo : g_wo_lo;
    float* C = (MODE == 0) ? g_qkv : Cout;

    uint32_t dsto[4];
    const __nv_bfloat16 *srcAh[4], *srcAl[4], *srcBh[4], *srcBl[4];
    #pragma unroll
    for (int j = 0; j < 4; j++) {
        int c = tid + j * 128;
        int row = c >> 2, col = c & 3;
        dsto[j] = (uint32_t)(row * 64 + (((uint32_t)col ^ (((uint32_t)row >> 1) & 3)) << 4));
        size_t aoff = (size_t)(m0 + row) * DIMC + col * 8;
        size_t boff = (size_t)(n0 + row) * DIMC + col * 8;
        srcAh[j] = gAhi + aoff; srcAl[j] = gAlo + aoff;
        srcBh[j] = gBhi + boff; srcBl[j] = gBlo + boff;
    }

    uint32_t aOff[4], aXor[4];
    #pragma unroll
    for (int mf = 0; mf < 4; mf++) {
        int row = wm * 64 + mf * 16 + (lane & 15);
        aOff[mf] = (uint32_t)row * 64;
        aXor[mf] = ((uint32_t)row >> 1) & 3;
    }
    const uint32_t aHi = (uint32_t)(lane >> 4);
    uint32_t bOff[4], bXor[4];
    #pragma unroll
    for (int g = 0; g < 4; g++) {
        int row = wn * 64 + (lane & 7) + ((lane >> 4) << 3) + g * 16;
        bOff[g] = (uint32_t)row * 64;
        bXor[g] = ((uint32_t)row >> 1) & 3;
    }
    const uint32_t bk = (uint32_t)((lane >> 3) & 1);

    float acc[4][8][4];
    #pragma unroll
    for (int i = 0; i < 4; i++)
        #pragma unroll
        for (int j = 0; j < 8; j++)
            #pragma unroll
            for (int q = 0; q < 4; q++) acc[i][j][q] = 0.f;

    const int NIT = DIMC / BK;   // 32

    #define ISSUE_TILE(tile) do {                                             \
        const uint32_t sd = sbase + (uint32_t)((tile) % NSTAGE) * STAGE;      \
        const int kt = (tile) * BK;                                           \
        _Pragma("unroll")                                                     \
        for (int j = 0; j < 4; j++) {                                         \
            CP_ASYNC16(sd + OFF_AHI + dsto[j], srcAh[j] + kt);                \
            CP_ASYNC16(sd + OFF_ALO + dsto[j], srcAl[j] + kt);                \
            CP_ASYNC16(sd + OFF_BHI + dsto[j], srcBh[j] + kt);                \
            CP_ASYNC16(sd + OFF_BLO + dsto[j], srcBl[j] + kt);                \
        }                                                                     \
        CP_COMMIT();                                                          \
    } while (0)

    ISSUE_TILE(0);
    ISSUE_TILE(1);

    #pragma unroll 1
    for (int it = 0; it < NIT; ++it) {
        if (it < NIT - 1) { CP_WAIT(1); } else { CP_WAIT(0); }
        __syncthreads();
        if (it + 2 < NIT) ISSUE_TILE(it + 2);

        const uint32_t s = sbase + (uint32_t)(it % NSTAGE) * STAGE;
        #pragma unroll
        for (int ks = 0; ks < 2; ++ks) {
            uint32_t ahi[4][4], alo[4][4];
            uint32_t bhi[4][4], blo[4][4];
            #pragma unroll
            for (int mf = 0; mf < 4; mf++) {
                uint32_t c = (((uint32_t)(ks * 2) + aHi) ^ aXor[mf]) << 4;
                LDSM4(ahi[mf], s + OFF_AHI + aOff[mf] + c);
            }
            #pragma unroll
            for (int g = 0; g < 4; g++) {
                uint32_t c = (((uint32_t)(ks * 2) + bk) ^ bXor[g]) << 4;
                LDSM4(bhi[g], s + OFF_BHI + bOff[g] + c);
            }
            #pragma unroll
            for (int mf = 0; mf < 4; mf++)
                #pragma unroll
                for (int nf = 0; nf < 8; nf++) {
                    const int g = nf >> 1, p = (nf & 1) * 2;
                    MMA16816(acc[mf][nf], ahi[mf], bhi[g][p], bhi[g][p + 1]);
                }
            #pragma unroll
            for (int g = 0; g < 4; g++) {
                uint32_t c = (((uint32_t)(ks * 2) + bk) ^ bXor[g]) << 4;
                LDSM4(blo[g], s + OFF_BLO + bOff[g] + c);
            }
            #pragma unroll
            for (int mf = 0; mf < 4; mf++)
                #pragma unroll
                for (int nf = 0; nf < 8; nf++) {
                    const int g = nf >> 1, p = (nf & 1) * 2;
                    MMA16816(acc[mf][nf], ahi[mf], blo[g][p], blo[g][p + 1]);
                }
            #pragma unroll
            for (int mf = 0; mf < 4; mf++) {
                uint32_t c = (((uint32_t)(ks * 2) + aHi) ^ aXor[mf]) << 4;
                LDSM4(alo[mf], s + OFF_ALO + aOff[mf] + c);
            }
            #pragma unroll
            for (int mf = 0; mf < 4; mf++)
                #pragma unroll
                for (int nf = 0; nf < 8; nf++) {
                    const int g = nf >> 1, p = (nf & 1) * 2;
                    MMA16816(acc[mf][nf], alo[mf], bhi[g][p], bhi[g][p + 1]);
                }
        }
    }
    #undef ISSUE_TILE

    // Epilogue
    const int grp = lane >> 2;
    const int thr = lane & 3;
    #pragma unroll
    for (int mf = 0; mf < 4; mf++) {
        const int mrow = m0 + wm * 64 + mf * 16 + grp;
        #pragma unroll
        for (int nf = 0; nf < 8; nf++) {
            const int col = n0 + wn * 64 + nf * 8 + thr * 2;
            float2 v0 = make_float2(acc[mf][nf][0], acc[mf][nf][1]);
            float2 v1 = make_float2(acc[mf][nf][2], acc[mf][nf][3]);
            if (MODE == 1) {
                const float2 bv = *(const float2*)(bias + col);
                v0.x += bv.x; v0.y += bv.y;
                v1.x += bv.x; v1.y += bv.y;
            }
            *(float2*)(C + (size_t)mrow * Ncols + col)       = v0;
            *(float2*)(C + (size_t)(mrow + 8) * Ncols + col) = v1;
        }
    }
}

// ---------------------------------------------------------------------------
// Per-patch attention. g_qkv is COMPACT (32768 rows); pad tokens (n>=4096)
// are zero-filled in smem (their qkv is exactly 0: x pad rows are 0, no bias).
//   dots: 2x2 tile with row pairing {a, a+10} x {b, b+10} (bank-friendlier)
//   AV:   4 s-rows per thread (80 threads) — v loads reused 4x
// ---------------------------------------------------------------------------
#define RSTR 68
__global__ void __launch_bounds__(256) attn_kernel()
{
    const int r   = blockIdx.x;
    const int h   = blockIdx.y;
    const int b   = blockIdx.z;
    const int blk = r >> 1, par = r & 1;

    __shared__ float q[SP * RSTR];
    __shared__ float k[SP * RSTR];
    __shared__ float v[SP * RSTR];
    __shared__ float dots[SP][SP + 1];

    const int tid = threadIdx.x;
    const size_t base = (size_t)b * NTOK * K3;

    // Load q/k/v tiles (20 tokens x 16 float4 each); zero-fill pad tokens
    for (int i = tid; i < SP * 16; i += 256) {
        int s = i >> 4, j = i & 15;
        int n = blk * 40 + par + 2 * s;
        float4 qv, kv, vv;
        if (n < NTOK) {
            const float* rp = g_qkv + base + (size_t)n * K3 + h * HDIM;
            qv = ((const float4*)(rp))[j];
            kv = ((const float4*)(rp + DIMC))[j];
            vv = ((const float4*)(rp + 2 * DIMC))[j];
        } else {
            qv = kv = vv = make_float4(0.f, 0.f, 0.f, 0.f);
        }
        *(float4*)(q + s * RSTR + 4 * j) = qv;
        *(float4*)(k + s * RSTR + 4 * j) = kv;
        *(float4*)(v + s * RSTR + 4 * j) = vv;
    }
    __syncthreads();

    // dots: 2x2 register tile per thread, rows {a, a+10}, cols {b, b+10}
    const float scale = 0.125f;  // 64^-0.5
    if (tid < 100) {
        const int a  = tid / 10;
        const int bq = tid % 10;
        const float4* q0 = (const float4*)(q + a * RSTR);
        const float4* q1 = (const float4*)(q + (a + 10) * RSTR);
        const float4* k0 = (const float4*)(k + bq * RSTR);
        const float4* k1 = (const float4*)(k + (bq + 10) * RSTR);
        float d00 = 0.f, d01 = 0.f, d10 = 0.f, d11 = 0.f;
        #pragma unroll
        for (int e4 = 0; e4 < 16; e4++) {
            float4 a0 = q0[e4], a1 = q1[e4];
            float4 c0 = k0[e4], c1 = k1[e4];
            d00 = fmaf(a0.x, c0.x, d00); d00 = fmaf(a0.y, c0.y, d00);
            d00 = fmaf(a0.z, c0.z, d00); d00 = fmaf(a0.w, c0.w, d00);
            d01 = fmaf(a0.x, c1.x, d01); d01 = fmaf(a0.y, c1.y, d01);
            d01 = fmaf(a0.z, c1.z, d01); d01 = fmaf(a0.w, c1.w, d01);
            d10 = fmaf(a1.x, c0.x, d10); d10 = fmaf(a1.y, c0.y, d10);
            d10 = fmaf(a1.z, c0.z, d10); d10 = fmaf(a1.w, c0.w, d10);
            d11 = fmaf(a1.x, c1.x, d11); d11 = fmaf(a1.y, c1.y, d11);
            d11 = fmaf(a1.z, c1.z, d11); d11 = fmaf(a1.w, c1.w, d11);
        }
        dots[a][bq]            = d00 * scale;
        dots[a][bq + 10]       = d01 * scale;
        dots[a + 10][bq]       = d10 * scale;
        dots[a + 10][bq + 10]  = d11 * scale;
    }
    __syncthreads();

    // Row softmax (threads 0..19)
    if (tid < SP) {
        float mx = -1e30f;
        #pragma unroll
        for (int t = 0; t < SP; t++) mx = fmaxf(mx, dots[tid][t]);
        float ex[SP]; float sum = 0.f;
        #pragma unroll
        for (int t = 0; t < SP; t++) { float e = expf(dots[tid][t] - mx); ex[t] = e; sum += e; }
        float inv = 1.f / sum;
        #pragma unroll
        for (int t = 0; t < SP; t++) dots[tid][t] = ex[t] * inv;
    }
    __syncthreads();

    // AV: 4 s-rows per thread (80 threads), v loads reused 4x
    if (tid < 80) {
        const int sg = tid >> 4;     // 0..4
        const int e4 = tid & 15;
        const int s0 = sg, s1 = sg + 5, s2 = sg + 10, s3 = sg + 15;
        float4 a0 = make_float4(0.f, 0.f, 0.f, 0.f);
        float4 a1 = a0, a2 = a0, a3 = a0;
        #pragma unroll
        for (int t = 0; t < SP; t++) {
            float w0 = dots[s0][t], w1 = dots[s1][t];
            float w2 = dots[s2][t], w3 = dots[s3][t];
            float4 vv = *(const float4*)(v + t * RSTR + 4 * e4);
            a0.x = fmaf(w0, vv.x, a0.x); a0.y = fmaf(w0, vv.y, a0.y);
            a0.z = fmaf(w0, vv.z, a0.z); a0.w = fmaf(w0, vv.w, a0.w);
            a1.x = fmaf(w1, vv.x, a1.x); a1.y = fmaf(w1, vv.y, a1.y);
            a1.z = fmaf(w1, vv.z, a1.z); a1.w = fmaf(w1, vv.w, a1.w);
            a2.x = fmaf(w2, vv.x, a2.x); a2.y = fmaf(w2, vv.y, a2.y);
            a2.z = fmaf(w2, vv.z, a2.z); a2.w = fmaf(w2, vv.w, a2.w);
            a3.x = fmaf(w3, vv.x, a3.x); a3.y = fmaf(w3, vv.y, a3.y);
            a3.z = fmaf(w3, vv.z, a3.z); a3.w = fmaf(w3, vv.w, a3.w);
        }
        const int ss[4] = { s0, s1, s2, s3 };
        float4 res[4] = { a0, a1, a2, a3 };
        #pragma unroll
        for (int j = 0; j < 4; j++) {
            int n = blk * 40 + par + 2 * ss[j];
            if (n < NTOK) {
                uint2 hh, ll;
                split4(res[j], hh, ll);
                size_t idx = ((size_t)b * NTOK + n) * DIMC + h * HDIM + e4 * 4;
                *(uint2*)(g_att_hi + idx) = hh;
                *(uint2*)(g_att_lo + idx) = ll;
            }
        }
    }
}

// ---------------------------------------------------------------------------
extern "C" void kernel_launch(void* const* d_in, const int* in_sizes, int n_in,
                              void* d_out, int out_size)
{
    const float* x    = (const float*)d_in[0];  // (8, 4096, 1024)
    const float* Wqkv = (const float*)d_in[1];  // (3072, 1024)
    const float* Wout = (const float*)d_in[2];  // (1024, 1024)
    const float* bout = (const float*)d_in[3];  // (1024,)
    float* out = (float*)d_out;                 // (8, 4096, 1024)

    static bool attr_done = false;
    if (!attr_done) {
        cudaFuncSetAttribute(gemm_mma<0>, cudaFuncAttributeMaxDynamicSharedMemorySize, SMEM_TOTAL);
        cudaFuncSetAttribute(gemm_mma<1>, cudaFuncAttributeMaxDynamicSharedMemorySize, SMEM_TOTAL);
        attr_done = true;
    }

    // 0) Split inputs/weights into bf16 hi/lo (single merged launch)
    conv_all<<<(unsigned)CONV_BLOCKS, 256>>>(x, Wqkv, Wout);

    // 1) QKV projection: M=32768 (compact), N=3072
    gemm_mma<0><<<dim3(K3 / 128, MROWS / 128), 128, SMEM_TOTAL>>>(nullptr, nullptr, K3);

    // 2) Patch attention (pad tokens synthesized as zeros)
    attn_kernel<<<dim3(RR, NHEADS, BATCH), 256>>>();

    // 3) Output projection + bias: M=32768, N=1024
    gemm_mma<1><<<dim3(DIMC / 128, MROWS / 128), 128, SMEM_TOTAL>>>(bout, out, DIMC);
}

// round 9
// speedup vs baseline: 3.4597x; 1.0589x over previous
#include <cuda_runtime.h>
#include <cuda_bf16.h>
#include <cstdint>
#include <cstddef>

// ---------------------------------------------------------------------------
// Problem constants
// ---------------------------------------------------------------------------
#define DIMC   1024
#define NHEADS 16
#define HDIM   64
#define NTOK   4096
#define BATCH  8
#define RR     206       // 103 blocks * 2 parities
#define SP     20        // tokens per patch
#define K3     3072      // 3*DIM

#define MROWS  (BATCH*NTOK)    // 32768 (both GEMMs, compact)

// ---------------------------------------------------------------------------
// Device scratch
// ---------------------------------------------------------------------------
__device__ __align__(16) float          g_qkv[(size_t)MROWS * K3];
__device__ __align__(16) __nv_bfloat16  g_x_hi[(size_t)MROWS * DIMC];
__device__ __align__(16) __nv_bfloat16  g_x_lo[(size_t)MROWS * DIMC];
__device__ __align__(16) __nv_bfloat16  g_att_hi[(size_t)MROWS * DIMC];
__device__ __align__(16) __nv_bfloat16  g_att_lo[(size_t)MROWS * DIMC];
__device__ __align__(16) __nv_bfloat16  g_wq_hi[(size_t)K3 * DIMC];
__device__ __align__(16) __nv_bfloat16  g_wq_lo[(size_t)K3 * DIMC];
__device__ __align__(16) __nv_bfloat16  g_wo_hi[(size_t)DIMC * DIMC];
__device__ __align__(16) __nv_bfloat16  g_wo_lo[(size_t)DIMC * DIMC];

// ---------------------------------------------------------------------------
// Helpers
// ---------------------------------------------------------------------------
__device__ __forceinline__ uint32_t smem_to_u32(const void* p) {
    uint32_t a;
    asm("{ .reg .u64 t; cvta.to.shared.u64 t, %1; cvt.u32.u64 %0, t; }"
        : "=r"(a) : "l"(p));
    return a;
}

__device__ __forceinline__ uint32_t pack_bf(__nv_bfloat16 a, __nv_bfloat16 b) {
    return (uint32_t)__bfloat16_as_ushort(a) | ((uint32_t)__bfloat16_as_ushort(b) << 16);
}

__device__ __forceinline__ void split4(const float4 v, uint2& hi, uint2& lo) {
    __nv_bfloat16 h0 = __float2bfloat16_rn(v.x), h1 = __float2bfloat16_rn(v.y);
    __nv_bfloat16 h2 = __float2bfloat16_rn(v.z), h3 = __float2bfloat16_rn(v.w);
    __nv_bfloat16 l0 = __float2bfloat16_rn(v.x - __bfloat162float(h0));
    __nv_bfloat16 l1 = __float2bfloat16_rn(v.y - __bfloat162float(h1));
    __nv_bfloat16 l2 = __float2bfloat16_rn(v.z - __bfloat162float(h2));
    __nv_bfloat16 l3 = __float2bfloat16_rn(v.w - __bfloat162float(h3));
    hi.x = pack_bf(h0, h1); hi.y = pack_bf(h2, h3);
    lo.x = pack_bf(l0, l1); lo.y = pack_bf(l2, l3);
}

#define LDSM4(r, addr) \
    asm volatile("ldmatrix.sync.aligned.m8n8.x4.shared.b16 {%0,%1,%2,%3}, [%4];" \
        : "=r"((r)[0]), "=r"((r)[1]), "=r"((r)[2]), "=r"((r)[3]) : "r"(addr))

#define MMA16816(d, a, b0, b1) \
    asm volatile("mma.sync.aligned.m16n8k16.row.col.f32.bf16.bf16.f32 " \
        "{%0,%1,%2,%3}, {%4,%5,%6,%7}, {%8,%9}, {%0,%1,%2,%3};" \
        : "+f"((d)[0]), "+f"((d)[1]), "+f"((d)[2]), "+f"((d)[3]) \
        : "r"((a)[0]), "r"((a)[1]), "r"((a)[2]), "r"((a)[3]), "r"(b0), "r"(b1))

#define CP_ASYNC16(dst, src) \
    asm volatile("cp.async.cg.shared.global [%0], [%1], 16;" :: "r"(dst), "l"(src))
#define CP_COMMIT() asm volatile("cp.async.commit_group;" ::: "memory")
#define CP_WAIT(n)  asm volatile("cp.async.wait_group %0;" :: "n"(n) : "memory")

// ---------------------------------------------------------------------------
// Single merged conversion prepass: fp32 -> split bf16 for x, Wqkv, Wout.
// ---------------------------------------------------------------------------
#define NF4_X  ((size_t)MROWS * DIMC / 4)          // 8388608
#define NF4_WQ ((size_t)K3 * DIMC / 4)             // 786432
#define NF4_WO ((size_t)DIMC * DIMC / 4)           // 262144
#define CONV_BLOCKS ((NF4_X + NF4_WQ + NF4_WO) / 256)

__global__ void __launch_bounds__(256) conv_all(const float* __restrict__ x,
                                                const float* __restrict__ wq,
                                                const float* __restrict__ wo) {
    size_t i = (size_t)blockIdx.x * 256 + threadIdx.x;   // one float4
    uint2 h, l;
    if (i < NF4_X) {
        size_t e = i * 4;
        float4 v = *(const float4*)(x + e);
        split4(v, h, l);
        *(uint2*)(g_x_hi + e) = h;
        *(uint2*)(g_x_lo + e) = l;
    } else if (i < NF4_X + NF4_WQ) {
        size_t e = (i - NF4_X) * 4;
        float4 v = *(const float4*)(wq + e);
        split4(v, h, l);
        *(uint2*)(g_wq_hi + e) = h;
        *(uint2*)(g_wq_lo + e) = l;
    } else {
        size_t e = (i - NF4_X - NF4_WQ) * 4;
        float4 v = *(const float4*)(wo + e);
        split4(v, h, l);
        *(uint2*)(g_wo_hi + e) = h;
        *(uint2*)(g_wo_lo + e) = l;
    }
}

// ---------------------------------------------------------------------------
// Split-bf16 mma.sync GEMM, CTA 128x128, 4 warps (warp tile 64x64), BK=32,
// 3-stage cp.async pipeline, single barrier per k-iter. 2 CTAs/SM.
// Register-lean: base+offset cp.async addressing; per-g B fragment loads.
// ---------------------------------------------------------------------------
#define BK      32
#define NSTAGE  3
#define STAGE   32768
#define OFF_AHI 0
#define OFF_ALO 8192
#define OFF_BHI 16384
#define OFF_BLO 24576
#define SMEM_TOTAL (NSTAGE*STAGE)   // 98304

template<int MODE>
__global__ void __launch_bounds__(128, 2)
gemm_mma(const float* __restrict__ bias, float* __restrict__ Cout, int Ncols)
{
    extern __shared__ char smem[];
    const uint32_t sbase = smem_to_u32(smem);
    const int tid  = threadIdx.x;
    const int lane = tid & 31;
    const int wid  = tid >> 5;   // 0..3
    const int wm   = wid >> 1;   // 0..1
    const int wn   = wid & 1;    // 0..1
    const int m0   = blockIdx.y * 128;
    const int n0   = blockIdx.x * 128;

    const char* bAh = (const char*)((MODE == 0) ? g_x_hi : g_att_hi);
    const char* bAl = (const char*)((MODE == 0) ? g_x_lo : g_att_lo);
    const char* bBh = (const char*)((MODE == 0) ? g_wq_hi : g_wo_hi);
    const char* bBl = (const char*)((MODE == 0) ? g_wq_lo : g_wo_lo);
    float* C = (MODE == 0) ? g_qkv : Cout;

    // cp.async: 4 chunks of 16B per thread per region; 32-bit byte offsets
    uint32_t dsto[4], aoff[4], boff[4];
    #pragma unroll
    for (int j = 0; j < 4; j++) {
        int c = tid + j * 128;
        int row = c >> 2, col = c & 3;
        dsto[j] = (uint32_t)(row * 64 + (((uint32_t)col ^ (((uint32_t)row >> 1) & 3)) << 4));
        aoff[j] = (uint32_t)((m0 + row) * DIMC + col * 8) * 2u;
        boff[j] = (uint32_t)((n0 + row) * DIMC + col * 8) * 2u;
    }

    uint32_t aOff[4], aXor[4];
    #pragma unroll
    for (int mf = 0; mf < 4; mf++) {
        int row = wm * 64 + mf * 16 + (lane & 15);
        aOff[mf] = (uint32_t)row * 64;
        aXor[mf] = ((uint32_t)row >> 1) & 3;
    }
    const uint32_t aHi = (uint32_t)(lane >> 4);
    uint32_t bOff[4], bXor[4];
    #pragma unroll
    for (int g = 0; g < 4; g++) {
        int row = wn * 64 + (lane & 7) + ((lane >> 4) << 3) + g * 16;
        bOff[g] = (uint32_t)row * 64;
        bXor[g] = ((uint32_t)row >> 1) & 3;
    }
    const uint32_t bk = (uint32_t)((lane >> 3) & 1);

    float acc[4][8][4];
    #pragma unroll
    for (int i = 0; i < 4; i++)
        #pragma unroll
        for (int j = 0; j < 8; j++)
            #pragma unroll
            for (int q = 0; q < 4; q++) acc[i][j][q] = 0.f;

    const int NIT = DIMC / BK;   // 32

    #define ISSUE_TILE(tile) do {                                             \
        const uint32_t sd = sbase + (uint32_t)((tile) % NSTAGE) * STAGE;      \
        const uint32_t kb = (uint32_t)(tile) * (BK * 2);                      \
        _Pragma("unroll")                                                     \
        for (int j = 0; j < 4; j++) {                                         \
            CP_ASYNC16(sd + OFF_AHI + dsto[j], bAh + aoff[j] + kb);           \
            CP_ASYNC16(sd + OFF_ALO + dsto[j], bAl + aoff[j] + kb);           \
            CP_ASYNC16(sd + OFF_BHI + dsto[j], bBh + boff[j] + kb);           \
            CP_ASYNC16(sd + OFF_BLO + dsto[j], bBl + boff[j] + kb);           \
        }                                                                     \
        CP_COMMIT();                                                          \
    } while (0)

    ISSUE_TILE(0);
    ISSUE_TILE(1);

    #pragma unroll 1
    for (int it = 0; it < NIT; ++it) {
        if (it < NIT - 1) { CP_WAIT(1); } else { CP_WAIT(0); }
        __syncthreads();
        if (it + 2 < NIT) ISSUE_TILE(it + 2);

        const uint32_t s = sbase + (uint32_t)(it % NSTAGE) * STAGE;
        #pragma unroll
        for (int ks = 0; ks < 2; ++ks) {
            uint32_t ahi[4][4], alo[4][4];
            #pragma unroll
            for (int mf = 0; mf < 4; mf++) {
                uint32_t c = (((uint32_t)(ks * 2) + aHi) ^ aXor[mf]) << 4;
                LDSM4(ahi[mf], s + OFF_AHI + aOff[mf] + c);
                LDSM4(alo[mf], s + OFF_ALO + aOff[mf] + c);
            }
            // Per-g B loads: only 8 B regs live at a time.
            #pragma unroll
            for (int g = 0; g < 4; g++) {
                uint32_t bh[4], bl[4];
                uint32_t c = (((uint32_t)(ks * 2) + bk) ^ bXor[g]) << 4;
                LDSM4(bh, s + OFF_BHI + bOff[g] + c);
                LDSM4(bl, s + OFF_BLO + bOff[g] + c);
                // Same accumulation set/order per acc element as before:
                // hi*hi, then hi*lo, then lo*hi.
                #pragma unroll
                for (int mf = 0; mf < 4; mf++) {
                    MMA16816(acc[mf][2 * g],     ahi[mf], bh[0], bh[1]);
                    MMA16816(acc[mf][2 * g + 1], ahi[mf], bh[2], bh[3]);
                }
                #pragma unroll
                for (int mf = 0; mf < 4; mf++) {
                    MMA16816(acc[mf][2 * g],     ahi[mf], bl[0], bl[1]);
                    MMA16816(acc[mf][2 * g + 1], ahi[mf], bl[2], bl[3]);
                }
                #pragma unroll
                for (int mf = 0; mf < 4; mf++) {
                    MMA16816(acc[mf][2 * g],     alo[mf], bh[0], bh[1]);
                    MMA16816(acc[mf][2 * g + 1], alo[mf], bh[2], bh[3]);
                }
            }
        }
    }
    #undef ISSUE_TILE

    // Epilogue
    const int grp = lane >> 2;
    const int thr = lane & 3;
    #pragma unroll
    for (int mf = 0; mf < 4; mf++) {
        const int mrow = m0 + wm * 64 + mf * 16 + grp;
        #pragma unroll
        for (int nf = 0; nf < 8; nf++) {
            const int col = n0 + wn * 64 + nf * 8 + thr * 2;
            float2 v0 = make_float2(acc[mf][nf][0], acc[mf][nf][1]);
            float2 v1 = make_float2(acc[mf][nf][2], acc[mf][nf][3]);
            if (MODE == 1) {
                const float2 bv = *(const float2*)(bias + col);
                v0.x += bv.x; v0.y += bv.y;
                v1.x += bv.x; v1.y += bv.y;
            }
            *(float2*)(C + (size_t)mrow * Ncols + col)       = v0;
            *(float2*)(C + (size_t)(mrow + 8) * Ncols + col) = v1;
        }
    }
}

// ---------------------------------------------------------------------------
// Per-patch attention. g_qkv is COMPACT (32768 rows); pad tokens (n>=4096)
// are zero-filled in smem (their qkv is exactly 0: x pad rows are 0, no bias).
// ---------------------------------------------------------------------------
#define RSTR 68
__global__ void __launch_bounds__(256) attn_kernel()
{
    const int r   = blockIdx.x;
    const int h   = blockIdx.y;
    const int b   = blockIdx.z;
    const int blk = r >> 1, par = r & 1;

    __shared__ float q[SP * RSTR];
    __shared__ float k[SP * RSTR];
    __shared__ float v[SP * RSTR];
    __shared__ float dots[SP][SP + 1];

    const int tid = threadIdx.x;
    const size_t base = (size_t)b * NTOK * K3;

    for (int i = tid; i < SP * 16; i += 256) {
        int s = i >> 4, j = i & 15;
        int n = blk * 40 + par + 2 * s;
        float4 qv, kv, vv;
        if (n < NTOK) {
            const float* rp = g_qkv + base + (size_t)n * K3 + h * HDIM;
            qv = ((const float4*)(rp))[j];
            kv = ((const float4*)(rp + DIMC))[j];
            vv = ((const float4*)(rp + 2 * DIMC))[j];
        } else {
            qv = kv = vv = make_float4(0.f, 0.f, 0.f, 0.f);
        }
        *(float4*)(q + s * RSTR + 4 * j) = qv;
        *(float4*)(k + s * RSTR + 4 * j) = kv;
        *(float4*)(v + s * RSTR + 4 * j) = vv;
    }
    __syncthreads();

    const float scale = 0.125f;  // 64^-0.5
    if (tid < 100) {
        const int a  = tid / 10;
        const int bq = tid % 10;
        const float4* q0 = (const float4*)(q + a * RSTR);
        const float4* q1 = (const float4*)(q + (a + 10) * RSTR);
        const float4* k0 = (const float4*)(k + bq * RSTR);
        const float4* k1 = (const float4*)(k + (bq + 10) * RSTR);
        float d00 = 0.f, d01 = 0.f, d10 = 0.f, d11 = 0.f;
        #pragma unroll
        for (int e4 = 0; e4 < 16; e4++) {
            float4 a0 = q0[e4], a1 = q1[e4];
            float4 c0 = k0[e4], c1 = k1[e4];
            d00 = fmaf(a0.x, c0.x, d00); d00 = fmaf(a0.y, c0.y, d00);
            d00 = fmaf(a0.z, c0.z, d00); d00 = fmaf(a0.w, c0.w, d00);
            d01 = fmaf(a0.x, c1.x, d01); d01 = fmaf(a0.y, c1.y, d01);
            d01 = fmaf(a0.z, c1.z, d01); d01 = fmaf(a0.w, c1.w, d01);
            d10 = fmaf(a1.x, c0.x, d10); d10 = fmaf(a1.y, c0.y, d10);
            d10 = fmaf(a1.z, c0.z, d10); d10 = fmaf(a1.w, c0.w, d10);
            d11 = fmaf(a1.x, c1.x, d11); d11 = fmaf(a1.y, c1.y, d11);
            d11 = fmaf(a1.z, c1.z, d11); d11 = fmaf(a1.w, c1.w, d11);
        }
        dots[a][bq]            = d00 * scale;
        dots[a][bq + 10]       = d01 * scale;
        dots[a + 10][bq]       = d10 * scale;
        dots[a + 10][bq + 10]  = d11 * scale;
    }
    __syncthreads();

    if (tid < SP) {
        float mx = -1e30f;
        #pragma unroll
        for (int t = 0; t < SP; t++) mx = fmaxf(mx, dots[tid][t]);
        float ex[SP]; float sum = 0.f;
        #pragma unroll
        for (int t = 0; t < SP; t++) { float e = expf(dots[tid][t] - mx); ex[t] = e; sum += e; }
        float inv = 1.f / sum;
        #pragma unroll
        for (int t = 0; t < SP; t++) dots[tid][t] = ex[t] * inv;
    }
    __syncthreads();

    if (tid < 80) {
        const int sg = tid >> 4;     // 0..4
        const int e4 = tid & 15;
        const int s0 = sg, s1 = sg + 5, s2 = sg + 10, s3 = sg + 15;
        float4 a0 = make_float4(0.f, 0.f, 0.f, 0.f);
        float4 a1 = a0, a2 = a0, a3 = a0;
        #pragma unroll
        for (int t = 0; t < SP; t++) {
            float w0 = dots[s0][t], w1 = dots[s1][t];
            float w2 = dots[s2][t], w3 = dots[s3][t];
            float4 vv = *(const float4*)(v + t * RSTR + 4 * e4);
            a0.x = fmaf(w0, vv.x, a0.x); a0.y = fmaf(w0, vv.y, a0.y);
            a0.z = fmaf(w0, vv.z, a0.z); a0.w = fmaf(w0, vv.w, a0.w);
            a1.x = fmaf(w1, vv.x, a1.x); a1.y = fmaf(w1, vv.y, a1.y);
            a1.z = fmaf(w1, vv.z, a1.z); a1.w = fmaf(w1, vv.w, a1.w);
            a2.x = fmaf(w2, vv.x, a2.x); a2.y = fmaf(w2, vv.y, a2.y);
            a2.z = fmaf(w2, vv.z, a2.z); a2.w = fmaf(w2, vv.w, a2.w);
            a3.x = fmaf(w3, vv.x, a3.x); a3.y = fmaf(w3, vv.y, a3.y);
            a3.z = fmaf(w3, vv.z, a3.z); a3.w = fmaf(w3, vv.w, a3.w);
        }
        const int ss[4] = { s0, s1, s2, s3 };
        float4 res[4] = { a0, a1, a2, a3 };
        #pragma unroll
        for (int j = 0; j < 4; j++) {
            int n = blk * 40 + par + 2 * ss[j];
            if (n < NTOK) {
                uint2 hh, ll;
                split4(res[j], hh, ll);
                size_t idx = ((size_t)b * NTOK + n) * DIMC + h * HDIM + e4 * 4;
                *(uint2*)(g_att_hi + idx) = hh;
                *(uint2*)(g_att_lo + idx) = ll;
            }
        }
    }
}

// ---------------------------------------------------------------------------
extern "C" void kernel_launch(void* const* d_in, const int* in_sizes, int n_in,
                              void* d_out, int out_size)
{
    const float* x    = (const float*)d_in[0];  // (8, 4096, 1024)
    const float* Wqkv = (const float*)d_in[1];  // (3072, 1024)
    const float* Wout = (const float*)d_in[2];  // (1024, 1024)
    const float* bout = (const float*)d_in[3];  // (1024,)
    float* out = (float*)d_out;                 // (8, 4096, 1024)

    static bool attr_done = false;
    if (!attr_done) {
        cudaFuncSetAttribute(gemm_mma<0>, cudaFuncAttributeMaxDynamicSharedMemorySize, SMEM_TOTAL);
        cudaFuncSetAttribute(gemm_mma<1>, cudaFuncAttributeMaxDynamicSharedMemorySize, SMEM_TOTAL);
        attr_done = true;
    }

    // 0) Split inputs/weights into bf16 hi/lo (single merged launch)
    conv_all<<<(unsigned)CONV_BLOCKS, 256>>>(x, Wqkv, Wout);

    // 1) QKV projection: M=32768 (compact), N=3072
    gemm_mma<0><<<dim3(K3 / 128, MROWS / 128), 128, SMEM_TOTAL>>>(nullptr, nullptr, K3);

    // 2) Patch attention (pad tokens synthesized as zeros)
    attn_kernel<<<dim3(RR, NHEADS, BATCH), 256>>>();

    // 3) Output projection + bias: M=32768, N=1024
    gemm_mma<1><<<dim3(DIMC / 128, MROWS / 128), 128, SMEM_TOTAL>>>(bout, out, DIMC);
}

// round 10
// speedup vs baseline: 4.8773x; 1.4097x over previous
#include <cuda_runtime.h>
#include <cuda_fp16.h>
#include <cstdint>
#include <cstddef>

// ---------------------------------------------------------------------------
// Problem constants
// ---------------------------------------------------------------------------
#define DIMC   1024
#define NHEADS 16
#define HDIM   64
#define NTOK   4096
#define BATCH  8
#define RR     206       // 103 blocks * 2 parities
#define SP     20        // tokens per patch
#define K3     3072      // 3*DIM

#define MROWS  (BATCH*NTOK)    // 32768 (both GEMMs, compact)

// Weight pre-scale (exact power of two; keeps fp16 lo-part out of subnormals)
#define WSCALE   1024.0f
#define INV_WSCALE (1.0f/1024.0f)

// ---------------------------------------------------------------------------
// Device scratch
// ---------------------------------------------------------------------------
__device__ __align__(16) float   g_qkv[(size_t)MROWS * K3];
__device__ __align__(16) __half  g_x_h[(size_t)MROWS * DIMC];     // A of GEMM1 (hi only)
__device__ __align__(16) __half  g_att_h[(size_t)MROWS * DIMC];   // A of GEMM2 (hi only)
__device__ __align__(16) __half  g_wq_h[(size_t)K3 * DIMC];       // B of GEMM1 (x1024)
__device__ __align__(16) __half  g_wq_l[(size_t)K3 * DIMC];
__device__ __align__(16) __half  g_wo_h[(size_t)DIMC * DIMC];     // B of GEMM2 (x1024)
__device__ __align__(16) __half  g_wo_l[(size_t)DIMC * DIMC];

// ---------------------------------------------------------------------------
// Helpers
// ---------------------------------------------------------------------------
__device__ __forceinline__ uint32_t smem_to_u32(const void* p) {
    uint32_t a;
    asm("{ .reg .u64 t; cvta.to.shared.u64 t, %1; cvt.u32.u64 %0, t; }"
        : "=r"(a) : "l"(p));
    return a;
}

__device__ __forceinline__ uint32_t pack_h(__half a, __half b) {
    return (uint32_t)__half_as_ushort(a) | ((uint32_t)__half_as_ushort(b) << 16);
}

// fp16 hi-only pack of float4
__device__ __forceinline__ uint2 h4(const float4 v) {
    uint2 r;
    r.x = pack_h(__float2half_rn(v.x), __float2half_rn(v.y));
    r.y = pack_h(__float2half_rn(v.z), __float2half_rn(v.w));
    return r;
}

// fp16 Dekker split of float4 (hi + lo)
__device__ __forceinline__ void split4h(const float4 v, uint2& hi, uint2& lo) {
    __half h0 = __float2half_rn(v.x), h1 = __float2half_rn(v.y);
    __half h2 = __float2half_rn(v.z), h3 = __float2half_rn(v.w);
    __half l0 = __float2half_rn(v.x - __half2float(h0));
    __half l1 = __float2half_rn(v.y - __half2float(h1));
    __half l2 = __float2half_rn(v.z - __half2float(h2));
    __half l3 = __float2half_rn(v.w - __half2float(h3));
    hi.x = pack_h(h0, h1); hi.y = pack_h(h2, h3);
    lo.x = pack_h(l0, l1); lo.y = pack_h(l2, l3);
}

#define LDSM4(r, addr) \
    asm volatile("ldmatrix.sync.aligned.m8n8.x4.shared.b16 {%0,%1,%2,%3}, [%4];" \
        : "=r"((r)[0]), "=r"((r)[1]), "=r"((r)[2]), "=r"((r)[3]) : "r"(addr))

#define MMA16816(d, a, b0, b1) \
    asm volatile("mma.sync.aligned.m16n8k16.row.col.f32.f16.f16.f32 " \
        "{%0,%1,%2,%3}, {%4,%5,%6,%7}, {%8,%9}, {%0,%1,%2,%3};" \
        : "+f"((d)[0]), "+f"((d)[1]), "+f"((d)[2]), "+f"((d)[3]) \
        : "r"((a)[0]), "r"((a)[1]), "r"((a)[2]), "r"((a)[3]), "r"(b0), "r"(b1))

#define CP_ASYNC16(dst, src) \
    asm volatile("cp.async.cg.shared.global [%0], [%1], 16;" :: "r"(dst), "l"(src))
#define CP_COMMIT() asm volatile("cp.async.commit_group;" ::: "memory")
#define CP_WAIT(n)  asm volatile("cp.async.wait_group %0;" :: "n"(n) : "memory")

// ---------------------------------------------------------------------------
// Merged conversion prepass: x -> fp16 hi; Wqkv/Wout -> (x1024) fp16 hi+lo.
// ---------------------------------------------------------------------------
#define NF4_X  ((size_t)MROWS * DIMC / 4)          // 8388608
#define NF4_WQ ((size_t)K3 * DIMC / 4)             // 786432
#define NF4_WO ((size_t)DIMC * DIMC / 4)           // 262144
#define CONV_BLOCKS ((NF4_X + NF4_WQ + NF4_WO) / 256)

__global__ void __launch_bounds__(256) conv_all(const float* __restrict__ x,
                                                const float* __restrict__ wq,
                                                const float* __restrict__ wo) {
    size_t i = (size_t)blockIdx.x * 256 + threadIdx.x;   // one float4
    if (i < NF4_X) {
        size_t e = i * 4;
        float4 v = *(const float4*)(x + e);
        *(uint2*)(g_x_h + e) = h4(v);
    } else if (i < NF4_X + NF4_WQ) {
        size_t e = (i - NF4_X) * 4;
        float4 v = *(const float4*)(wq + e);
        v.x *= WSCALE; v.y *= WSCALE; v.z *= WSCALE; v.w *= WSCALE;
        uint2 h, l; split4h(v, h, l);
        *(uint2*)(g_wq_h + e) = h;
        *(uint2*)(g_wq_l + e) = l;
    } else {
        size_t e = (i - NF4_X - NF4_WQ) * 4;
        float4 v = *(const float4*)(wo + e);
        v.x *= WSCALE; v.y *= WSCALE; v.z *= WSCALE; v.w *= WSCALE;
        uint2 h, l; split4h(v, h, l);
        *(uint2*)(g_wo_h + e) = h;
        *(uint2*)(g_wo_l + e) = l;
    }
}

// ---------------------------------------------------------------------------
// 2-term split-fp16 mma.sync GEMM: C = A * (Wx1024)^T / 1024 (+bias MODE 1).
// CTA 128x128, 4 warps (warp tile 64x64), BK=32, 4-stage cp.async pipeline,
// single barrier per k-iter, 2 CTAs/SM.
// Stage (24 KB): A_hi 8K | B_hi 8K | B_lo 8K.
// ---------------------------------------------------------------------------
#define BK      32
#define NSTAGE  4
#define STAGE   24576
#define OFF_AHI 0
#define OFF_BHI 8192
#define OFF_BLO 16384
#define SMEM_TOTAL (NSTAGE*STAGE)   // 98304

template<int MODE>
__global__ void __launch_bounds__(128, 2)
gemm_mma(const float* __restrict__ bias, float* __restrict__ Cout, int Ncols)
{
    extern __shared__ char smem[];
    const uint32_t sbase = smem_to_u32(smem);
    const int tid  = threadIdx.x;
    const int lane = tid & 31;
    const int wid  = tid >> 5;   // 0..3
    const int wm   = wid >> 1;   // 0..1
    const int wn   = wid & 1;    // 0..1
    const int m0   = blockIdx.y * 128;
    const int n0   = blockIdx.x * 128;

    const char* bAh = (const char*)((MODE == 0) ? g_x_h : g_att_h);
    const char* bBh = (const char*)((MODE == 0) ? g_wq_h : g_wo_h);
    const char* bBl = (const char*)((MODE == 0) ? g_wq_l : g_wo_l);
    float* C = (MODE == 0) ? g_qkv : Cout;

    // cp.async: 4 chunks of 16B per thread per region; 32-bit byte offsets
    uint32_t dsto[4], aoff[4], boff[4];
    #pragma unroll
    for (int j = 0; j < 4; j++) {
        int c = tid + j * 128;
        int row = c >> 2, col = c & 3;
        dsto[j] = (uint32_t)(row * 64 + (((uint32_t)col ^ (((uint32_t)row >> 1) & 3)) << 4));
        aoff[j] = (uint32_t)((m0 + row) * DIMC + col * 8) * 2u;
        boff[j] = (uint32_t)((n0 + row) * DIMC + col * 8) * 2u;
    }

    uint32_t aOff[4], aXor[4];
    #pragma unroll
    for (int mf = 0; mf < 4; mf++) {
        int row = wm * 64 + mf * 16 + (lane & 15);
        aOff[mf] = (uint32_t)row * 64;
        aXor[mf] = ((uint32_t)row >> 1) & 3;
    }
    const uint32_t aHi = (uint32_t)(lane >> 4);
    uint32_t bOff[4], bXor[4];
    #pragma unroll
    for (int g = 0; g < 4; g++) {
        int row = wn * 64 + (lane & 7) + ((lane >> 4) << 3) + g * 16;
        bOff[g] = (uint32_t)row * 64;
        bXor[g] = ((uint32_t)row >> 1) & 3;
    }
    const uint32_t bk = (uint32_t)((lane >> 3) & 1);

    float acc[4][8][4];
    #pragma unroll
    for (int i = 0; i < 4; i++)
        #pragma unroll
        for (int j = 0; j < 8; j++)
            #pragma unroll
            for (int q = 0; q < 4; q++) acc[i][j][q] = 0.f;

    const int NIT = DIMC / BK;   // 32

    #define ISSUE_TILE(tile) do {                                             \
        const uint32_t sd = sbase + (uint32_t)((tile) % NSTAGE) * STAGE;      \
        const uint32_t kb = (uint32_t)(tile) * (BK * 2);                      \
        _Pragma("unroll")                                                     \
        for (int j = 0; j < 4; j++) {                                         \
            CP_ASYNC16(sd + OFF_AHI + dsto[j], bAh + aoff[j] + kb);           \
            CP_ASYNC16(sd + OFF_BHI + dsto[j], bBh + boff[j] + kb);           \
            CP_ASYNC16(sd + OFF_BLO + dsto[j], bBl + boff[j] + kb);           \
        }                                                                     \
        CP_COMMIT();                                                          \
    } while (0)

    ISSUE_TILE(0);
    ISSUE_TILE(1);
    ISSUE_TILE(2);

    // Single barrier per iteration. Sync at iter `it` proves all warps
    // finished iter it-1; stage (it+3)%4 == (it-1)%4, so immediate reissue
    // into that stage is safe.
    #pragma unroll 1
    for (int it = 0; it < NIT; ++it) {
        if (it < NIT - 2)       { CP_WAIT(2); }
        else if (it == NIT - 2) { CP_WAIT(1); }
        else                    { CP_WAIT(0); }
        __syncthreads();
        if (it + 3 < NIT) ISSUE_TILE(it + 3);

        const uint32_t s = sbase + (uint32_t)(it % NSTAGE) * STAGE;
        #pragma unroll
        for (int ks = 0; ks < 2; ++ks) {
            uint32_t ahi[4][4];
            #pragma unroll
            for (int mf = 0; mf < 4; mf++) {
                uint32_t c = (((uint32_t)(ks * 2) + aHi) ^ aXor[mf]) << 4;
                LDSM4(ahi[mf], s + OFF_AHI + aOff[mf] + c);
            }
            #pragma unroll
            for (int g = 0; g < 4; g++) {
                uint32_t bh[4], bl[4];
                uint32_t c = (((uint32_t)(ks * 2) + bk) ^ bXor[g]) << 4;
                LDSM4(bh, s + OFF_BHI + bOff[g] + c);
                LDSM4(bl, s + OFF_BLO + bOff[g] + c);
                #pragma unroll
                for (int mf = 0; mf < 4; mf++) {
                    MMA16816(acc[mf][2 * g],     ahi[mf], bh[0], bh[1]);
                    MMA16816(acc[mf][2 * g + 1], ahi[mf], bh[2], bh[3]);
                }
                #pragma unroll
                for (int mf = 0; mf < 4; mf++) {
                    MMA16816(acc[mf][2 * g],     ahi[mf], bl[0], bl[1]);
                    MMA16816(acc[mf][2 * g + 1], ahi[mf], bl[2], bl[3]);
                }
            }
        }
    }
    #undef ISSUE_TILE

    // Epilogue: undo the exact 2^10 weight scale; fuse bias for MODE 1.
    const int grp = lane >> 2;
    const int thr = lane & 3;
    #pragma unroll
    for (int mf = 0; mf < 4; mf++) {
        const int mrow = m0 + wm * 64 + mf * 16 + grp;
        #pragma unroll
        for (int nf = 0; nf < 8; nf++) {
            const int col = n0 + wn * 64 + nf * 8 + thr * 2;
            float2 v0 = make_float2(acc[mf][nf][0] * INV_WSCALE,
                                    acc[mf][nf][1] * INV_WSCALE);
            float2 v1 = make_float2(acc[mf][nf][2] * INV_WSCALE,
                                    acc[mf][nf][3] * INV_WSCALE);
            if (MODE == 1) {
                const float2 bv = *(const float2*)(bias + col);
                v0.x += bv.x; v0.y += bv.y;
                v1.x += bv.x; v1.y += bv.y;
            }
            *(float2*)(C + (size_t)mrow * Ncols + col)       = v0;
            *(float2*)(C + (size_t)(mrow + 8) * Ncols + col) = v1;
        }
    }
}

// ---------------------------------------------------------------------------
// Per-patch attention. g_qkv is COMPACT (32768 rows); pad tokens (n>=4096)
// are zero-filled in smem. Output written as fp16 (hi only).
// ---------------------------------------------------------------------------
#define RSTR 68
__global__ void __launch_bounds__(256) attn_kernel()
{
    const int r   = blockIdx.x;
    const int h   = blockIdx.y;
    const int b   = blockIdx.z;
    const int blk = r >> 1, par = r & 1;

    __shared__ float q[SP * RSTR];
    __shared__ float k[SP * RSTR];
    __shared__ float v[SP * RSTR];
    __shared__ float dots[SP][SP + 1];

    const int tid = threadIdx.x;
    const size_t base = (size_t)b * NTOK * K3;

    for (int i = tid; i < SP * 16; i += 256) {
        int s = i >> 4, j = i & 15;
        int n = blk * 40 + par + 2 * s;
        float4 qv, kv, vv;
        if (n < NTOK) {
            const float* rp = g_qkv + base + (size_t)n * K3 + h * HDIM;
            qv = ((const float4*)(rp))[j];
            kv = ((const float4*)(rp + DIMC))[j];
            vv = ((const float4*)(rp + 2 * DIMC))[j];
        } else {
            qv = kv = vv = make_float4(0.f, 0.f, 0.f, 0.f);
        }
        *(float4*)(q + s * RSTR + 4 * j) = qv;
        *(float4*)(k + s * RSTR + 4 * j) = kv;
        *(float4*)(v + s * RSTR + 4 * j) = vv;
    }
    __syncthreads();

    const float scale = 0.125f;  // 64^-0.5
    if (tid < 100) {
        const int a  = tid / 10;
        const int bq = tid % 10;
        const float4* q0 = (const float4*)(q + a * RSTR);
        const float4* q1 = (const float4*)(q + (a + 10) * RSTR);
        const float4* k0 = (const float4*)(k + bq * RSTR);
        const float4* k1 = (const float4*)(k + (bq + 10) * RSTR);
        float d00 = 0.f, d01 = 0.f, d10 = 0.f, d11 = 0.f;
        #pragma unroll
        for (int e4 = 0; e4 < 16; e4++) {
            float4 a0 = q0[e4], a1 = q1[e4];
            float4 c0 = k0[e4], c1 = k1[e4];
            d00 = fmaf(a0.x, c0.x, d00); d00 = fmaf(a0.y, c0.y, d00);
            d00 = fmaf(a0.z, c0.z, d00); d00 = fmaf(a0.w, c0.w, d00);
            d01 = fmaf(a0.x, c1.x, d01); d01 = fmaf(a0.y, c1.y, d01);
            d01 = fmaf(a0.z, c1.z, d01); d01 = fmaf(a0.w, c1.w, d01);
            d10 = fmaf(a1.x, c0.x, d10); d10 = fmaf(a1.y, c0.y, d10);
            d10 = fmaf(a1.z, c0.z, d10); d10 = fmaf(a1.w, c0.w, d10);
            d11 = fmaf(a1.x, c1.x, d11); d11 = fmaf(a1.y, c1.y, d11);
            d11 = fmaf(a1.z, c1.z, d11); d11 = fmaf(a1.w, c1.w, d11);
        }
        dots[a][bq]            = d00 * scale;
        dots[a][bq + 10]       = d01 * scale;
        dots[a + 10][bq]       = d10 * scale;
        dots[a + 10][bq + 10]  = d11 * scale;
    }
    __syncthreads();

    if (tid < SP) {
        float mx = -1e30f;
        #pragma unroll
        for (int t = 0; t < SP; t++) mx = fmaxf(mx, dots[tid][t]);
        float ex[SP]; float sum = 0.f;
        #pragma unroll
        for (int t = 0; t < SP; t++) { float e = expf(dots[tid][t] - mx); ex[t] = e; sum += e; }
        float inv = 1.f / sum;
        #pragma unroll
        for (int t = 0; t < SP; t++) dots[tid][t] = ex[t] * inv;
    }
    __syncthreads();

    if (tid < 80) {
        const int sg = tid >> 4;     // 0..4
        const int e4 = tid & 15;
        const int s0 = sg, s1 = sg + 5, s2 = sg + 10, s3 = sg + 15;
        float4 a0 = make_float4(0.f, 0.f, 0.f, 0.f);
        float4 a1 = a0, a2 = a0, a3 = a0;
        #pragma unroll
        for (int t = 0; t < SP; t++) {
            float w0 = dots[s0][t], w1 = dots[s1][t];
            float w2 = dots[s2][t], w3 = dots[s3][t];
            float4 vv = *(const float4*)(v + t * RSTR + 4 * e4);
            a0.x = fmaf(w0, vv.x, a0.x); a0.y = fmaf(w0, vv.y, a0.y);
            a0.z = fmaf(w0, vv.z, a0.z); a0.w = fmaf(w0, vv.w, a0.w);
            a1.x = fmaf(w1, vv.x, a1.x); a1.y = fmaf(w1, vv.y, a1.y);
            a1.z = fmaf(w1, vv.z, a1.z); a1.w = fmaf(w1, vv.w, a1.w);
            a2.x = fmaf(w2, vv.x, a2.x); a2.y = fmaf(w2, vv.y, a2.y);
            a2.z = fmaf(w2, vv.z, a2.z); a2.w = fmaf(w2, vv.w, a2.w);
            a3.x = fmaf(w3, vv.x, a3.x); a3.y = fmaf(w3, vv.y, a3.y);
            a3.z = fmaf(w3, vv.z, a3.z); a3.w = fmaf(w3, vv.w, a3.w);
        }
        const int ss[4] = { s0, s1, s2, s3 };
        float4 res[4] = { a0, a1, a2, a3 };
        #pragma unroll
        for (int j = 0; j < 4; j++) {
            int n = blk * 40 + par + 2 * ss[j];
            if (n < NTOK) {
                size_t idx = ((size_t)b * NTOK + n) * DIMC + h * HDIM + e4 * 4;
                *(uint2*)(g_att_h + idx) = h4(res[j]);
            }
        }
    }
}

// ---------------------------------------------------------------------------
extern "C" void kernel_launch(void* const* d_in, const int* in_sizes, int n_in,
                              void* d_out, int out_size)
{
    const float* x    = (const float*)d_in[0];  // (8, 4096, 1024)
    const float* Wqkv = (const float*)d_in[1];  // (3072, 1024)
    const float* Wout = (const float*)d_in[2];  // (1024, 1024)
    const float* bout = (const float*)d_in[3];  // (1024,)
    float* out = (float*)d_out;                 // (8, 4096, 1024)

    static bool attr_done = false;
    if (!attr_done) {
        cudaFuncSetAttribute(gemm_mma<0>, cudaFuncAttributeMaxDynamicSharedMemorySize, SMEM_TOTAL);
        cudaFuncSetAttribute(gemm_mma<1>, cudaFuncAttributeMaxDynamicSharedMemorySize, SMEM_TOTAL);
        attr_done = true;
    }

    // 0) Convert: x -> fp16 hi; weights -> (x1024) fp16 hi/lo
    conv_all<<<(unsigned)CONV_BLOCKS, 256>>>(x, Wqkv, Wout);

    // 1) QKV projection: M=32768, N=3072
    gemm_mma<0><<<dim3(K3 / 128, MROWS / 128), 128, SMEM_TOTAL>>>(nullptr, nullptr, K3);

    // 2) Patch attention (pad tokens synthesized as zeros)
    attn_kernel<<<dim3(RR, NHEADS, BATCH), 256>>>();

    // 3) Output projection + bias: M=32768, N=1024
    gemm_mma<1><<<dim3(DIMC / 128, MROWS / 128), 128, SMEM_TOTAL>>>(bout, out, DIMC);
}

// round 11
// speedup vs baseline: 7.5225x; 1.5423x over previous
#include <cuda_runtime.h>
#include <cuda_fp16.h>
#include <cstdint>
#include <cstddef>

// ---------------------------------------------------------------------------
// Problem constants
// ---------------------------------------------------------------------------
#define DIMC   1024
#define NHEADS 16
#define HDIM   64
#define NTOK   4096
#define BATCH  8
#define RR     206       // 103 blocks * 2 parities
#define SP     20        // tokens per patch
#define K3     3072      // 3*DIM

#define MROWS  (BATCH*NTOK)    // 32768 (both GEMMs, compact)

// ---------------------------------------------------------------------------
// Device scratch
// ---------------------------------------------------------------------------
__device__ __align__(16) float   g_qkv[(size_t)MROWS * K3];
__device__ __align__(16) __half  g_x_h[(size_t)MROWS * DIMC];     // A of GEMM1
__device__ __align__(16) __half  g_att_h[(size_t)MROWS * DIMC];   // A of GEMM2
__device__ __align__(16) __half  g_wq_h[(size_t)K3 * DIMC];       // B of GEMM1
__device__ __align__(16) __half  g_wo_h[(size_t)DIMC * DIMC];     // B of GEMM2

// ---------------------------------------------------------------------------
// Helpers
// ---------------------------------------------------------------------------
__device__ __forceinline__ uint32_t smem_to_u32(const void* p) {
    uint32_t a;
    asm("{ .reg .u64 t; cvta.to.shared.u64 t, %1; cvt.u32.u64 %0, t; }"
        : "=r"(a) : "l"(p));
    return a;
}

__device__ __forceinline__ uint32_t pack_h(__half a, __half b) {
    return (uint32_t)__half_as_ushort(a) | ((uint32_t)__half_as_ushort(b) << 16);
}

__device__ __forceinline__ uint2 h4(const float4 v) {
    uint2 r;
    r.x = pack_h(__float2half_rn(v.x), __float2half_rn(v.y));
    r.y = pack_h(__float2half_rn(v.z), __float2half_rn(v.w));
    return r;
}

#define LDSM4(r, addr) \
    asm volatile("ldmatrix.sync.aligned.m8n8.x4.shared.b16 {%0,%1,%2,%3}, [%4];" \
        : "=r"((r)[0]), "=r"((r)[1]), "=r"((r)[2]), "=r"((r)[3]) : "r"(addr))

#define MMA16816(d, a, b0, b1) \
    asm volatile("mma.sync.aligned.m16n8k16.row.col.f32.f16.f16.f32 " \
        "{%0,%1,%2,%3}, {%4,%5,%6,%7}, {%8,%9}, {%0,%1,%2,%3};" \
        : "+f"((d)[0]), "+f"((d)[1]), "+f"((d)[2]), "+f"((d)[3]) \
        : "r"((a)[0]), "r"((a)[1]), "r"((a)[2]), "r"((a)[3]), "r"(b0), "r"(b1))

#define CP_ASYNC16(dst, src) \
    asm volatile("cp.async.cg.shared.global [%0], [%1], 16;" :: "r"(dst), "l"(src))
#define CP_COMMIT() asm volatile("cp.async.commit_group;" ::: "memory")
#define CP_WAIT(n)  asm volatile("cp.async.wait_group %0;" :: "n"(n) : "memory")

// ---------------------------------------------------------------------------
// Merged conversion prepass: x, Wqkv, Wout -> fp16
// ---------------------------------------------------------------------------
#define NF4_X  ((size_t)MROWS * DIMC / 4)          // 8388608
#define NF4_WQ ((size_t)K3 * DIMC / 4)             // 786432
#define NF4_WO ((size_t)DIMC * DIMC / 4)           // 262144
#define CONV_BLOCKS ((NF4_X + NF4_WQ + NF4_WO) / 256)

__global__ void __launch_bounds__(256) conv_all(const float* __restrict__ x,
                                                const float* __restrict__ wq,
                                                const float* __restrict__ wo) {
    size_t i = (size_t)blockIdx.x * 256 + threadIdx.x;   // one float4
    if (i < NF4_X) {
        size_t e = i * 4;
        *(uint2*)(g_x_h + e) = h4(*(const float4*)(x + e));
    } else if (i < NF4_X + NF4_WQ) {
        size_t e = (i - NF4_X) * 4;
        *(uint2*)(g_wq_h + e) = h4(*(const float4*)(wq + e));
    } else {
        size_t e = (i - NF4_X - NF4_WQ) * 4;
        *(uint2*)(g_wo_h + e) = h4(*(const float4*)(wo + e));
    }
}

// ---------------------------------------------------------------------------
// fp16 mma.sync GEMM: C[M,N] = A[M,1024] * W[N,1024]^T (+bias MODE 1).
// CTA 128x128, 4 warps (warp tile 64x64), BK=32, 6-stage cp.async pipeline,
// single barrier per k-iter, 2 CTAs/SM.
// Stage (16 KB): A 8K | B 8K.
// ---------------------------------------------------------------------------
#define BK      32
#define NSTAGE  6
#define STAGE   16384
#define OFF_A   0
#define OFF_B   8192
#define SMEM_TOTAL (NSTAGE*STAGE)   // 98304

template<int MODE>
__global__ void __launch_bounds__(128, 2)
gemm_mma(const float* __restrict__ bias, float* __restrict__ Cout, int Ncols)
{
    extern __shared__ char smem[];
    const uint32_t sbase = smem_to_u32(smem);
    const int tid  = threadIdx.x;
    const int lane = tid & 31;
    const int wid  = tid >> 5;   // 0..3
    const int wm   = wid >> 1;   // 0..1
    const int wn   = wid & 1;    // 0..1
    const int m0   = blockIdx.y * 128;
    const int n0   = blockIdx.x * 128;

    const char* bA = (const char*)((MODE == 0) ? g_x_h : g_att_h);
    const char* bB = (const char*)((MODE == 0) ? g_wq_h : g_wo_h);
    float* C = (MODE == 0) ? g_qkv : Cout;

    // cp.async: 4 chunks of 16B per thread per region; 32-bit byte offsets
    uint32_t dsto[4], aoff[4], boff[4];
    #pragma unroll
    for (int j = 0; j < 4; j++) {
        int c = tid + j * 128;
        int row = c >> 2, col = c & 3;
        dsto[j] = (uint32_t)(row * 64 + (((uint32_t)col ^ (((uint32_t)row >> 1) & 3)) << 4));
        aoff[j] = (uint32_t)((m0 + row) * DIMC + col * 8) * 2u;
        boff[j] = (uint32_t)((n0 + row) * DIMC + col * 8) * 2u;
    }

    uint32_t aOff[4], aXor[4];
    #pragma unroll
    for (int mf = 0; mf < 4; mf++) {
        int row = wm * 64 + mf * 16 + (lane & 15);
        aOff[mf] = (uint32_t)row * 64;
        aXor[mf] = ((uint32_t)row >> 1) & 3;
    }
    const uint32_t aHi = (uint32_t)(lane >> 4);
    uint32_t bOff[4], bXor[4];
    #pragma unroll
    for (int g = 0; g < 4; g++) {
        int row = wn * 64 + (lane & 7) + ((lane >> 4) << 3) + g * 16;
        bOff[g] = (uint32_t)row * 64;
        bXor[g] = ((uint32_t)row >> 1) & 3;
    }
    const uint32_t bk = (uint32_t)((lane >> 3) & 1);

    float acc[4][8][4];
    #pragma unroll
    for (int i = 0; i < 4; i++)
        #pragma unroll
        for (int j = 0; j < 8; j++)
            #pragma unroll
            for (int q = 0; q < 4; q++) acc[i][j][q] = 0.f;

    const int NIT = DIMC / BK;   // 32

    #define ISSUE_TILE(tile) do {                                             \
        const uint32_t sd = sbase + (uint32_t)((tile) % NSTAGE) * STAGE;      \
        const uint32_t kb = (uint32_t)(tile) * (BK * 2);                      \
        _Pragma("unroll")                                                     \
        for (int j = 0; j < 4; j++) {                                         \
            CP_ASYNC16(sd + OFF_A + dsto[j], bA + aoff[j] + kb);              \
            CP_ASYNC16(sd + OFF_B + dsto[j], bB + boff[j] + kb);              \
        }                                                                     \
        CP_COMMIT();                                                          \
    } while (0)

    ISSUE_TILE(0); ISSUE_TILE(1); ISSUE_TILE(2); ISSUE_TILE(3); ISSUE_TILE(4);

    // Single barrier per iteration. Sync at iter `it` proves all warps
    // finished iter it-1; stage (it+5)%6 == (it-1)%6, so immediate reissue
    // into that stage is safe. Tail wait counts keep tile `it` complete.
    #pragma unroll 1
    for (int it = 0; it < NIT; ++it) {
        if      (it <  NIT - 4) { CP_WAIT(4); }
        else if (it == NIT - 4) { CP_WAIT(3); }
        else if (it == NIT - 3) { CP_WAIT(2); }
        else if (it == NIT - 2) { CP_WAIT(1); }
        else                    { CP_WAIT(0); }
        __syncthreads();
        if (it + 5 < NIT) ISSUE_TILE(it + 5);

        const uint32_t s = sbase + (uint32_t)(it % NSTAGE) * STAGE;
        #pragma unroll
        for (int ks = 0; ks < 2; ++ks) {
            uint32_t ahi[4][4];
            #pragma unroll
            for (int mf = 0; mf < 4; mf++) {
                uint32_t c = (((uint32_t)(ks * 2) + aHi) ^ aXor[mf]) << 4;
                LDSM4(ahi[mf], s + OFF_A + aOff[mf] + c);
            }
            #pragma unroll
            for (int g = 0; g < 4; g++) {
                uint32_t bh[4];
                uint32_t c = (((uint32_t)(ks * 2) + bk) ^ bXor[g]) << 4;
                LDSM4(bh, s + OFF_B + bOff[g] + c);
                #pragma unroll
                for (int mf = 0; mf < 4; mf++) {
                    MMA16816(acc[mf][2 * g],     ahi[mf], bh[0], bh[1]);
                    MMA16816(acc[mf][2 * g + 1], ahi[mf], bh[2], bh[3]);
                }
            }
        }
    }
    #undef ISSUE_TILE

    // Epilogue (fused bias for MODE 1)
    const int grp = lane >> 2;
    const int thr = lane & 3;
    #pragma unroll
    for (int mf = 0; mf < 4; mf++) {
        const int mrow = m0 + wm * 64 + mf * 16 + grp;
        #pragma unroll
        for (int nf = 0; nf < 8; nf++) {
            const int col = n0 + wn * 64 + nf * 8 + thr * 2;
            float2 v0 = make_float2(acc[mf][nf][0], acc[mf][nf][1]);
            float2 v1 = make_float2(acc[mf][nf][2], acc[mf][nf][3]);
            if (MODE == 1) {
                const float2 bv = *(const float2*)(bias + col);
                v0.x += bv.x; v0.y += bv.y;
                v1.x += bv.x; v1.y += bv.y;
            }
            *(float2*)(C + (size_t)mrow * Ncols + col)       = v0;
            *(float2*)(C + (size_t)(mrow + 8) * Ncols + col) = v1;
        }
    }
}

// ---------------------------------------------------------------------------
// Per-patch attention. g_qkv is COMPACT (32768 rows); pad tokens (n>=4096)
// are zero-filled in smem. Output written as fp16.
// ---------------------------------------------------------------------------
#define RSTR 68
__global__ void __launch_bounds__(256) attn_kernel()
{
    const int r   = blockIdx.x;
    const int h   = blockIdx.y;
    const int b   = blockIdx.z;
    const int blk = r >> 1, par = r & 1;

    __shared__ float q[SP * RSTR];
    __shared__ float k[SP * RSTR];
    __shared__ float v[SP * RSTR];
    __shared__ float dots[SP][SP + 1];

    const int tid = threadIdx.x;
    const size_t base = (size_t)b * NTOK * K3;

    for (int i = tid; i < SP * 16; i += 256) {
        int s = i >> 4, j = i & 15;
        int n = blk * 40 + par + 2 * s;
        float4 qv, kv, vv;
        if (n < NTOK) {
            const float* rp = g_qkv + base + (size_t)n * K3 + h * HDIM;
            qv = ((const float4*)(rp))[j];
            kv = ((const float4*)(rp + DIMC))[j];
            vv = ((const float4*)(rp + 2 * DIMC))[j];
        } else {
            qv = kv = vv = make_float4(0.f, 0.f, 0.f, 0.f);
        }
        *(float4*)(q + s * RSTR + 4 * j) = qv;
        *(float4*)(k + s * RSTR + 4 * j) = kv;
        *(float4*)(v + s * RSTR + 4 * j) = vv;
    }
    __syncthreads();

    const float scale = 0.125f;  // 64^-0.5
    if (tid < 100) {
        const int a  = tid / 10;
        const int bq = tid % 10;
        const float4* q0 = (const float4*)(q + a * RSTR);
        const float4* q1 = (const float4*)(q + (a + 10) * RSTR);
        const float4* k0 = (const float4*)(k + bq * RSTR);
        const float4* k1 = (const float4*)(k + (bq + 10) * RSTR);
        float d00 = 0.f, d01 = 0.f, d10 = 0.f, d11 = 0.f;
        #pragma unroll
        for (int e4 = 0; e4 < 16; e4++) {
            float4 a0 = q0[e4], a1 = q1[e4];
            float4 c0 = k0[e4], c1 = k1[e4];
            d00 = fmaf(a0.x, c0.x, d00); d00 = fmaf(a0.y, c0.y, d00);
            d00 = fmaf(a0.z, c0.z, d00); d00 = fmaf(a0.w, c0.w, d00);
            d01 = fmaf(a0.x, c1.x, d01); d01 = fmaf(a0.y, c1.y, d01);
            d01 = fmaf(a0.z, c1.z, d01); d01 = fmaf(a0.w, c1.w, d01);
            d10 = fmaf(a1.x, c0.x, d10); d10 = fmaf(a1.y, c0.y, d10);
            d10 = fmaf(a1.z, c0.z, d10); d10 = fmaf(a1.w, c0.w, d10);
            d11 = fmaf(a1.x, c1.x, d11); d11 = fmaf(a1.y, c1.y, d11);
            d11 = fmaf(a1.z, c1.z, d11); d11 = fmaf(a1.w, c1.w, d11);
        }
        dots[a][bq]            = d00 * scale;
        dots[a][bq + 10]       = d01 * scale;
        dots[a + 10][bq]       = d10 * scale;
        dots[a + 10][bq + 10]  = d11 * scale;
    }
    __syncthreads();

    if (tid < SP) {
        float mx = -1e30f;
        #pragma unroll
        for (int t = 0; t < SP; t++) mx = fmaxf(mx, dots[tid][t]);
        float ex[SP]; float sum = 0.f;
        #pragma unroll
        for (int t = 0; t < SP; t++) { float e = expf(dots[tid][t] - mx); ex[t] = e; sum += e; }
        float inv = 1.f / sum;
        #pragma unroll
        for (int t = 0; t < SP; t++) dots[tid][t] = ex[t] * inv;
    }
    __syncthreads();

    if (tid < 80) {
        const int sg = tid >> 4;     // 0..4
        const int e4 = tid & 15;
        const int s0 = sg, s1 = sg + 5, s2 = sg + 10, s3 = sg + 15;
        float4 a0 = make_float4(0.f, 0.f, 0.f, 0.f);
        float4 a1 = a0, a2 = a0, a3 = a0;
        #pragma unroll
        for (int t = 0; t < SP; t++) {
            float w0 = dots[s0][t], w1 = dots[s1][t];
            float w2 = dots[s2][t], w3 = dots[s3][t];
            float4 vv = *(const float4*)(v + t * RSTR + 4 * e4);
            a0.x = fmaf(w0, vv.x, a0.x); a0.y = fmaf(w0, vv.y, a0.y);
            a0.z = fmaf(w0, vv.z, a0.z); a0.w = fmaf(w0, vv.w, a0.w);
            a1.x = fmaf(w1, vv.x, a1.x); a1.y = fmaf(w1, vv.y, a1.y);
            a1.z = fmaf(w1, vv.z, a1.z); a1.w = fmaf(w1, vv.w, a1.w);
            a2.x = fmaf(w2, vv.x, a2.x); a2.y = fmaf(w2, vv.y, a2.y);
            a2.z = fmaf(w2, vv.z, a2.z); a2.w = fmaf(w2, vv.w, a2.w);
            a3.x = fmaf(w3, vv.x, a3.x); a3.y = fmaf(w3, vv.y, a3.y);
            a3.z = fmaf(w3, vv.z, a3.z); a3.w = fmaf(w3, vv.w, a3.w);
        }
        const int ss[4] = { s0, s1, s2, s3 };
        float4 res[4] = { a0, a1, a2, a3 };
        #pragma unroll
        for (int j = 0; j < 4; j++) {
            int n = blk * 40 + par + 2 * ss[j];
            if (n < NTOK) {
                size_t idx = ((size_t)b * NTOK + n) * DIMC + h * HDIM + e4 * 4;
                *(uint2*)(g_att_h + idx) = h4(res[j]);
            }
        }
    }
}

// ---------------------------------------------------------------------------
extern "C" void kernel_launch(void* const* d_in, const int* in_sizes, int n_in,
                              void* d_out, int out_size)
{
    const float* x    = (const float*)d_in[0];  // (8, 4096, 1024)
    const float* Wqkv = (const float*)d_in[1];  // (3072, 1024)
    const float* Wout = (const float*)d_in[2];  // (1024, 1024)
    const float* bout = (const float*)d_in[3];  // (1024,)
    float* out = (float*)d_out;                 // (8, 4096, 1024)

    static bool attr_done = false;
    if (!attr_done) {
        cudaFuncSetAttribute(gemm_mma<0>, cudaFuncAttributeMaxDynamicSharedMemorySize, SMEM_TOTAL);
        cudaFuncSetAttribute(gemm_mma<1>, cudaFuncAttributeMaxDynamicSharedMemorySize, SMEM_TOTAL);
        attr_done = true;
    }

    // 0) Convert x, Wqkv, Wout -> fp16
    conv_all<<<(unsigned)CONV_BLOCKS, 256>>>(x, Wqkv, Wout);

    // 1) QKV projection: M=32768, N=3072
    gemm_mma<0><<<dim3(K3 / 128, MROWS / 128), 128, SMEM_TOTAL>>>(nullptr, nullptr, K3);

    // 2) Patch attention (pad tokens synthesized as zeros)
    attn_kernel<<<dim3(RR, NHEADS, BATCH), 256>>>();

    // 3) Output projection + bias: M=32768, N=1024
    gemm_mma<1><<<dim3(DIMC / 128, MROWS / 128), 128, SMEM_TOTAL>>>(bout, out, DIMC);
}

// round 12
// speedup vs baseline: 7.6316x; 1.0145x over previous
#include <cuda_runtime.h>
#include <cuda_fp16.h>
#include <cstdint>
#include <cstddef>

// ---------------------------------------------------------------------------
// Problem constants
// ---------------------------------------------------------------------------
#define DIMC   1024
#define NHEADS 16
#define HDIM   64
#define NTOK   4096
#define BATCH  8
#define RR     206       // 103 blocks * 2 parities
#define SP     20        // tokens per patch
#define K3     3072      // 3*DIM

#define MROWS  (BATCH*NTOK)    // 32768 (both GEMMs, compact)

// ---------------------------------------------------------------------------
// Device scratch
// ---------------------------------------------------------------------------
__device__ __align__(16) __half  g_qkv_h[(size_t)MROWS * K3];     // fp16 qkv
__device__ __align__(16) __half  g_x_h[(size_t)MROWS * DIMC];     // A of GEMM1
__device__ __align__(16) __half  g_att_h[(size_t)MROWS * DIMC];   // A of GEMM2
__device__ __align__(16) __half  g_wq_h[(size_t)K3 * DIMC];       // B of GEMM1
__device__ __align__(16) __half  g_wo_h[(size_t)DIMC * DIMC];     // B of GEMM2

// ---------------------------------------------------------------------------
// Helpers
// ---------------------------------------------------------------------------
__device__ __forceinline__ uint32_t smem_to_u32(const void* p) {
    uint32_t a;
    asm("{ .reg .u64 t; cvta.to.shared.u64 t, %1; cvt.u32.u64 %0, t; }"
        : "=r"(a) : "l"(p));
    return a;
}

__device__ __forceinline__ uint32_t pack_h(__half a, __half b) {
    return (uint32_t)__half_as_ushort(a) | ((uint32_t)__half_as_ushort(b) << 16);
}

__device__ __forceinline__ uint2 h4(const float4 v) {
    uint2 r;
    r.x = pack_h(__float2half_rn(v.x), __float2half_rn(v.y));
    r.y = pack_h(__float2half_rn(v.z), __float2half_rn(v.w));
    return r;
}

// unpack 4 halves (uint2) -> float4
__device__ __forceinline__ float4 u2f4(const uint2 p) {
    __half2 h0 = *(const __half2*)&p.x;
    __half2 h1 = *(const __half2*)&p.y;
    float2 f0 = __half22float2(h0);
    float2 f1 = __half22float2(h1);
    return make_float4(f0.x, f0.y, f1.x, f1.y);
}

#define LDSM4(r, addr) \
    asm volatile("ldmatrix.sync.aligned.m8n8.x4.shared.b16 {%0,%1,%2,%3}, [%4];" \
        : "=r"((r)[0]), "=r"((r)[1]), "=r"((r)[2]), "=r"((r)[3]) : "r"(addr))

#define MMA16816(d, a, b0, b1) \
    asm volatile("mma.sync.aligned.m16n8k16.row.col.f32.f16.f16.f32 " \
        "{%0,%1,%2,%3}, {%4,%5,%6,%7}, {%8,%9}, {%0,%1,%2,%3};" \
        : "+f"((d)[0]), "+f"((d)[1]), "+f"((d)[2]), "+f"((d)[3]) \
        : "r"((a)[0]), "r"((a)[1]), "r"((a)[2]), "r"((a)[3]), "r"(b0), "r"(b1))

#define CP_ASYNC16(dst, src) \
    asm volatile("cp.async.cg.shared.global [%0], [%1], 16;" :: "r"(dst), "l"(src))
#define CP_COMMIT() asm volatile("cp.async.commit_group;" ::: "memory")
#define CP_WAIT(n)  asm volatile("cp.async.wait_group %0;" :: "n"(n) : "memory")

// ---------------------------------------------------------------------------
// Merged conversion prepass: x, Wqkv, Wout -> fp16
// ---------------------------------------------------------------------------
#define NF4_X  ((size_t)MROWS * DIMC / 4)          // 8388608
#define NF4_WQ ((size_t)K3 * DIMC / 4)             // 786432
#define NF4_WO ((size_t)DIMC * DIMC / 4)           // 262144
#define CONV_BLOCKS ((NF4_X + NF4_WQ + NF4_WO) / 256)

__global__ void __launch_bounds__(256) conv_all(const float* __restrict__ x,
                                                const float* __restrict__ wq,
                                                const float* __restrict__ wo) {
    size_t i = (size_t)blockIdx.x * 256 + threadIdx.x;   // one float4
    if (i < NF4_X) {
        size_t e = i * 4;
        *(uint2*)(g_x_h + e) = h4(*(const float4*)(x + e));
    } else if (i < NF4_X + NF4_WQ) {
        size_t e = (i - NF4_X) * 4;
        *(uint2*)(g_wq_h + e) = h4(*(const float4*)(wq + e));
    } else {
        size_t e = (i - NF4_X - NF4_WQ) * 4;
        *(uint2*)(g_wo_h + e) = h4(*(const float4*)(wo + e));
    }
}

// ---------------------------------------------------------------------------
// fp16 mma.sync GEMM: C[M,N] = A[M,1024] * W[N,1024]^T (+bias MODE 1).
// CTA 128x128, 4 warps (warp tile 64x64), BK=32, 6-stage cp.async pipeline,
// single barrier per k-iter, 2 CTAs/SM.
// MODE 0 stores fp16 (qkv scratch); MODE 1 stores fp32 + bias (final out).
// ---------------------------------------------------------------------------
#define BK      32
#define NSTAGE  6
#define STAGE   16384
#define OFF_A   0
#define OFF_B   8192
#define SMEM_TOTAL (NSTAGE*STAGE)   // 98304

template<int MODE>
__global__ void __launch_bounds__(128, 2)
gemm_mma(const float* __restrict__ bias, float* __restrict__ Cout, int Ncols)
{
    extern __shared__ char smem[];
    const uint32_t sbase = smem_to_u32(smem);
    const int tid  = threadIdx.x;
    const int lane = tid & 31;
    const int wid  = tid >> 5;   // 0..3
    const int wm   = wid >> 1;   // 0..1
    const int wn   = wid & 1;    // 0..1
    const int m0   = blockIdx.y * 128;
    const int n0   = blockIdx.x * 128;

    const char* bA = (const char*)((MODE == 0) ? g_x_h : g_att_h);
    const char* bB = (const char*)((MODE == 0) ? g_wq_h : g_wo_h);

    // cp.async: 4 chunks of 16B per thread per region; 32-bit byte offsets
    uint32_t dsto[4], aoff[4], boff[4];
    #pragma unroll
    for (int j = 0; j < 4; j++) {
        int c = tid + j * 128;
        int row = c >> 2, col = c & 3;
        dsto[j] = (uint32_t)(row * 64 + (((uint32_t)col ^ (((uint32_t)row >> 1) & 3)) << 4));
        aoff[j] = (uint32_t)((m0 + row) * DIMC + col * 8) * 2u;
        boff[j] = (uint32_t)((n0 + row) * DIMC + col * 8) * 2u;
    }

    uint32_t aOff[4], aXor[4];
    #pragma unroll
    for (int mf = 0; mf < 4; mf++) {
        int row = wm * 64 + mf * 16 + (lane & 15);
        aOff[mf] = (uint32_t)row * 64;
        aXor[mf] = ((uint32_t)row >> 1) & 3;
    }
    const uint32_t aHi = (uint32_t)(lane >> 4);
    uint32_t bOff[4], bXor[4];
    #pragma unroll
    for (int g = 0; g < 4; g++) {
        int row = wn * 64 + (lane & 7) + ((lane >> 4) << 3) + g * 16;
        bOff[g] = (uint32_t)row * 64;
        bXor[g] = ((uint32_t)row >> 1) & 3;
    }
    const uint32_t bk = (uint32_t)((lane >> 3) & 1);

    float acc[4][8][4];
    #pragma unroll
    for (int i = 0; i < 4; i++)
        #pragma unroll
        for (int j = 0; j < 8; j++)
            #pragma unroll
            for (int q = 0; q < 4; q++) acc[i][j][q] = 0.f;

    const int NIT = DIMC / BK;   // 32

    #define ISSUE_TILE(tile) do {                                             \
        const uint32_t sd = sbase + (uint32_t)((tile) % NSTAGE) * STAGE;      \
        const uint32_t kb = (uint32_t)(tile) * (BK * 2);                      \
        _Pragma("unroll")                                                     \
        for (int j = 0; j < 4; j++) {                                         \
            CP_ASYNC16(sd + OFF_A + dsto[j], bA + aoff[j] + kb);              \
            CP_ASYNC16(sd + OFF_B + dsto[j], bB + boff[j] + kb);              \
        }                                                                     \
        CP_COMMIT();                                                          \
    } while (0)

    ISSUE_TILE(0); ISSUE_TILE(1); ISSUE_TILE(2); ISSUE_TILE(3); ISSUE_TILE(4);

    #pragma unroll 1
    for (int it = 0; it < NIT; ++it) {
        if      (it <  NIT - 4) { CP_WAIT(4); }
        else if (it == NIT - 4) { CP_WAIT(3); }
        else if (it == NIT - 3) { CP_WAIT(2); }
        else if (it == NIT - 2) { CP_WAIT(1); }
        else                    { CP_WAIT(0); }
        __syncthreads();
        if (it + 5 < NIT) ISSUE_TILE(it + 5);

        const uint32_t s = sbase + (uint32_t)(it % NSTAGE) * STAGE;
        #pragma unroll
        for (int ks = 0; ks < 2; ++ks) {
            uint32_t ahi[4][4];
            #pragma unroll
            for (int mf = 0; mf < 4; mf++) {
                uint32_t c = (((uint32_t)(ks * 2) + aHi) ^ aXor[mf]) << 4;
                LDSM4(ahi[mf], s + OFF_A + aOff[mf] + c);
            }
            #pragma unroll
            for (int g = 0; g < 4; g++) {
                uint32_t bh[4];
                uint32_t c = (((uint32_t)(ks * 2) + bk) ^ bXor[g]) << 4;
                LDSM4(bh, s + OFF_B + bOff[g] + c);
                #pragma unroll
                for (int mf = 0; mf < 4; mf++) {
                    MMA16816(acc[mf][2 * g],     ahi[mf], bh[0], bh[1]);
                    MMA16816(acc[mf][2 * g + 1], ahi[mf], bh[2], bh[3]);
                }
            }
        }
    }
    #undef ISSUE_TILE

    // Epilogue
    const int grp = lane >> 2;
    const int thr = lane & 3;
    #pragma unroll
    for (int mf = 0; mf < 4; mf++) {
        const int mrow = m0 + wm * 64 + mf * 16 + grp;
        #pragma unroll
        for (int nf = 0; nf < 8; nf++) {
            const int col = n0 + wn * 64 + nf * 8 + thr * 2;
            if (MODE == 0) {
                // fp16 store to qkv scratch
                __half* Ch = g_qkv_h;
                *(uint32_t*)(Ch + (size_t)mrow * Ncols + col) =
                    pack_h(__float2half_rn(acc[mf][nf][0]), __float2half_rn(acc[mf][nf][1]));
                *(uint32_t*)(Ch + (size_t)(mrow + 8) * Ncols + col) =
                    pack_h(__float2half_rn(acc[mf][nf][2]), __float2half_rn(acc[mf][nf][3]));
            } else {
                const float2 bv = *(const float2*)(bias + col);
                float2 v0 = make_float2(acc[mf][nf][0] + bv.x, acc[mf][nf][1] + bv.y);
                float2 v1 = make_float2(acc[mf][nf][2] + bv.x, acc[mf][nf][3] + bv.y);
                *(float2*)(Cout + (size_t)mrow * Ncols + col)       = v0;
                *(float2*)(Cout + (size_t)(mrow + 8) * Ncols + col) = v1;
            }
        }
    }
}

// ---------------------------------------------------------------------------
// Per-patch attention. Reads fp16 qkv (compact), computes fp32 in smem,
// writes fp16 attention output. Pad tokens (n>=4096) zero-filled.
// ---------------------------------------------------------------------------
#define RSTR 68
__global__ void __launch_bounds__(256) attn_kernel()
{
    const int r   = blockIdx.x;
    const int h   = blockIdx.y;
    const int b   = blockIdx.z;
    const int blk = r >> 1, par = r & 1;

    __shared__ float q[SP * RSTR];
    __shared__ float k[SP * RSTR];
    __shared__ float v[SP * RSTR];
    __shared__ float dots[SP][SP + 1];

    const int tid = threadIdx.x;
    const size_t base = (size_t)b * NTOK * K3;

    // Load q/k/v tiles (20 tokens x 16 groups of 4 halves each)
    for (int i = tid; i < SP * 16; i += 256) {
        int s = i >> 4, j = i & 15;
        int n = blk * 40 + par + 2 * s;
        float4 qv, kv, vv;
        if (n < NTOK) {
            const __half* rp = g_qkv_h + base + (size_t)n * K3 + h * HDIM;
            qv = u2f4(((const uint2*)(rp))[j]);
            kv = u2f4(((const uint2*)(rp + DIMC))[j]);
            vv = u2f4(((const uint2*)(rp + 2 * DIMC))[j]);
        } else {
            qv = kv = vv = make_float4(0.f, 0.f, 0.f, 0.f);
        }
        *(float4*)(q + s * RSTR + 4 * j) = qv;
        *(float4*)(k + s * RSTR + 4 * j) = kv;
        *(float4*)(v + s * RSTR + 4 * j) = vv;
    }
    __syncthreads();

    const float scale = 0.125f;  // 64^-0.5
    if (tid < 100) {
        const int a  = tid / 10;
        const int bq = tid % 10;
        const float4* q0 = (const float4*)(q + a * RSTR);
        const float4* q1 = (const float4*)(q + (a + 10) * RSTR);
        const float4* k0 = (const float4*)(k + bq * RSTR);
        const float4* k1 = (const float4*)(k + (bq + 10) * RSTR);
        float d00 = 0.f, d01 = 0.f, d10 = 0.f, d11 = 0.f;
        #pragma unroll
        for (int e4 = 0; e4 < 16; e4++) {
            float4 a0 = q0[e4], a1 = q1[e4];
            float4 c0 = k0[e4], c1 = k1[e4];
            d00 = fmaf(a0.x, c0.x, d00); d00 = fmaf(a0.y, c0.y, d00);
            d00 = fmaf(a0.z, c0.z, d00); d00 = fmaf(a0.w, c0.w, d00);
            d01 = fmaf(a0.x, c1.x, d01); d01 = fmaf(a0.y, c1.y, d01);
            d01 = fmaf(a0.z, c1.z, d01); d01 = fmaf(a0.w, c1.w, d01);
            d10 = fmaf(a1.x, c0.x, d10); d10 = fmaf(a1.y, c0.y, d10);
            d10 = fmaf(a1.z, c0.z, d10); d10 = fmaf(a1.w, c0.w, d10);
            d11 = fmaf(a1.x, c1.x, d11); d11 = fmaf(a1.y, c1.y, d11);
            d11 = fmaf(a1.z, c1.z, d11); d11 = fmaf(a1.w, c1.w, d11);
        }
        dots[a][bq]            = d00 * scale;
        dots[a][bq + 10]       = d01 * scale;
        dots[a + 10][bq]       = d10 * scale;
        dots[a + 10][bq + 10]  = d11 * scale;
    }
    __syncthreads();

    if (tid < SP) {
        float mx = -1e30f;
        #pragma unroll
        for (int t = 0; t < SP; t++) mx = fmaxf(mx, dots[tid][t]);
        float ex[SP]; float sum = 0.f;
        #pragma unroll
        for (int t = 0; t < SP; t++) { float e = expf(dots[tid][t] - mx); ex[t] = e; sum += e; }
        float inv = 1.f / sum;
        #pragma unroll
        for (int t = 0; t < SP; t++) dots[tid][t] = ex[t] * inv;
    }
    __syncthreads();

    if (tid < 80) {
        const int sg = tid >> 4;     // 0..4
        const int e4 = tid & 15;
        const int s0 = sg, s1 = sg + 5, s2 = sg + 10, s3 = sg + 15;
        float4 a0 = make_float4(0.f, 0.f, 0.f, 0.f);
        float4 a1 = a0, a2 = a0, a3 = a0;
        #pragma unroll
        for (int t = 0; t < SP; t++) {
            float w0 = dots[s0][t], w1 = dots[s1][t];
            float w2 = dots[s2][t], w3 = dots[s3][t];
            float4 vv = *(const float4*)(v + t * RSTR + 4 * e4);
            a0.x = fmaf(w0, vv.x, a0.x); a0.y = fmaf(w0, vv.y, a0.y);
            a0.z = fmaf(w0, vv.z, a0.z); a0.w = fmaf(w0, vv.w, a0.w);
            a1.x = fmaf(w1, vv.x, a1.x); a1.y = fmaf(w1, vv.y, a1.y);
            a1.z = fmaf(w1, vv.z, a1.z); a1.w = fmaf(w1, vv.w, a1.w);
            a2.x = fmaf(w2, vv.x, a2.x); a2.y = fmaf(w2, vv.y, a2.y);
            a2.z = fmaf(w2, vv.z, a2.z); a2.w = fmaf(w2, vv.w, a2.w);
            a3.x = fmaf(w3, vv.x, a3.x); a3.y = fmaf(w3, vv.y, a3.y);
            a3.z = fmaf(w3, vv.z, a3.z); a3.w = fmaf(w3, vv.w, a3.w);
        }
        const int ss[4] = { s0, s1, s2, s3 };
        float4 res[4] = { a0, a1, a2, a3 };
        #pragma unroll
        for (int j = 0; j < 4; j++) {
            int n = blk * 40 + par + 2 * ss[j];
            if (n < NTOK) {
                size_t idx = ((size_t)b * NTOK + n) * DIMC + h * HDIM + e4 * 4;
                *(uint2*)(g_att_h + idx) = h4(res[j]);
            }
        }
    }
}

// ---------------------------------------------------------------------------
extern "C" void kernel_launch(void* const* d_in, const int* in_sizes, int n_in,
                              void* d_out, int out_size)
{
    const float* x    = (const float*)d_in[0];  // (8, 4096, 1024)
    const float* Wqkv = (const float*)d_in[1];  // (3072, 1024)
    const float* Wout = (const float*)d_in[2];  // (1024, 1024)
    const float* bout = (const float*)d_in[3];  // (1024,)
    float* out = (float*)d_out;                 // (8, 4096, 1024)

    static bool attr_done = false;
    if (!attr_done) {
        cudaFuncSetAttribute(gemm_mma<0>, cudaFuncAttributeMaxDynamicSharedMemorySize, SMEM_TOTAL);
        cudaFuncSetAttribute(gemm_mma<1>, cudaFuncAttributeMaxDynamicSharedMemorySize, SMEM_TOTAL);
        attr_done = true;
    }

    // 0) Convert x, Wqkv, Wout -> fp16
    conv_all<<<(unsigned)CONV_BLOCKS, 256>>>(x, Wqkv, Wout);

    // 1) QKV projection: M=32768, N=3072, fp16 output
    gemm_mma<0><<<dim3(K3 / 128, MROWS / 128), 128, SMEM_TOTAL>>>(nullptr, nullptr, K3);

    // 2) Patch attention (fp16 in/out, fp32 math)
    attn_kernel<<<dim3(RR, NHEADS, BATCH), 256>>>();

    // 3) Output projection + bias: M=32768, N=1024, fp32 output
    gemm_mma<1><<<dim3(DIMC / 128, MROWS / 128), 128, SMEM_TOTAL>>>(bout, out, DIMC);
}